// round 4
// baseline (speedup 1.0000x reference)
#include <cuda_runtime.h>
#include <cstddef>

#define B_ 4
#define T_ 4096
#define C_ 512
#define CHUNK 64
#define NCHUNK (T_/CHUNK)

typedef unsigned long long ull_t;

__device__ __forceinline__ float2 ffma2(float2 a, float2 b, float2 c) {
    ull_t ua = *reinterpret_cast<ull_t*>(&a);
    ull_t ub = *reinterpret_cast<ull_t*>(&b);
    ull_t uc = *reinterpret_cast<ull_t*>(&c);
    ull_t ud;
    asm("fma.rn.f32x2 %0, %1, %2, %3;" : "=l"(ud) : "l"(ua), "l"(ub), "l"(uc));
    return *reinterpret_cast<float2*>(&ud);
}
__device__ __forceinline__ float2 fmul2_(float2 a, float2 b) {
    ull_t ua = *reinterpret_cast<ull_t*>(&a);
    ull_t ub = *reinterpret_cast<ull_t*>(&b);
    ull_t ud;
    asm("mul.rn.f32x2 %0, %1, %2;" : "=l"(ud) : "l"(ua), "l"(ub));
    return *reinterpret_cast<float2*>(&ud);
}

// scratch (__device__ globals: no allocation APIs allowed)
__device__ float g_Qs[B_*T_*C_];   // Q~ = Q * r_t (chunk-local cumulative gamma)
__device__ float g_Ks[B_*T_*C_];   // K~ = K / r_t
__device__ float g_V [B_*T_*C_];
__device__ float g_OL[B_*T_*C_];   // per-chunk masked local attention output
__device__ float g_sQ[T_];
__device__ float g_sK[T_];
__device__ float g_SR[NCHUNK];

// gammas = linspace(0.96, 0.99, T); r = chunk-local cumulative product
__global__ void scales_kernel() {
    int ch = threadIdx.x;
    if (ch >= NCHUNK) return;
    const float step = 0.03f / 4095.0f;
    float r = 1.0f;
    for (int i = 0; i < CHUNK; ++i) {
        int t = ch * CHUNK + i;
        float g = 0.96f + step * (float)t;
        r *= g;
        g_sQ[t] = r;
        g_sK[t] = 1.0f / r;
    }
    g_SR[ch] = r;
}

// ---------------- fused QKV projection (unchanged, passing) ----------------
#define BM 128
#define BN 64
#define BK 16
__global__ __launch_bounds__(256, 2) void proj_kernel(
        const float* __restrict__ X,
        const float* __restrict__ WQ, const float* __restrict__ bQ,
        const float* __restrict__ WK, const float* __restrict__ bK,
        const float* __restrict__ WV, const float* __restrict__ bV) {
    __shared__ __align__(16) float  As[2][BK][BM];
    __shared__ __align__(16) float2 Bs[2][BK][BN];
    const int tid = threadIdx.x;
    const int which = blockIdx.x >> 3;
    const int n0 = (blockIdx.x & 7) * BN;
    const int m0 = blockIdx.y * BM;
    const float* W    = (which == 0) ? WQ : ((which == 1) ? WK : WV);
    const float* bias = (which == 0) ? bQ : ((which == 1) ? bK : bV);
    float* out        = (which == 0) ? g_Qs : ((which == 1) ? g_Ks : g_V);
    const int tx = tid & 15, ty = tid >> 4;

    float2 acc[4][4];
    #pragma unroll
    for (int i = 0; i < 4; ++i)
        #pragma unroll
        for (int j = 0; j < 4; ++j) acc[i][j] = make_float2(0.f, 0.f);

    {
        #pragma unroll
        for (int i = 0; i < 2; ++i) {
            int lin = tid + i * 256, m = lin >> 2, k4 = lin & 3;
            float4 v = *(const float4*)&X[(size_t)(m0 + m) * C_ + k4 * 4];
            As[0][k4*4+0][m] = v.x; As[0][k4*4+1][m] = v.y;
            As[0][k4*4+2][m] = v.z; As[0][k4*4+3][m] = v.w;
        }
        int k = tid >> 4, n4 = tid & 15;
        float4 v = *(const float4*)&W[(size_t)k * C_ + n0 + n4 * 4];
        Bs[0][k][n4*4+0] = make_float2(v.x, v.x);
        Bs[0][k][n4*4+1] = make_float2(v.y, v.y);
        Bs[0][k][n4*4+2] = make_float2(v.z, v.z);
        Bs[0][k][n4*4+3] = make_float2(v.w, v.w);
    }
    __syncthreads();

    int cur = 0;
    const int NT = C_ / BK;
    for (int kt = 0; kt < NT; ++kt) {
        float4 pa[2]; float4 pb;
        const bool pre = (kt + 1 < NT);
        if (pre) {
            int k0 = (kt + 1) * BK;
            #pragma unroll
            for (int i = 0; i < 2; ++i) {
                int lin = tid + i * 256, m = lin >> 2, k4 = lin & 3;
                pa[i] = *(const float4*)&X[(size_t)(m0 + m) * C_ + k0 + k4 * 4];
            }
            int k = tid >> 4, n4 = tid & 15;
            pb = *(const float4*)&W[(size_t)(k0 + k) * C_ + n0 + n4 * 4];
        }
        #pragma unroll
        for (int kk = 0; kk < BK; ++kk) {
            float4 a0 = *(const float4*)&As[cur][kk][ty * 8];
            float4 a1 = *(const float4*)&As[cur][kk][ty * 8 + 4];
            float2 a2[4] = { make_float2(a0.x, a0.y), make_float2(a0.z, a0.w),
                             make_float2(a1.x, a1.y), make_float2(a1.z, a1.w) };
            const float4* bp = (const float4*)&Bs[cur][kk][tx * 4];
            float4 bb0 = bp[0], bb1 = bp[1];
            float2 b2[4] = { make_float2(bb0.x, bb0.y), make_float2(bb0.z, bb0.w),
                             make_float2(bb1.x, bb1.y), make_float2(bb1.z, bb1.w) };
            #pragma unroll
            for (int m2 = 0; m2 < 4; ++m2)
                #pragma unroll
                for (int j = 0; j < 4; ++j)
                    acc[m2][j] = ffma2(a2[m2], b2[j], acc[m2][j]);
        }
        if (pre) {
            int nxt = cur ^ 1;
            #pragma unroll
            for (int i = 0; i < 2; ++i) {
                int lin = tid + i * 256, m = lin >> 2, k4 = lin & 3;
                As[nxt][k4*4+0][m] = pa[i].x; As[nxt][k4*4+1][m] = pa[i].y;
                As[nxt][k4*4+2][m] = pa[i].z; As[nxt][k4*4+3][m] = pa[i].w;
            }
            int k = tid >> 4, n4 = tid & 15;
            Bs[nxt][k][n4*4+0] = make_float2(pb.x, pb.x);
            Bs[nxt][k][n4*4+1] = make_float2(pb.y, pb.y);
            Bs[nxt][k][n4*4+2] = make_float2(pb.z, pb.z);
            Bs[nxt][k][n4*4+3] = make_float2(pb.w, pb.w);
            __syncthreads();
            cur = nxt;
        }
    }

    float4 bias4 = *(const float4*)&bias[n0 + tx * 4];
    #pragma unroll
    for (int m2 = 0; m2 < 4; ++m2) {
        #pragma unroll
        for (int h = 0; h < 2; ++h) {
            int m = m0 + ty * 8 + m2 * 2 + h;
            int tt = m & (T_ - 1);
            float s = (which == 0) ? g_sQ[tt] : ((which == 1) ? g_sK[tt] : 1.0f);
            float4 o;
            o.x = ((h ? acc[m2][0].y : acc[m2][0].x) + bias4.x) * s;
            o.y = ((h ? acc[m2][1].y : acc[m2][1].x) + bias4.y) * s;
            o.z = ((h ? acc[m2][2].y : acc[m2][2].x) + bias4.z) * s;
            o.w = ((h ? acc[m2][3].y : acc[m2][3].x) + bias4.w) * s;
            *(float4*)&out[(size_t)m * C_ + n0 + tx * 4] = o;
        }
    }
}

// ---------------- local (in-chunk) masked attention (unchanged, passing) ----------------
#define QS_STRIDE 68
__global__ __launch_bounds__(256) void local_kernel() {
    extern __shared__ float sm3[];
    float* qs = sm3;
    float* ks = sm3 + 64 * QS_STRIDE;
    float* As = sm3 + 2 * 64 * QS_STRIDE;
    float* vs = As + 64 * 64;

    const int tid = threadIdx.x;
    const int b  = blockIdx.x >> 6;
    const int ch = blockIdx.x & 63;
    const int tt = tid >> 4, ss = tid & 15;
    const int r = tid >> 2, cseg = tid & 3;
    const size_t rowbase = (size_t)b * T_ + (size_t)ch * CHUNK;
    const float* Qb = g_Qs + rowbase * C_;
    const float* Kb = g_Ks + rowbase * C_;
    const float* Vb = g_V  + rowbase * C_;

    float2 accA[4][4];
    #pragma unroll
    for (int i = 0; i < 4; ++i)
        #pragma unroll
        for (int j = 0; j < 4; ++j) accA[i][j] = make_float2(0.f, 0.f);

    for (int ct = 0; ct < 8; ++ct) {
        #pragma unroll
        for (int u = 0; u < 4; ++u) {
            float4 qv = *(const float4*)&Qb[(size_t)r * C_ + ct * 64 + cseg * 16 + u * 4];
            float4 kv = *(const float4*)&Kb[(size_t)r * C_ + ct * 64 + cseg * 16 + u * 4];
            *(float4*)&qs[r * QS_STRIDE + cseg * 16 + u * 4] = qv;
            *(float4*)&ks[r * QS_STRIDE + cseg * 16 + u * 4] = kv;
        }
        __syncthreads();
        #pragma unroll 4
        for (int c4 = 0; c4 < 16; ++c4) {
            float4 q[4], k[4];
            #pragma unroll
            for (int i = 0; i < 4; ++i)
                q[i] = *(const float4*)&qs[(tt * 4 + i) * QS_STRIDE + c4 * 4];
            #pragma unroll
            for (int j = 0; j < 4; ++j)
                k[j] = *(const float4*)&ks[(ss * 4 + j) * QS_STRIDE + c4 * 4];
            #pragma unroll
            for (int i = 0; i < 4; ++i)
                #pragma unroll
                for (int j = 0; j < 4; ++j) {
                    accA[i][j] = ffma2(make_float2(q[i].x, q[i].y),
                                       make_float2(k[j].x, k[j].y), accA[i][j]);
                    accA[i][j] = ffma2(make_float2(q[i].z, q[i].w),
                                       make_float2(k[j].z, k[j].w), accA[i][j]);
                }
        }
        __syncthreads();
    }
    #pragma unroll
    for (int i = 0; i < 4; ++i)
        #pragma unroll
        for (int j = 0; j < 4; ++j) {
            int t = tt * 4 + i, s = ss * 4 + j;
            As[t * 64 + s] = (s <= t) ? (accA[i][j].x + accA[i][j].y) : 0.f;
        }
    __syncthreads();

    const int dd = tid & 15;
    const int smax = tt * 4 + 4;
    for (int dt = 0; dt < 4; ++dt) {
        #pragma unroll
        for (int u = 0; u < 8; ++u) {
            float4 vv = *(const float4*)&Vb[(size_t)r * C_ + dt * 128 + cseg * 32 + u * 4];
            *(float4*)&vs[r * 128 + cseg * 32 + u * 4] = vv;
        }
        __syncthreads();
        float2 accO[4][4];
        #pragma unroll
        for (int i = 0; i < 4; ++i)
            #pragma unroll
            for (int p = 0; p < 4; ++p) accO[i][p] = make_float2(0.f, 0.f);
        for (int s = 0; s < smax; ++s) {
            float4 v0 = *(const float4*)&vs[s * 128 + dd * 8];
            float4 v1 = *(const float4*)&vs[s * 128 + dd * 8 + 4];
            float2 vp[4] = { make_float2(v0.x, v0.y), make_float2(v0.z, v0.w),
                             make_float2(v1.x, v1.y), make_float2(v1.z, v1.w) };
            #pragma unroll
            for (int i = 0; i < 4; ++i) {
                float a = As[(tt * 4 + i) * 64 + s];
                float2 a2 = make_float2(a, a);
                #pragma unroll
                for (int p = 0; p < 4; ++p)
                    accO[i][p] = ffma2(a2, vp[p], accO[i][p]);
            }
        }
        #pragma unroll
        for (int i = 0; i < 4; ++i) {
            float4 o0 = make_float4(accO[i][0].x, accO[i][0].y, accO[i][1].x, accO[i][1].y);
            float4 o1 = make_float4(accO[i][2].x, accO[i][2].y, accO[i][3].x, accO[i][3].y);
            float* dst = &g_OL[(rowbase + tt * 4 + i) * C_ + dt * 128 + dd * 8];
            *(float4*)dst = o0;
            *(float4*)(dst + 4) = o1;
        }
        __syncthreads();
    }
}

// ---------------- chunked state scan v3: 512 threads, register-blocked GEMMs ----------------
// grid = B*32 (16-wide d slab). S^T[16][516] in smem (layout [d][c]).
// Per chunk: 4 q-tile phases (GEMM1: cross = q~ . S_start) then 4 k-tile phases
// (GEMM2: S = (S + k~^T v) * R). O = tanh(cross + OL).
#define ST_S 516
#define QK_S 132
#define VD_S 36
#define RED_CG 1032

__global__ __launch_bounds__(512) void scan3_kernel(
        float* __restrict__ O, float* __restrict__ Sout, int writeS) {
    extern __shared__ float sm[];
    float* ST  = sm;                       // [16][516]   S transposed
    float* QK  = ST + 16 * ST_S;           // [64][132]   staged q/k tile
    float* VD  = QK + 64 * QK_S;           // [64][36]    v slab, d-duplicated
    float* RED = VD + 64 * VD_S;           // [8][1032]   GEMM1 c-group partials

    const int tid = threadIdx.x;
    const int b  = blockIdx.x >> 5;
    const int d0 = (blockIdx.x & 31) * 16;
    // GEMM1 mapping: tid = cgH(1)|tg(3)|cgL(2)|dg(3)
    const int dg   = tid & 7;
    const int cgL  = (tid >> 3) & 3;
    const int tg   = (tid >> 5) & 7;
    const int cgH  = tid >> 8;
    const int cg   = cgH * 4 + cgL;
    const int dloc = dg * 2;
    // GEMM2 mapping: warp = c-octet, lane = sg(2)|dg(3)
    const int w16 = tid >> 5;
    const int sg  = (tid >> 3) & 3;
    // output mapping (2 outputs per thread per chunk)
    const int ot  = (tid * 2) >> 4;
    const int odl = (tid * 2) & 15;

    const float* Qb  = g_Qs + (size_t)b * T_ * C_;
    const float* Kb  = g_Ks + (size_t)b * T_ * C_;
    const float* Vb  = g_V  + (size_t)b * T_ * C_;
    const float* OLb = g_OL + (size_t)b * T_ * C_;
    float* Ob = O + (size_t)b * T_ * C_;

    for (int i = tid; i < 16 * ST_S; i += 512) ST[i] = 0.f;

    float4 P[4]; float2 Pv; float2 Pol = make_float2(0.f, 0.f);
    {   // prologue: prefetch chunk-0 q-tile-0 + v slab
        #pragma unroll
        for (int u = 0; u < 4; ++u) {
            int f4 = tid + 512 * u, row = f4 >> 5, col = f4 & 31;
            P[u] = __ldg((const float4*)&Qb[(size_t)row * C_ + col * 4]);
        }
        Pv = __ldg((const float2*)&Vb[(size_t)ot * C_ + d0 + odl]);
    }

    float2 acc1[8][2];
    #pragma unroll
    for (int i = 0; i < 8; ++i) { acc1[i][0] = make_float2(0.f,0.f); acc1[i][1] = make_float2(0.f,0.f); }

    for (int ch = 0; ch < NCHUNK; ++ch) {
        const size_t crow = (size_t)ch * CHUNK;
        const float Rch = __ldg(&g_SR[ch]);

        for (int ph = 0; ph < 8; ++ph) {
            __syncthreads();
            #pragma unroll
            for (int u = 0; u < 4; ++u) {
                int f4 = tid + 512 * u, row = f4 >> 5, col = f4 & 31;
                *(float4*)&QK[row * QK_S + col * 4] = P[u];
            }
            if (ph == 0)
                *(float4*)&VD[ot * VD_S + odl * 2] = make_float4(Pv.x, Pv.x, Pv.y, Pv.y);
            __syncthreads();

            // prefetch next tile
            {
                const float* src; size_t rb = crow; int tix;
                if (ph < 3)      { src = Qb; tix = ph + 1; }
                else if (ph < 7) { src = Kb; tix = ph - 3; }
                else {
                    int chn = (ch < NCHUNK - 1) ? ch + 1 : ch;
                    rb = (size_t)chn * CHUNK; src = Qb; tix = 0;
                    Pv = __ldg((const float2*)&Vb[(rb + ot) * C_ + d0 + odl]);
                }
                #pragma unroll
                for (int u = 0; u < 4; ++u) {
                    int f4 = tid + 512 * u, row = f4 >> 5, col = f4 & 31;
                    P[u] = __ldg((const float4*)&src[(rb + row) * C_ + tix * 128 + col * 4]);
                }
                if (ph == 2)
                    Pol = __ldg((const float2*)&OLb[(crow + ot) * C_ + d0 + odl]);
            }

            if (ph < 4) {
                // GEMM1: acc1[t][dd] += q~[t][c-slice] * S[c][d]
                #pragma unroll
                for (int j = 0; j < 4; ++j) {
                    const int cl = cg * 4 + j * 32;       // tile-local c
                    const int gc = ph * 128 + cl;          // global c
                    float4 Sa = *(const float4*)&ST[dloc * ST_S + gc];
                    float4 Sb = *(const float4*)&ST[(dloc + 1) * ST_S + gc];
                    float2 sa0 = make_float2(Sa.x, Sa.y), sa1 = make_float2(Sa.z, Sa.w);
                    float2 sb0 = make_float2(Sb.x, Sb.y), sb1 = make_float2(Sb.z, Sb.w);
                    #pragma unroll
                    for (int i = 0; i < 8; ++i) {
                        float4 q = *(const float4*)&QK[(tg * 8 + i) * QK_S + cl];
                        float2 q0 = make_float2(q.x, q.y), q1 = make_float2(q.z, q.w);
                        acc1[i][0] = ffma2(q0, sa0, acc1[i][0]);
                        acc1[i][0] = ffma2(q1, sa1, acc1[i][0]);
                        acc1[i][1] = ffma2(q0, sb0, acc1[i][1]);
                        acc1[i][1] = ffma2(q1, sb1, acc1[i][1]);
                    }
                }
                if (ph == 3) {
                    // c-group reduction + output
                    #pragma unroll
                    for (int i = 0; i < 8; ++i) {
                        RED[cg * RED_CG + (tg * 8 + i) * 16 + dloc]     = acc1[i][0].x + acc1[i][0].y;
                        RED[cg * RED_CG + (tg * 8 + i) * 16 + dloc + 1] = acc1[i][1].x + acc1[i][1].y;
                        acc1[i][0] = make_float2(0.f, 0.f);
                        acc1[i][1] = make_float2(0.f, 0.f);
                    }
                    __syncthreads();
                    float s0 = 0.f, s1 = 0.f;
                    #pragma unroll
                    for (int g = 0; g < 8; ++g) {
                        s0 += RED[g * RED_CG + ot * 16 + odl];
                        s1 += RED[g * RED_CG + ot * 16 + odl + 1];
                    }
                    float2 o = make_float2(tanhf(s0 + Pol.x), tanhf(s1 + Pol.y));
                    *(float2*)&Ob[(crow + ot) * C_ + d0 + odl] = o;
                }
            } else {
                // GEMM2: acc2[cp][dd] += k~[s][c] * v[s][d], s-slice by sg
                float2 a[4][2];
                #pragma unroll
                for (int cp = 0; cp < 4; ++cp) { a[cp][0] = make_float2(0.f,0.f); a[cp][1] = make_float2(0.f,0.f); }
                #pragma unroll 4
                for (int si = 0; si < 16; ++si) {
                    int s = sg + 4 * si;
                    float4 ka = *(const float4*)&QK[s * QK_S + w16 * 8];
                    float4 kb = *(const float4*)&QK[s * QK_S + w16 * 8 + 4];
                    float4 v  = *(const float4*)&VD[s * VD_S + dloc * 2];
                    float2 v0 = make_float2(v.x, v.y), v1 = make_float2(v.z, v.w);
                    float2 k0 = make_float2(ka.x, ka.y), k1 = make_float2(ka.z, ka.w);
                    float2 k2 = make_float2(kb.x, kb.y), k3 = make_float2(kb.z, kb.w);
                    a[0][0] = ffma2(k0, v0, a[0][0]); a[0][1] = ffma2(k0, v1, a[0][1]);
                    a[1][0] = ffma2(k1, v0, a[1][0]); a[1][1] = ffma2(k1, v1, a[1][1]);
                    a[2][0] = ffma2(k2, v0, a[2][0]); a[2][1] = ffma2(k2, v1, a[2][1]);
                    a[3][0] = ffma2(k3, v0, a[3][0]); a[3][1] = ffma2(k3, v1, a[3][1]);
                }
                // reduce-scatter over sg (lane bits 3,4); lane sg keeps cp==sg
                const int b0 = sg & 1, b1 = sg >> 1;
                float2 mine[2];
                #pragma unroll
                for (int dd = 0; dd < 2; ++dd) {
                    float2 s01 = b0 ? a[0][dd] : a[1][dd];
                    float2 s23 = b0 ? a[2][dd] : a[3][dd];
                    float2 r01, r23;
                    r01.x = __shfl_xor_sync(0xffffffffu, s01.x, 8);
                    r01.y = __shfl_xor_sync(0xffffffffu, s01.y, 8);
                    r23.x = __shfl_xor_sync(0xffffffffu, s23.x, 8);
                    r23.y = __shfl_xor_sync(0xffffffffu, s23.y, 8);
                    float2 ka_ = b0 ? a[1][dd] : a[0][dd];
                    float2 kb_ = b0 ? a[3][dd] : a[2][dd];
                    ka_.x += r01.x; ka_.y += r01.y;
                    kb_.x += r23.x; kb_.y += r23.y;
                    float2 snd = b1 ? ka_ : kb_;
                    float2 rcv;
                    rcv.x = __shfl_xor_sync(0xffffffffu, snd.x, 16);
                    rcv.y = __shfl_xor_sync(0xffffffffu, snd.y, 16);
                    float2 kp = b1 ? kb_ : ka_;
                    mine[dd] = make_float2(kp.x + rcv.x, kp.y + rcv.y);
                }
                // S[c-pair][d], S = (S + acc)*R
                const int gc = (ph - 4) * 128 + w16 * 8 + sg * 2;
                float2 R2 = make_float2(Rch, Rch);
                #pragma unroll
                for (int dd = 0; dd < 2; ++dd) {
                    float2 Sold = *(const float2*)&ST[(dloc + dd) * ST_S + gc];
                    float2 t = fmul2_(mine[dd], R2);
                    *(float2*)&ST[(dloc + dd) * ST_S + gc] = ffma2(Sold, R2, t);
                }
            }
        }
    }

    __syncthreads();
    if (writeS) {
        for (int idx = tid; idx < C_ * 16; idx += 512) {
            int c = idx >> 4, dl = idx & 15;
            Sout[((size_t)b * C_ + c) * C_ + d0 + dl] = ST[dl * ST_S + c];
        }
    }
}

extern "C" void kernel_launch(void* const* d_in, const int* in_sizes, int n_in,
                              void* d_out, int out_size) {
    const float* X  = (const float*)d_in[0];
    // d_in[1] = S_n (ignored; reference resets state to zero)
    const float* WQ = (const float*)d_in[2];
    const float* bQ = (const float*)d_in[3];
    const float* WK = (const float*)d_in[4];
    const float* bK = (const float*)d_in[5];
    const float* WV = (const float*)d_in[6];
    const float* bV = (const float*)d_in[7];
    float* out = (float*)d_out;

    const int oElems = B_ * T_ * C_;
    const int sElems = B_ * C_ * C_;
    int writeS = (out_size >= oElems + sElems) ? 1 : 0;
    float* Sout = out + oElems;

    const int sm3 = (2 * 64 * QS_STRIDE + 64 * 64 + 64 * 128) * 4;
    const int smS = (16 * ST_S + 64 * QK_S + 64 * VD_S + 8 * RED_CG) * 4;
    cudaFuncSetAttribute(local_kernel, cudaFuncAttributeMaxDynamicSharedMemorySize, sm3);
    cudaFuncSetAttribute(scan3_kernel, cudaFuncAttributeMaxDynamicSharedMemorySize, smS);

    scales_kernel<<<1, NCHUNK>>>();
    dim3 pg(24, (B_ * T_) / BM);
    proj_kernel<<<pg, 256>>>(X, WQ, bQ, WK, bK, WV, bV);
    local_kernel<<<B_ * NCHUNK, 256, sm3>>>();
    scan3_kernel<<<B_ * 32, 512, smS>>>(out, Sout, writeS);
}

// round 6
// speedup vs baseline: 2.4385x; 2.4385x over previous
#include <cuda_runtime.h>
#include <cuda_bf16.h>
#include <cstdint>
#include <cstddef>

#define B_ 4
#define T_ 4096
#define C_ 512
#define CHUNK 64
#define NCHUNK (T_/CHUNK)

typedef unsigned long long ull_t;

__device__ __forceinline__ float2 ffma2(float2 a, float2 b, float2 c) {
    ull_t ua = *reinterpret_cast<ull_t*>(&a);
    ull_t ub = *reinterpret_cast<ull_t*>(&b);
    ull_t uc = *reinterpret_cast<ull_t*>(&c);
    ull_t ud;
    asm("fma.rn.f32x2 %0, %1, %2, %3;" : "=l"(ud) : "l"(ua), "l"(ub), "l"(uc));
    return *reinterpret_cast<float2*>(&ud);
}
__device__ __forceinline__ float2 fmul2_(float2 a, float2 b) {
    ull_t ua = *reinterpret_cast<ull_t*>(&a);
    ull_t ub = *reinterpret_cast<ull_t*>(&b);
    ull_t ud;
    asm("mul.rn.f32x2 %0, %1, %2;" : "=l"(ud) : "l"(ua), "l"(ub));
    return *reinterpret_cast<float2*>(&ud);
}
// bf16 warp MMA: D(16x8,f32) += A(16x16,row) * B(16x8,col)
__device__ __forceinline__ void mma16816(float* c, const uint32_t* a, const uint32_t* b) {
    asm volatile(
        "mma.sync.aligned.m16n8k16.row.col.f32.bf16.bf16.f32 "
        "{%0,%1,%2,%3}, {%4,%5,%6,%7}, {%8,%9}, {%0,%1,%2,%3};\n"
        : "+f"(c[0]), "+f"(c[1]), "+f"(c[2]), "+f"(c[3])
        : "r"(a[0]), "r"(a[1]), "r"(a[2]), "r"(a[3]), "r"(b[0]), "r"(b[1]));
}

// -------- scratch (__device__ globals: no allocation APIs allowed) --------
__device__ float g_Qs[B_*T_*C_];   // Q~ = Q * r_t
__device__ float g_Ks[B_*T_*C_];   // K~ = K / r_t
__device__ float g_V [B_*T_*C_];
__device__ float g_OL[B_*T_*C_];   // per-chunk masked local attention output
__device__ float g_sQ[T_];
__device__ float g_sK[T_];
__device__ float g_SR[NCHUNK];
// split-bf16 operands for the HMMA projection
__device__ __nv_bfloat16 g_Xh[B_*T_*C_];
__device__ __nv_bfloat16 g_Xl[B_*T_*C_];
__device__ __nv_bfloat16 g_Wht[3*C_*C_];  // transposed [which][n][k]
__device__ __nv_bfloat16 g_Wlt[3*C_*C_];

// -------- gamma scales --------
__global__ void scales_kernel() {
    int ch = threadIdx.x;
    if (ch >= NCHUNK) return;
    const float step = 0.03f / 4095.0f;
    float r = 1.0f;
    for (int i = 0; i < CHUNK; ++i) {
        int t = ch * CHUNK + i;
        float g = 0.96f + step * (float)t;
        r *= g;
        g_sQ[t] = r;
        g_sK[t] = 1.0f / r;
    }
    g_SR[ch] = r;
}

// -------- split-bf16 converts --------
__global__ __launch_bounds__(256) void convX_kernel(const float* __restrict__ X) {
    int i = blockIdx.x * 256 + threadIdx.x;   // one float4 each
    float4 v = *(const float4*)&X[(size_t)i * 4];
    __nv_bfloat16 h[4], l[4];
    float vv[4] = {v.x, v.y, v.z, v.w};
    #pragma unroll
    for (int j = 0; j < 4; ++j) {
        h[j] = __float2bfloat16(vv[j]);
        l[j] = __float2bfloat16(vv[j] - __bfloat162float(h[j]));
    }
    *(uint2*)&g_Xh[(size_t)i * 4] = *(uint2*)h;
    *(uint2*)&g_Xl[(size_t)i * 4] = *(uint2*)l;
}

__global__ __launch_bounds__(256) void convW_kernel(
        const float* __restrict__ W0, const float* __restrict__ W1,
        const float* __restrict__ W2) {
    __shared__ float tile[32][33];
    const int w = blockIdx.z;
    const float* W = (w == 0) ? W0 : ((w == 1) ? W1 : W2);
    const int k0 = blockIdx.y * 32, n0 = blockIdx.x * 32;
    const int tx = threadIdx.x & 31, ty = threadIdx.x >> 5;
    #pragma unroll
    for (int i = 0; i < 32; i += 8)
        tile[ty + i][tx] = W[(size_t)(k0 + ty + i) * C_ + n0 + tx];
    __syncthreads();
    #pragma unroll
    for (int i = 0; i < 32; i += 8) {
        int nl = ty + i;
        float v = tile[tx][nl];                       // = W[k0+tx][n0+nl]
        __nv_bfloat16 h = __float2bfloat16(v);
        __nv_bfloat16 l = __float2bfloat16(v - __bfloat162float(h));
        size_t o = ((size_t)w * C_ + (n0 + nl)) * C_ + k0 + tx;
        g_Wht[o] = h;
        g_Wlt[o] = l;
    }
}

// -------- HMMA projection: out = (X @ W + b) * rowscale, split-bf16 (hh + hl + lh) --------
// CTA 128m x 128n, 8 warps (warp tile 64m x 32n), k in 16 chunks of 32.
// Smem tiles stride 40 halfwords -> conflict-free LDS.32 fragment loads.
#define SA 40
#define TILE_HW (128 * SA)
__global__ __launch_bounds__(256, 2) void projmma_kernel(
        const float* __restrict__ bQ, const float* __restrict__ bK,
        const float* __restrict__ bV) {
    extern __shared__ __nv_bfloat16 sh[];
    __nv_bfloat16* Ah = sh;
    __nv_bfloat16* Al = sh + TILE_HW;
    __nv_bfloat16* Bh = sh + 2 * TILE_HW;
    __nv_bfloat16* Bl = sh + 3 * TILE_HW;

    const int tid = threadIdx.x;
    const int w = tid >> 5, lane = tid & 31;
    const int g = lane >> 2, t4 = lane & 3;
    const int wm = w >> 2, wn = w & 3;          // 2 x 4 warp grid
    const int which = blockIdx.x >> 2;
    const int n0 = (blockIdx.x & 3) * 128;
    const int m0 = blockIdx.y * 128;
    const float* bias = (which == 0) ? bQ : ((which == 1) ? bK : bV);
    float* out = (which == 0) ? g_Qs : ((which == 1) ? g_Ks : g_V);
    const __nv_bfloat16* WhT = g_Wht + (size_t)which * C_ * C_;
    const __nv_bfloat16* WlT = g_Wlt + (size_t)which * C_ * C_;

    float acc[4][4][4];
    #pragma unroll
    for (int i = 0; i < 4; ++i)
        #pragma unroll
        for (int j = 0; j < 4; ++j)
            #pragma unroll
            for (int r = 0; r < 4; ++r) acc[i][j][r] = 0.f;

    for (int ck = 0; ck < 16; ++ck) {
        const int k0 = ck * 32;
        __syncthreads();
        #pragma unroll
        for (int u = 0; u < 2; ++u) {
            int unit = tid + u * 256;            // 512 units: 128 rows x 4 col-octets
            int r = unit >> 2, cg = unit & 3;
            int hw = r * SA + cg * 8;
            size_t ga = (size_t)(m0 + r) * C_ + k0 + cg * 8;
            size_t gb = (size_t)(n0 + r) * C_ + k0 + cg * 8;
            *(uint4*)&Ah[hw] = *(const uint4*)&g_Xh[ga];
            *(uint4*)&Al[hw] = *(const uint4*)&g_Xl[ga];
            *(uint4*)&Bh[hw] = *(const uint4*)&WhT[gb];
            *(uint4*)&Bl[hw] = *(const uint4*)&WlT[gb];
        }
        __syncthreads();

        #pragma unroll
        for (int kk = 0; kk < 32; kk += 16) {
            // B fragments: b0 = {B[2t][n], B[2t+1][n]} = Wt[n][2t..2t+1]
            uint32_t bh[4][2], bl[4][2];
            #pragma unroll
            for (int nf = 0; nf < 4; ++nf) {
                int hw = (wn * 32 + nf * 8 + g) * SA + kk + 2 * t4;
                bh[nf][0] = *(const uint32_t*)&Bh[hw];
                bh[nf][1] = *(const uint32_t*)&Bh[hw + 8];
                bl[nf][0] = *(const uint32_t*)&Bl[hw];
                bl[nf][1] = *(const uint32_t*)&Bl[hw + 8];
            }
            #pragma unroll
            for (int mf = 0; mf < 4; ++mf) {
                int row = (wm * 64 + mf * 16 + g) * SA + kk + 2 * t4;
                uint32_t ah[4], al[4];
                ah[0] = *(const uint32_t*)&Ah[row];
                ah[1] = *(const uint32_t*)&Ah[row + 8 * SA];
                ah[2] = *(const uint32_t*)&Ah[row + 8];
                ah[3] = *(const uint32_t*)&Ah[row + 8 * SA + 8];
                al[0] = *(const uint32_t*)&Al[row];
                al[1] = *(const uint32_t*)&Al[row + 8 * SA];
                al[2] = *(const uint32_t*)&Al[row + 8];
                al[3] = *(const uint32_t*)&Al[row + 8 * SA + 8];
                #pragma unroll
                for (int nf = 0; nf < 4; ++nf) {
                    mma16816(acc[mf][nf], ah, bh[nf]);
                    mma16816(acc[mf][nf], ah, bl[nf]);
                    mma16816(acc[mf][nf], al, bh[nf]);
                }
            }
        }
    }

    // epilogue: c0=C[g][2t], c1=C[g][2t+1], c2=C[g+8][2t], c3=C[g+8][2t+1]
    #pragma unroll
    for (int mf = 0; mf < 4; ++mf) {
        int m = m0 + wm * 64 + mf * 16 + g;
        int tA = m & (T_ - 1);
        int tB = (m + 8) & (T_ - 1);
        float sA = (which == 0) ? g_sQ[tA] : ((which == 1) ? g_sK[tA] : 1.0f);
        float sB = (which == 0) ? g_sQ[tB] : ((which == 1) ? g_sK[tB] : 1.0f);
        #pragma unroll
        for (int nf = 0; nf < 4; ++nf) {
            int n = n0 + wn * 32 + nf * 8 + 2 * t4;
            float2 bb = *(const float2*)&bias[n];
            float2 o0 = make_float2((acc[mf][nf][0] + bb.x) * sA,
                                    (acc[mf][nf][1] + bb.y) * sA);
            float2 o1 = make_float2((acc[mf][nf][2] + bb.x) * sB,
                                    (acc[mf][nf][3] + bb.y) * sB);
            *(float2*)&out[(size_t)m * C_ + n] = o0;
            *(float2*)&out[(size_t)(m + 8) * C_ + n] = o1;
        }
    }
}

// ---------------- local (in-chunk) masked attention (unchanged, passing) ----------------
#define QS_STRIDE 68
__global__ __launch_bounds__(256) void local_kernel() {
    extern __shared__ float sm3[];
    float* qs = sm3;
    float* ks = sm3 + 64 * QS_STRIDE;
    float* As = sm3 + 2 * 64 * QS_STRIDE;
    float* vs = As + 64 * 64;

    const int tid = threadIdx.x;
    const int b  = blockIdx.x >> 6;
    const int ch = blockIdx.x & 63;
    const int tt = tid >> 4, ss = tid & 15;
    const int r = tid >> 2, cseg = tid & 3;
    const size_t rowbase = (size_t)b * T_ + (size_t)ch * CHUNK;
    const float* Qb = g_Qs + rowbase * C_;
    const float* Kb = g_Ks + rowbase * C_;
    const float* Vb = g_V  + rowbase * C_;

    float2 accA[4][4];
    #pragma unroll
    for (int i = 0; i < 4; ++i)
        #pragma unroll
        for (int j = 0; j < 4; ++j) accA[i][j] = make_float2(0.f, 0.f);

    for (int ct = 0; ct < 8; ++ct) {
        #pragma unroll
        for (int u = 0; u < 4; ++u) {
            float4 qv = *(const float4*)&Qb[(size_t)r * C_ + ct * 64 + cseg * 16 + u * 4];
            float4 kv = *(const float4*)&Kb[(size_t)r * C_ + ct * 64 + cseg * 16 + u * 4];
            *(float4*)&qs[r * QS_STRIDE + cseg * 16 + u * 4] = qv;
            *(float4*)&ks[r * QS_STRIDE + cseg * 16 + u * 4] = kv;
        }
        __syncthreads();
        #pragma unroll 4
        for (int c4 = 0; c4 < 16; ++c4) {
            float4 q[4], k[4];
            #pragma unroll
            for (int i = 0; i < 4; ++i)
                q[i] = *(const float4*)&qs[(tt * 4 + i) * QS_STRIDE + c4 * 4];
            #pragma unroll
            for (int j = 0; j < 4; ++j)
                k[j] = *(const float4*)&ks[(ss * 4 + j) * QS_STRIDE + c4 * 4];
            #pragma unroll
            for (int i = 0; i < 4; ++i)
                #pragma unroll
                for (int j = 0; j < 4; ++j) {
                    accA[i][j] = ffma2(make_float2(q[i].x, q[i].y),
                                       make_float2(k[j].x, k[j].y), accA[i][j]);
                    accA[i][j] = ffma2(make_float2(q[i].z, q[i].w),
                                       make_float2(k[j].z, k[j].w), accA[i][j]);
                }
        }
        __syncthreads();
    }
    #pragma unroll
    for (int i = 0; i < 4; ++i)
        #pragma unroll
        for (int j = 0; j < 4; ++j) {
            int t = tt * 4 + i, s = ss * 4 + j;
            As[t * 64 + s] = (s <= t) ? (accA[i][j].x + accA[i][j].y) : 0.f;
        }
    __syncthreads();

    const int dd = tid & 15;
    const int smax = tt * 4 + 4;
    for (int dt = 0; dt < 4; ++dt) {
        #pragma unroll
        for (int u = 0; u < 8; ++u) {
            float4 vv = *(const float4*)&Vb[(size_t)r * C_ + dt * 128 + cseg * 32 + u * 4];
            *(float4*)&vs[r * 128 + cseg * 32 + u * 4] = vv;
        }
        __syncthreads();
        float2 accO[4][4];
        #pragma unroll
        for (int i = 0; i < 4; ++i)
            #pragma unroll
            for (int p = 0; p < 4; ++p) accO[i][p] = make_float2(0.f, 0.f);
        for (int s = 0; s < smax; ++s) {
            float4 v0 = *(const float4*)&vs[s * 128 + dd * 8];
            float4 v1 = *(const float4*)&vs[s * 128 + dd * 8 + 4];
            float2 vp[4] = { make_float2(v0.x, v0.y), make_float2(v0.z, v0.w),
                             make_float2(v1.x, v1.y), make_float2(v1.z, v1.w) };
            #pragma unroll
            for (int i = 0; i < 4; ++i) {
                float a = As[(tt * 4 + i) * 64 + s];
                float2 a2 = make_float2(a, a);
                #pragma unroll
                for (int p = 0; p < 4; ++p)
                    accO[i][p] = ffma2(a2, vp[p], accO[i][p]);
            }
        }
        #pragma unroll
        for (int i = 0; i < 4; ++i) {
            float4 o0 = make_float4(accO[i][0].x, accO[i][0].y, accO[i][1].x, accO[i][1].y);
            float4 o1 = make_float4(accO[i][2].x, accO[i][2].y, accO[i][3].x, accO[i][3].y);
            float* dst = &g_OL[(rowbase + tt * 4 + i) * C_ + dt * 128 + dd * 8];
            *(float4*)dst = o0;
            *(float4*)(dst + 4) = o1;
        }
        __syncthreads();
    }
}

// ---------------- chunked state scan v3 (unchanged, passing) ----------------
#define ST_S 516
#define QK_S 132
#define VD_S 36
#define RED_CG 1032

__global__ __launch_bounds__(512) void scan3_kernel(
        float* __restrict__ O, float* __restrict__ Sout, int writeS) {
    extern __shared__ float sm[];
    float* ST  = sm;
    float* QK  = ST + 16 * ST_S;
    float* VD  = QK + 64 * QK_S;
    float* RED = VD + 64 * VD_S;

    const int tid = threadIdx.x;
    const int b  = blockIdx.x >> 5;
    const int d0 = (blockIdx.x & 31) * 16;
    const int dg   = tid & 7;
    const int cgL  = (tid >> 3) & 3;
    const int tg   = (tid >> 5) & 7;
    const int cgH  = tid >> 8;
    const int cg   = cgH * 4 + cgL;
    const int dloc = dg * 2;
    const int w16 = tid >> 5;
    const int sg  = (tid >> 3) & 3;
    const int ot  = (tid * 2) >> 4;
    const int odl = (tid * 2) & 15;

    const float* Qb  = g_Qs + (size_t)b * T_ * C_;
    const float* Kb  = g_Ks + (size_t)b * T_ * C_;
    const float* Vb  = g_V  + (size_t)b * T_ * C_;
    const float* OLb = g_OL + (size_t)b * T_ * C_;
    float* Ob = O + (size_t)b * T_ * C_;

    for (int i = tid; i < 16 * ST_S; i += 512) ST[i] = 0.f;

    float4 P[4]; float2 Pv; float2 Pol = make_float2(0.f, 0.f);
    {
        #pragma unroll
        for (int u = 0; u < 4; ++u) {
            int f4 = tid + 512 * u, row = f4 >> 5, col = f4 & 31;
            P[u] = __ldg((const float4*)&Qb[(size_t)row * C_ + col * 4]);
        }
        Pv = __ldg((const float2*)&Vb[(size_t)ot * C_ + d0 + odl]);
    }

    float2 acc1[8][2];
    #pragma unroll
    for (int i = 0; i < 8; ++i) { acc1[i][0] = make_float2(0.f,0.f); acc1[i][1] = make_float2(0.f,0.f); }

    for (int ch = 0; ch < NCHUNK; ++ch) {
        const size_t crow = (size_t)ch * CHUNK;
        const float Rch = __ldg(&g_SR[ch]);

        for (int ph = 0; ph < 8; ++ph) {
            __syncthreads();
            #pragma unroll
            for (int u = 0; u < 4; ++u) {
                int f4 = tid + 512 * u, row = f4 >> 5, col = f4 & 31;
                *(float4*)&QK[row * QK_S + col * 4] = P[u];
            }
            if (ph == 0)
                *(float4*)&VD[ot * VD_S + odl * 2] = make_float4(Pv.x, Pv.x, Pv.y, Pv.y);
            __syncthreads();

            {
                const float* src; size_t rb = crow; int tix;
                if (ph < 3)      { src = Qb; tix = ph + 1; }
                else if (ph < 7) { src = Kb; tix = ph - 3; }
                else {
                    int chn = (ch < NCHUNK - 1) ? ch + 1 : ch;
                    rb = (size_t)chn * CHUNK; src = Qb; tix = 0;
                    Pv = __ldg((const float2*)&Vb[(rb + ot) * C_ + d0 + odl]);
                }
                #pragma unroll
                for (int u = 0; u < 4; ++u) {
                    int f4 = tid + 512 * u, row = f4 >> 5, col = f4 & 31;
                    P[u] = __ldg((const float4*)&src[(rb + row) * C_ + tix * 128 + col * 4]);
                }
                if (ph == 2)
                    Pol = __ldg((const float2*)&OLb[(crow + ot) * C_ + d0 + odl]);
            }

            if (ph < 4) {
                #pragma unroll
                for (int j = 0; j < 4; ++j) {
                    const int cl = cg * 4 + j * 32;
                    const int gc = ph * 128 + cl;
                    float4 Sa = *(const float4*)&ST[dloc * ST_S + gc];
                    float4 Sb = *(const float4*)&ST[(dloc + 1) * ST_S + gc];
                    float2 sa0 = make_float2(Sa.x, Sa.y), sa1 = make_float2(Sa.z, Sa.w);
                    float2 sb0 = make_float2(Sb.x, Sb.y), sb1 = make_float2(Sb.z, Sb.w);
                    #pragma unroll
                    for (int i = 0; i < 8; ++i) {
                        float4 q = *(const float4*)&QK[(tg * 8 + i) * QK_S + cl];
                        float2 q0 = make_float2(q.x, q.y), q1 = make_float2(q.z, q.w);
                        acc1[i][0] = ffma2(q0, sa0, acc1[i][0]);
                        acc1[i][0] = ffma2(q1, sa1, acc1[i][0]);
                        acc1[i][1] = ffma2(q0, sb0, acc1[i][1]);
                        acc1[i][1] = ffma2(q1, sb1, acc1[i][1]);
                    }
                }
                if (ph == 3) {
                    #pragma unroll
                    for (int i = 0; i < 8; ++i) {
                        RED[cg * RED_CG + (tg * 8 + i) * 16 + dloc]     = acc1[i][0].x + acc1[i][0].y;
                        RED[cg * RED_CG + (tg * 8 + i) * 16 + dloc + 1] = acc1[i][1].x + acc1[i][1].y;
                        acc1[i][0] = make_float2(0.f, 0.f);
                        acc1[i][1] = make_float2(0.f, 0.f);
                    }
                    __syncthreads();
                    float s0 = 0.f, s1 = 0.f;
                    #pragma unroll
                    for (int g = 0; g < 8; ++g) {
                        s0 += RED[g * RED_CG + ot * 16 + odl];
                        s1 += RED[g * RED_CG + ot * 16 + odl + 1];
                    }
                    float2 o = make_float2(tanhf(s0 + Pol.x), tanhf(s1 + Pol.y));
                    *(float2*)&Ob[(crow + ot) * C_ + d0 + odl] = o;
                }
            } else {
                float2 a[4][2];
                #pragma unroll
                for (int cp = 0; cp < 4; ++cp) { a[cp][0] = make_float2(0.f,0.f); a[cp][1] = make_float2(0.f,0.f); }
                #pragma unroll 4
                for (int si = 0; si < 16; ++si) {
                    int s = sg + 4 * si;
                    float4 ka = *(const float4*)&QK[s * QK_S + w16 * 8];
                    float4 kb = *(const float4*)&QK[s * QK_S + w16 * 8 + 4];
                    float4 v  = *(const float4*)&VD[s * VD_S + dloc * 2];
                    float2 v0 = make_float2(v.x, v.y), v1 = make_float2(v.z, v.w);
                    float2 k0 = make_float2(ka.x, ka.y), k1 = make_float2(ka.z, ka.w);
                    float2 k2 = make_float2(kb.x, kb.y), k3 = make_float2(kb.z, kb.w);
                    a[0][0] = ffma2(k0, v0, a[0][0]); a[0][1] = ffma2(k0, v1, a[0][1]);
                    a[1][0] = ffma2(k1, v0, a[1][0]); a[1][1] = ffma2(k1, v1, a[1][1]);
                    a[2][0] = ffma2(k2, v0, a[2][0]); a[2][1] = ffma2(k2, v1, a[2][1]);
                    a[3][0] = ffma2(k3, v0, a[3][0]); a[3][1] = ffma2(k3, v1, a[3][1]);
                }
                const int b0 = sg & 1, b1 = sg >> 1;
                float2 mine[2];
                #pragma unroll
                for (int dd = 0; dd < 2; ++dd) {
                    float2 s01 = b0 ? a[0][dd] : a[1][dd];
                    float2 s23 = b0 ? a[2][dd] : a[3][dd];
                    float2 r01, r23;
                    r01.x = __shfl_xor_sync(0xffffffffu, s01.x, 8);
                    r01.y = __shfl_xor_sync(0xffffffffu, s01.y, 8);
                    r23.x = __shfl_xor_sync(0xffffffffu, s23.x, 8);
                    r23.y = __shfl_xor_sync(0xffffffffu, s23.y, 8);
                    float2 ka_ = b0 ? a[1][dd] : a[0][dd];
                    float2 kb_ = b0 ? a[3][dd] : a[2][dd];
                    ka_.x += r01.x; ka_.y += r01.y;
                    kb_.x += r23.x; kb_.y += r23.y;
                    float2 snd = b1 ? ka_ : kb_;
                    float2 rcv;
                    rcv.x = __shfl_xor_sync(0xffffffffu, snd.x, 16);
                    rcv.y = __shfl_xor_sync(0xffffffffu, snd.y, 16);
                    float2 kp = b1 ? kb_ : ka_;
                    mine[dd] = make_float2(kp.x + rcv.x, kp.y + rcv.y);
                }
                const int gc = (ph - 4) * 128 + w16 * 8 + sg * 2;
                float2 R2 = make_float2(Rch, Rch);
                #pragma unroll
                for (int dd = 0; dd < 2; ++dd) {
                    float2 Sold = *(const float2*)&ST[(dloc + dd) * ST_S + gc];
                    float2 t = fmul2_(mine[dd], R2);
                    *(float2*)&ST[(dloc + dd) * ST_S + gc] = ffma2(Sold, R2, t);
                }
            }
        }
    }

    __syncthreads();
    if (writeS) {
        for (int idx = tid; idx < C_ * 16; idx += 512) {
            int c = idx >> 4, dl = idx & 15;
            Sout[((size_t)b * C_ + c) * C_ + d0 + dl] = ST[dl * ST_S + c];
        }
    }
}

extern "C" void kernel_launch(void* const* d_in, const int* in_sizes, int n_in,
                              void* d_out, int out_size) {
    const float* X  = (const float*)d_in[0];
    // d_in[1] = S_n (ignored; reference resets state to zero)
    const float* WQ = (const float*)d_in[2];
    const float* bQ = (const float*)d_in[3];
    const float* WK = (const float*)d_in[4];
    const float* bK = (const float*)d_in[5];
    const float* WV = (const float*)d_in[6];
    const float* bV = (const float*)d_in[7];
    float* out = (float*)d_out;

    const int oElems = B_ * T_ * C_;
    const int sElems = B_ * C_ * C_;
    int writeS = (out_size >= oElems + sElems) ? 1 : 0;
    float* Sout = out + oElems;

    const int smP = 4 * TILE_HW * 2;   // 40960 B
    const int sm3 = (2 * 64 * QS_STRIDE + 64 * 64 + 64 * 128) * 4;
    const int smS = (16 * ST_S + 64 * QK_S + 64 * VD_S + 8 * RED_CG) * 4;
    cudaFuncSetAttribute(projmma_kernel, cudaFuncAttributeMaxDynamicSharedMemorySize, smP);
    cudaFuncSetAttribute(local_kernel, cudaFuncAttributeMaxDynamicSharedMemorySize, sm3);
    cudaFuncSetAttribute(scan3_kernel, cudaFuncAttributeMaxDynamicSharedMemorySize, smS);

    scales_kernel<<<1, NCHUNK>>>();
    convX_kernel<<<(B_ * T_ * C_) / 1024, 256>>>(X);
    dim3 wg(16, 16, 3);
    convW_kernel<<<wg, 256>>>(WQ, WK, WV);
    dim3 pg(12, (B_ * T_) / 128);
    projmma_kernel<<<pg, 256, smP>>>(bQ, bK, bV);
    local_kernel<<<B_ * NCHUNK, 256, sm3>>>();
    scan3_kernel<<<B_ * 32, 512, smS>>>(out, Sout, writeS);
}

// round 7
// speedup vs baseline: 3.0793x; 1.2627x over previous
#include <cuda_runtime.h>
#include <cuda_bf16.h>
#include <cstdint>
#include <cstddef>

#define B_ 4
#define T_ 4096
#define C_ 512
#define CHUNK 64
#define NCHUNK (T_/CHUNK)

typedef unsigned long long ull_t;

__device__ __forceinline__ float2 ffma2(float2 a, float2 b, float2 c) {
    ull_t ua = *reinterpret_cast<ull_t*>(&a);
    ull_t ub = *reinterpret_cast<ull_t*>(&b);
    ull_t uc = *reinterpret_cast<ull_t*>(&c);
    ull_t ud;
    asm("fma.rn.f32x2 %0, %1, %2, %3;" : "=l"(ud) : "l"(ua), "l"(ub), "l"(uc));
    return *reinterpret_cast<float2*>(&ud);
}
// bf16 warp MMA: D(16x8,f32) += A(16x16,row) * B(16x8,col)
__device__ __forceinline__ void mma16816(float* c, const uint32_t* a, const uint32_t* b) {
    asm volatile(
        "mma.sync.aligned.m16n8k16.row.col.f32.bf16.bf16.f32 "
        "{%0,%1,%2,%3}, {%4,%5,%6,%7}, {%8,%9}, {%0,%1,%2,%3};\n"
        : "+f"(c[0]), "+f"(c[1]), "+f"(c[2]), "+f"(c[3])
        : "r"(a[0]), "r"(a[1]), "r"(a[2]), "r"(a[3]), "r"(b[0]), "r"(b[1]));
}
__device__ __forceinline__ uint32_t smem_u32(const void* p) {
    uint32_t a;
    asm("{ .reg .u64 t; cvta.to.shared.u64 t, %1; cvt.u32.u64 %0, t; }" : "=r"(a) : "l"(p));
    return a;
}
__device__ __forceinline__ void cpasync16(uint32_t s, const void* g) {
    asm volatile("cp.async.cg.shared.global [%0], [%1], 16;" :: "r"(s), "l"(g));
}
#define CP_COMMIT() asm volatile("cp.async.commit_group;" ::: "memory")
#define CP_WAIT0()  asm volatile("cp.async.wait_group 0;" ::: "memory")

// -------- scratch (__device__ globals) --------
__device__ float g_Qs[B_*T_*C_];   // Q~ = Q * r_t
__device__ float g_Ks[B_*T_*C_];   // K~ = K / r_t
__device__ float g_V [B_*T_*C_];
__device__ float g_OL[B_*T_*C_];   // per-chunk local attention output
__device__ float g_sQ[T_];
__device__ float g_sK[T_];
__device__ float g_SR[NCHUNK];
// split-bf16 operands
__device__ __nv_bfloat16 g_Xh[B_*T_*C_];
__device__ __nv_bfloat16 g_Xl[B_*T_*C_];
__device__ __nv_bfloat16 g_Wht[3*C_*C_];  // [which][n][k]
__device__ __nv_bfloat16 g_Wlt[3*C_*C_];
__device__ __nv_bfloat16 g_Qh[B_*T_*C_];   // [b][t][c]
__device__ __nv_bfloat16 g_Ql[B_*T_*C_];
__device__ __nv_bfloat16 g_KTh[B_*C_*T_];  // [b][c][t]
__device__ __nv_bfloat16 g_KTl[B_*C_*T_];
__device__ __nv_bfloat16 g_VTh[B_*C_*T_];  // [b][d][t]
__device__ __nv_bfloat16 g_VTl[B_*C_*T_];

// -------- gamma scales --------
__global__ void scales_kernel() {
    int ch = threadIdx.x;
    if (ch >= NCHUNK) return;
    const float step = 0.03f / 4095.0f;
    float r = 1.0f;
    for (int i = 0; i < CHUNK; ++i) {
        int t = ch * CHUNK + i;
        float g = 0.96f + step * (float)t;
        r *= g;
        g_sQ[t] = r;
        g_sK[t] = 1.0f / r;
    }
    g_SR[ch] = r;
}

// -------- split-bf16 converts --------
__global__ __launch_bounds__(256) void convX_kernel(const float* __restrict__ X) {
    int i = blockIdx.x * 256 + threadIdx.x;
    float4 v = *(const float4*)&X[(size_t)i * 4];
    __nv_bfloat16 h[4], l[4];
    float vv[4] = {v.x, v.y, v.z, v.w};
    #pragma unroll
    for (int j = 0; j < 4; ++j) {
        h[j] = __float2bfloat16(vv[j]);
        l[j] = __float2bfloat16(vv[j] - __bfloat162float(h[j]));
    }
    *(uint2*)&g_Xh[(size_t)i * 4] = *(uint2*)h;
    *(uint2*)&g_Xl[(size_t)i * 4] = *(uint2*)l;
}

__global__ __launch_bounds__(256) void convW_kernel(
        const float* __restrict__ W0, const float* __restrict__ W1,
        const float* __restrict__ W2) {
    __shared__ float tile[32][33];
    const int w = blockIdx.z;
    const float* W = (w == 0) ? W0 : ((w == 1) ? W1 : W2);
    const int k0 = blockIdx.y * 32, n0 = blockIdx.x * 32;
    const int tx = threadIdx.x & 31, ty = threadIdx.x >> 5;
    #pragma unroll
    for (int i = 0; i < 32; i += 8)
        tile[ty + i][tx] = W[(size_t)(k0 + ty + i) * C_ + n0 + tx];
    __syncthreads();
    #pragma unroll
    for (int i = 0; i < 32; i += 8) {
        int nl = ty + i;
        float v = tile[tx][nl];
        __nv_bfloat16 h = __float2bfloat16(v);
        __nv_bfloat16 l = __float2bfloat16(v - __bfloat162float(h));
        size_t o = ((size_t)w * C_ + (n0 + nl)) * C_ + k0 + tx;
        g_Wht[o] = h;
        g_Wlt[o] = l;
    }
}

// split of Q~ (row-major, for scan GEMM1 A operand)
__global__ __launch_bounds__(256) void convQ_kernel() {
    int i = blockIdx.x * 256 + threadIdx.x;
    float4 v = *(const float4*)&g_Qs[(size_t)i * 4];
    __nv_bfloat16 h[4], l[4];
    float vv[4] = {v.x, v.y, v.z, v.w};
    #pragma unroll
    for (int j = 0; j < 4; ++j) {
        h[j] = __float2bfloat16(vv[j]);
        l[j] = __float2bfloat16(vv[j] - __bfloat162float(h[j]));
    }
    *(uint2*)&g_Qh[(size_t)i * 4] = *(uint2*)h;
    *(uint2*)&g_Ql[(size_t)i * 4] = *(uint2*)l;
}

// transposed splits: K~ -> g_KT*, V -> g_VT*   ([b][c][t])
__global__ __launch_bounds__(256) void convT_kernel() {
    __shared__ float tile[32][33];
    const int z = blockIdx.z;
    const int b = z >> 1, which = z & 1;
    const float* src = (which ? g_V : g_Ks) + (size_t)b * T_ * C_;
    __nv_bfloat16* dh = (which ? g_VTh : g_KTh) + (size_t)b * C_ * T_;
    __nv_bfloat16* dl = (which ? g_VTl : g_KTl) + (size_t)b * C_ * T_;
    const int t0 = blockIdx.x * 32, c0 = blockIdx.y * 32;
    const int tx = threadIdx.x & 31, ty = threadIdx.x >> 5;
    #pragma unroll
    for (int i = 0; i < 32; i += 8)
        tile[ty + i][tx] = src[(size_t)(t0 + ty + i) * C_ + c0 + tx];
    __syncthreads();
    #pragma unroll
    for (int i = 0; i < 32; i += 8) {
        int c = c0 + ty + i;
        float v = tile[tx][ty + i];
        __nv_bfloat16 h = __float2bfloat16(v);
        __nv_bfloat16 l = __float2bfloat16(v - __bfloat162float(h));
        dh[(size_t)c * T_ + t0 + tx] = h;
        dl[(size_t)c * T_ + t0 + tx] = l;
    }
}

// -------- HMMA projection (unchanged, passing: 271us) --------
#define SA 40
#define TILE_HW (128 * SA)
__global__ __launch_bounds__(256, 2) void projmma_kernel(
        const float* __restrict__ bQ, const float* __restrict__ bK,
        const float* __restrict__ bV) {
    extern __shared__ __nv_bfloat16 sh[];
    __nv_bfloat16* Ah = sh;
    __nv_bfloat16* Al = sh + TILE_HW;
    __nv_bfloat16* Bh = sh + 2 * TILE_HW;
    __nv_bfloat16* Bl = sh + 3 * TILE_HW;

    const int tid = threadIdx.x;
    const int w = tid >> 5, lane = tid & 31;
    const int g = lane >> 2, t4 = lane & 3;
    const int wm = w >> 2, wn = w & 3;
    const int which = blockIdx.x >> 2;
    const int n0 = (blockIdx.x & 3) * 128;
    const int m0 = blockIdx.y * 128;
    const float* bias = (which == 0) ? bQ : ((which == 1) ? bK : bV);
    float* out = (which == 0) ? g_Qs : ((which == 1) ? g_Ks : g_V);
    const __nv_bfloat16* WhT = g_Wht + (size_t)which * C_ * C_;
    const __nv_bfloat16* WlT = g_Wlt + (size_t)which * C_ * C_;

    float acc[4][4][4];
    #pragma unroll
    for (int i = 0; i < 4; ++i)
        #pragma unroll
        for (int j = 0; j < 4; ++j)
            #pragma unroll
            for (int r = 0; r < 4; ++r) acc[i][j][r] = 0.f;

    for (int ck = 0; ck < 16; ++ck) {
        const int k0 = ck * 32;
        __syncthreads();
        #pragma unroll
        for (int u = 0; u < 2; ++u) {
            int unit = tid + u * 256;
            int r = unit >> 2, cg = unit & 3;
            int hw = r * SA + cg * 8;
            size_t ga = (size_t)(m0 + r) * C_ + k0 + cg * 8;
            size_t gb = (size_t)(n0 + r) * C_ + k0 + cg * 8;
            *(uint4*)&Ah[hw] = *(const uint4*)&g_Xh[ga];
            *(uint4*)&Al[hw] = *(const uint4*)&g_Xl[ga];
            *(uint4*)&Bh[hw] = *(const uint4*)&WhT[gb];
            *(uint4*)&Bl[hw] = *(const uint4*)&WlT[gb];
        }
        __syncthreads();

        #pragma unroll
        for (int kk = 0; kk < 32; kk += 16) {
            uint32_t bhf[4][2], blf[4][2];
            #pragma unroll
            for (int nf = 0; nf < 4; ++nf) {
                int hw = (wn * 32 + nf * 8 + g) * SA + kk + 2 * t4;
                bhf[nf][0] = *(const uint32_t*)&Bh[hw];
                bhf[nf][1] = *(const uint32_t*)&Bh[hw + 8];
                blf[nf][0] = *(const uint32_t*)&Bl[hw];
                blf[nf][1] = *(const uint32_t*)&Bl[hw + 8];
            }
            #pragma unroll
            for (int mf = 0; mf < 4; ++mf) {
                int row = (wm * 64 + mf * 16 + g) * SA + kk + 2 * t4;
                uint32_t ah[4], al[4];
                ah[0] = *(const uint32_t*)&Ah[row];
                ah[1] = *(const uint32_t*)&Ah[row + 8 * SA];
                ah[2] = *(const uint32_t*)&Ah[row + 8];
                ah[3] = *(const uint32_t*)&Ah[row + 8 * SA + 8];
                al[0] = *(const uint32_t*)&Al[row];
                al[1] = *(const uint32_t*)&Al[row + 8 * SA];
                al[2] = *(const uint32_t*)&Al[row + 8];
                al[3] = *(const uint32_t*)&Al[row + 8 * SA + 8];
                #pragma unroll
                for (int nf = 0; nf < 4; ++nf) {
                    mma16816(acc[mf][nf], ah, bhf[nf]);
                    mma16816(acc[mf][nf], ah, blf[nf]);
                    mma16816(acc[mf][nf], al, bhf[nf]);
                }
            }
        }
    }

    #pragma unroll
    for (int mf = 0; mf < 4; ++mf) {
        int m = m0 + wm * 64 + mf * 16 + g;
        int tA = m & (T_ - 1);
        int tB = (m + 8) & (T_ - 1);
        float sA = (which == 0) ? g_sQ[tA] : ((which == 1) ? g_sK[tA] : 1.0f);
        float sB = (which == 0) ? g_sQ[tB] : ((which == 1) ? g_sK[tB] : 1.0f);
        #pragma unroll
        for (int nf = 0; nf < 4; ++nf) {
            int n = n0 + wn * 32 + nf * 8 + 2 * t4;
            float2 bb = *(const float2*)&bias[n];
            float2 o0 = make_float2((acc[mf][nf][0] + bb.x) * sA,
                                    (acc[mf][nf][1] + bb.y) * sA);
            float2 o1 = make_float2((acc[mf][nf][2] + bb.x) * sB,
                                    (acc[mf][nf][3] + bb.y) * sB);
            *(float2*)&out[(size_t)m * C_ + n] = o0;
            *(float2*)&out[(size_t)(m + 8) * C_ + n] = o1;
        }
    }
}

// ---------------- local (in-chunk) masked attention (unchanged, passing) ----------------
#define QS_STRIDE 68
__global__ __launch_bounds__(256) void local_kernel() {
    extern __shared__ float sm3[];
    float* qs = sm3;
    float* ks = sm3 + 64 * QS_STRIDE;
    float* As = sm3 + 2 * 64 * QS_STRIDE;
    float* vs = As + 64 * 64;

    const int tid = threadIdx.x;
    const int b  = blockIdx.x >> 6;
    const int ch = blockIdx.x & 63;
    const int tt = tid >> 4, ss = tid & 15;
    const int r = tid >> 2, cseg = tid & 3;
    const size_t rowbase = (size_t)b * T_ + (size_t)ch * CHUNK;
    const float* Qb = g_Qs + rowbase * C_;
    const float* Kb = g_Ks + rowbase * C_;
    const float* Vb = g_V  + rowbase * C_;

    float2 accA[4][4];
    #pragma unroll
    for (int i = 0; i < 4; ++i)
        #pragma unroll
        for (int j = 0; j < 4; ++j) accA[i][j] = make_float2(0.f, 0.f);

    for (int ct = 0; ct < 8; ++ct) {
        #pragma unroll
        for (int u = 0; u < 4; ++u) {
            float4 qv = *(const float4*)&Qb[(size_t)r * C_ + ct * 64 + cseg * 16 + u * 4];
            float4 kv = *(const float4*)&Kb[(size_t)r * C_ + ct * 64 + cseg * 16 + u * 4];
            *(float4*)&qs[r * QS_STRIDE + cseg * 16 + u * 4] = qv;
            *(float4*)&ks[r * QS_STRIDE + cseg * 16 + u * 4] = kv;
        }
        __syncthreads();
        #pragma unroll 4
        for (int c4 = 0; c4 < 16; ++c4) {
            float4 q[4], k[4];
            #pragma unroll
            for (int i = 0; i < 4; ++i)
                q[i] = *(const float4*)&qs[(tt * 4 + i) * QS_STRIDE + c4 * 4];
            #pragma unroll
            for (int j = 0; j < 4; ++j)
                k[j] = *(const float4*)&ks[(ss * 4 + j) * QS_STRIDE + c4 * 4];
            #pragma unroll
            for (int i = 0; i < 4; ++i)
                #pragma unroll
                for (int j = 0; j < 4; ++j) {
                    accA[i][j] = ffma2(make_float2(q[i].x, q[i].y),
                                       make_float2(k[j].x, k[j].y), accA[i][j]);
                    accA[i][j] = ffma2(make_float2(q[i].z, q[i].w),
                                       make_float2(k[j].z, k[j].w), accA[i][j]);
                }
        }
        __syncthreads();
    }
    #pragma unroll
    for (int i = 0; i < 4; ++i)
        #pragma unroll
        for (int j = 0; j < 4; ++j) {
            int t = tt * 4 + i, s = ss * 4 + j;
            As[t * 64 + s] = (s <= t) ? (accA[i][j].x + accA[i][j].y) : 0.f;
        }
    __syncthreads();

    const int dd = tid & 15;
    const int smax = tt * 4 + 4;
    for (int dt = 0; dt < 4; ++dt) {
        #pragma unroll
        for (int u = 0; u < 8; ++u) {
            float4 vv = *(const float4*)&Vb[(size_t)r * C_ + dt * 128 + cseg * 32 + u * 4];
            *(float4*)&vs[r * 128 + cseg * 32 + u * 4] = vv;
        }
        __syncthreads();
        float2 accO[4][4];
        #pragma unroll
        for (int i = 0; i < 4; ++i)
            #pragma unroll
            for (int p = 0; p < 4; ++p) accO[i][p] = make_float2(0.f, 0.f);
        for (int s = 0; s < smax; ++s) {
            float4 v0 = *(const float4*)&vs[s * 128 + dd * 8];
            float4 v1 = *(const float4*)&vs[s * 128 + dd * 8 + 4];
            float2 vp[4] = { make_float2(v0.x, v0.y), make_float2(v0.z, v0.w),
                             make_float2(v1.x, v1.y), make_float2(v1.z, v1.w) };
            #pragma unroll
            for (int i = 0; i < 4; ++i) {
                float a = As[(tt * 4 + i) * 64 + s];
                float2 a2 = make_float2(a, a);
                #pragma unroll
                for (int p = 0; p < 4; ++p)
                    accO[i][p] = ffma2(a2, vp[p], accO[i][p]);
            }
        }
        #pragma unroll
        for (int i = 0; i < 4; ++i) {
            float4 o0 = make_float4(accO[i][0].x, accO[i][0].y, accO[i][1].x, accO[i][1].y);
            float4 o1 = make_float4(accO[i][2].x, accO[i][2].y, accO[i][3].x, accO[i][3].y);
            float* dst = &g_OL[(rowbase + tt * 4 + i) * C_ + dt * 128 + dd * 8];
            *(float4*)dst = o0;
            *(float4*)(dst + 4) = o1;
        }
        __syncthreads();
    }
}

// ---------------- scan v4: HMMA chunked scan ----------------
// 128 CTAs (b, 16-d slab), 256 threads / 8 warps. S fp32 [16][516] + incremental
// bf16 hi/lo copies [16][520]. 8 phases/chunk: q0..q3 (GEMM1 cross = Q~ . S,
// warp = 16-wide k-slice), k0..k3 (GEMM2 S = (S + K~^T V)*R, warp = 16-wide c-slice).
// cp.async double-buffered tile staging.
#define S4_ST    0
#define S4_SHH   33024
#define S4_SHL   49664
#define S4_STG   66304
#define S4_STGSZ 18432
#define S4_VT    140032
#define S4_RED   144640
#define S4_SMEM  177408

__global__ __launch_bounds__(256) void scan4_kernel(
        float* __restrict__ O, float* __restrict__ Sout, int writeS) {
    extern __shared__ char s4[];
    float* ST  = (float*)(s4 + S4_ST);
    __nv_bfloat16* SHh = (__nv_bfloat16*)(s4 + S4_SHH);
    __nv_bfloat16* SHl = (__nv_bfloat16*)(s4 + S4_SHL);
    float* RED = (float*)(s4 + S4_RED);
    const uint32_t sbase = smem_u32(s4);

    const int tid = threadIdx.x;
    const int w = tid >> 5, lane = tid & 31;
    const int g = lane >> 2, t4 = lane & 3;
    const int b = blockIdx.x >> 5;
    const int d0 = (blockIdx.x & 31) * 16;

    const __nv_bfloat16* Qh  = g_Qh  + (size_t)b * T_ * C_;
    const __nv_bfloat16* Ql  = g_Ql  + (size_t)b * T_ * C_;
    const __nv_bfloat16* KTh = g_KTh + (size_t)b * C_ * T_;
    const __nv_bfloat16* KTl = g_KTl + (size_t)b * C_ * T_;
    const __nv_bfloat16* VTh = g_VTh + (size_t)b * C_ * T_;
    const __nv_bfloat16* VTl = g_VTl + (size_t)b * C_ * T_;
    const float* OLb = g_OL + (size_t)b * T_ * C_;
    float* Ob = O + (size_t)b * T_ * C_;

    for (int i = tid; i < 16 * 516; i += 256) ST[i] = 0.f;
    for (int i = tid; i < 16 * 520 / 2; i += 256) {
        ((uint32_t*)SHh)[i] = 0u;
        ((uint32_t*)SHl)[i] = 0u;
    }

    // staging helpers
    auto stage_q = [&](int bufi, size_t rb, int colblk) {
        #pragma unroll
        for (int hl = 0; hl < 2; ++hl) {
            uint32_t sm0 = sbase + S4_STG + (uint32_t)(bufi * 2 + hl) * S4_STGSZ;
            const __nv_bfloat16* src = hl ? Ql : Qh;
            #pragma unroll
            for (int j = 0; j < 4; ++j) {
                int u = tid + 256 * j;
                int row = u >> 4, c16 = u & 15;
                cpasync16(sm0 + row * 272 + c16 * 16,
                          src + (rb + row) * C_ + colblk * 128 + c16 * 8);
            }
        }
    };
    auto stage_k = [&](int bufi, size_t rb, int cblk) {
        #pragma unroll
        for (int hl = 0; hl < 2; ++hl) {
            uint32_t sm0 = sbase + S4_STG + (uint32_t)(bufi * 2 + hl) * S4_STGSZ;
            const __nv_bfloat16* src = hl ? KTl : KTh;
            #pragma unroll
            for (int j = 0; j < 4; ++j) {
                int u = tid + 256 * j;
                int row = u >> 3, c8 = u & 7;
                cpasync16(sm0 + row * 144 + c8 * 16,
                          src + (size_t)(cblk * 128 + row) * T_ + rb + c8 * 8);
            }
        }
    };
    auto stage_vt = [&](size_t rb) {
        int hl = tid >> 7, u = tid & 127;
        int row = u >> 3, c8 = u & 7;
        const __nv_bfloat16* src = hl ? VTl : VTh;
        cpasync16(sbase + S4_VT + hl * 2304 + row * 144 + c8 * 16,
                  src + (size_t)(d0 + row) * T_ + rb + c8 * 8);
    };

    // prologue: preload chunk 0 q-tile 0 into buf 0
    stage_q(0, 0, 0);
    CP_COMMIT(); CP_WAIT0();
    __syncthreads();

    float acc1[4][2][4];
    #pragma unroll
    for (int i = 0; i < 4; ++i)
        #pragma unroll
        for (int j = 0; j < 2; ++j)
            #pragma unroll
            for (int r = 0; r < 4; ++r) acc1[i][j][r] = 0.f;
    float4 olr = make_float4(0.f, 0.f, 0.f, 0.f);
    const int outT = tid >> 2, outD = (tid & 3) * 4;

    for (int ch = 0; ch < NCHUNK; ++ch) {
        const size_t crow = (size_t)ch * CHUNK;
        const float R = __ldg(&g_SR[ch]);

        for (int p = 0; p < 8; ++p) {
            const int buf = p & 1, nbuf = buf ^ 1;
            // issue next-phase prefetch
            if (p < 3)       stage_q(nbuf, crow, p + 1);
            else if (p == 3) { stage_k(nbuf, crow, 0); stage_vt(crow); }
            else if (p < 7)  stage_k(nbuf, crow, p - 3);
            else {
                size_t nrow = (ch + 1 < NCHUNK) ? crow + CHUNK : crow;
                stage_q(nbuf, nrow, 0);
            }
            CP_COMMIT();

            if (p == 0)
                olr = __ldg((const float4*)&OLb[(crow + outT) * C_ + d0 + outD]);

            if (p < 4) {
                const __nv_bfloat16* Qsh = (const __nv_bfloat16*)(s4 + S4_STG + (buf * 2 + 0) * S4_STGSZ);
                const __nv_bfloat16* Qsl = (const __nv_bfloat16*)(s4 + S4_STG + (buf * 2 + 1) * S4_STGSZ);
                uint32_t bh[2][2], bl[2][2];
                #pragma unroll
                for (int nf = 0; nf < 2; ++nf) {
                    int hw = (nf * 8 + g) * 520 + p * 128 + w * 16 + 2 * t4;
                    bh[nf][0] = *(const uint32_t*)&SHh[hw];
                    bh[nf][1] = *(const uint32_t*)&SHh[hw + 8];
                    bl[nf][0] = *(const uint32_t*)&SHl[hw];
                    bl[nf][1] = *(const uint32_t*)&SHl[hw + 8];
                }
                #pragma unroll
                for (int mf = 0; mf < 4; ++mf) {
                    int hw = (mf * 16 + g) * 136 + w * 16 + 2 * t4;
                    uint32_t ah[4], al[4];
                    ah[0] = *(const uint32_t*)&Qsh[hw];
                    ah[1] = *(const uint32_t*)&Qsh[hw + 8 * 136];
                    ah[2] = *(const uint32_t*)&Qsh[hw + 8];
                    ah[3] = *(const uint32_t*)&Qsh[hw + 8 * 136 + 8];
                    al[0] = *(const uint32_t*)&Qsl[hw];
                    al[1] = *(const uint32_t*)&Qsl[hw + 8 * 136];
                    al[2] = *(const uint32_t*)&Qsl[hw + 8];
                    al[3] = *(const uint32_t*)&Qsl[hw + 8 * 136 + 8];
                    #pragma unroll
                    for (int nf = 0; nf < 2; ++nf) {
                        mma16816(acc1[mf][nf], ah, bh[nf]);
                        mma16816(acc1[mf][nf], ah, bl[nf]);
                        mma16816(acc1[mf][nf], al, bh[nf]);
                    }
                }
                if (p == 3) {
                    #pragma unroll
                    for (int mf = 0; mf < 4; ++mf)
                        #pragma unroll
                        for (int nf = 0; nf < 2; ++nf) {
                            int base = w * 1024 + (mf * 16 + g) * 16 + nf * 8 + 2 * t4;
                            *(float2*)&RED[base] = make_float2(acc1[mf][nf][0], acc1[mf][nf][1]);
                            *(float2*)&RED[base + 128] = make_float2(acc1[mf][nf][2], acc1[mf][nf][3]);
                            acc1[mf][nf][0] = acc1[mf][nf][1] = 0.f;
                            acc1[mf][nf][2] = acc1[mf][nf][3] = 0.f;
                        }
                }
            } else {
                if (p == 4) {
                    float4 s = olr;
                    #pragma unroll
                    for (int part = 0; part < 8; ++part) {
                        float4 rr = *(const float4*)&RED[part * 1024 + tid * 4];
                        s.x += rr.x; s.y += rr.y; s.z += rr.z; s.w += rr.w;
                    }
                    float4 o = make_float4(tanhf(s.x), tanhf(s.y), tanhf(s.z), tanhf(s.w));
                    *(float4*)&Ob[(crow + outT) * C_ + d0 + outD] = o;
                }
                const __nv_bfloat16* Ksh = (const __nv_bfloat16*)(s4 + S4_STG + (buf * 2 + 0) * S4_STGSZ);
                const __nv_bfloat16* Ksl = (const __nv_bfloat16*)(s4 + S4_STG + (buf * 2 + 1) * S4_STGSZ);
                const __nv_bfloat16* Vth = (const __nv_bfloat16*)(s4 + S4_VT);
                const __nv_bfloat16* Vtl = (const __nv_bfloat16*)(s4 + S4_VT + 2304);
                float acc2[2][4];
                #pragma unroll
                for (int nf = 0; nf < 2; ++nf)
                    #pragma unroll
                    for (int r = 0; r < 4; ++r) acc2[nf][r] = 0.f;
                #pragma unroll
                for (int ks = 0; ks < 4; ++ks) {
                    int hwA = (w * 16 + g) * 72 + ks * 16 + 2 * t4;
                    uint32_t ah[4], al[4];
                    ah[0] = *(const uint32_t*)&Ksh[hwA];
                    ah[1] = *(const uint32_t*)&Ksh[hwA + 8 * 72];
                    ah[2] = *(const uint32_t*)&Ksh[hwA + 8];
                    ah[3] = *(const uint32_t*)&Ksh[hwA + 8 * 72 + 8];
                    al[0] = *(const uint32_t*)&Ksl[hwA];
                    al[1] = *(const uint32_t*)&Ksl[hwA + 8 * 72];
                    al[2] = *(const uint32_t*)&Ksl[hwA + 8];
                    al[3] = *(const uint32_t*)&Ksl[hwA + 8 * 72 + 8];
                    #pragma unroll
                    for (int nf = 0; nf < 2; ++nf) {
                        int hwB = (nf * 8 + g) * 72 + ks * 16 + 2 * t4;
                        uint32_t bh2[2], bl2[2];
                        bh2[0] = *(const uint32_t*)&Vth[hwB];
                        bh2[1] = *(const uint32_t*)&Vth[hwB + 8];
                        bl2[0] = *(const uint32_t*)&Vtl[hwB];
                        bl2[1] = *(const uint32_t*)&Vtl[hwB + 8];
                        mma16816(acc2[nf], ah, bh2);
                        mma16816(acc2[nf], ah, bl2);
                        mma16816(acc2[nf], al, bh2);
                    }
                }
                // S = (S + delta) * R, plus incremental bf16 split update
                const int cb = (p - 4) * 128 + w * 16 + g;
                #pragma unroll
                for (int nf = 0; nf < 2; ++nf) {
                    const int d = nf * 8 + 2 * t4;
                    #pragma unroll
                    for (int half = 0; half < 2; ++half) {
                        int cc = cb + half * 8;
                        float v0 = (ST[d * 516 + cc] + acc2[nf][half * 2 + 0]) * R;
                        float v1 = (ST[(d + 1) * 516 + cc] + acc2[nf][half * 2 + 1]) * R;
                        ST[d * 516 + cc] = v0;
                        ST[(d + 1) * 516 + cc] = v1;
                        __nv_bfloat16 h0 = __float2bfloat16(v0);
                        __nv_bfloat16 h1 = __float2bfloat16(v1);
                        SHh[d * 520 + cc] = h0;
                        SHh[(d + 1) * 520 + cc] = h1;
                        SHl[d * 520 + cc] = __float2bfloat16(v0 - __bfloat162float(h0));
                        SHl[(d + 1) * 520 + cc] = __float2bfloat16(v1 - __bfloat162float(h1));
                    }
                }
            }
            CP_WAIT0();
            __syncthreads();
        }
    }

    if (writeS) {
        for (int idx = tid; idx < C_ * 16; idx += 256) {
            int c = idx >> 4, dl = idx & 15;
            Sout[((size_t)b * C_ + c) * C_ + d0 + dl] = ST[dl * 516 + c];
        }
    }
}

extern "C" void kernel_launch(void* const* d_in, const int* in_sizes, int n_in,
                              void* d_out, int out_size) {
    const float* X  = (const float*)d_in[0];
    // d_in[1] = S_n (ignored; reference resets state to zero)
    const float* WQ = (const float*)d_in[2];
    const float* bQ = (const float*)d_in[3];
    const float* WK = (const float*)d_in[4];
    const float* bK = (const float*)d_in[5];
    const float* WV = (const float*)d_in[6];
    const float* bV = (const float*)d_in[7];
    float* out = (float*)d_out;

    const int oElems = B_ * T_ * C_;
    const int sElems = B_ * C_ * C_;
    int writeS = (out_size >= oElems + sElems) ? 1 : 0;
    float* Sout = out + oElems;

    const int smP = 4 * TILE_HW * 2;
    const int sm3 = (2 * 64 * QS_STRIDE + 64 * 64 + 64 * 128) * 4;
    cudaFuncSetAttribute(projmma_kernel, cudaFuncAttributeMaxDynamicSharedMemorySize, smP);
    cudaFuncSetAttribute(local_kernel, cudaFuncAttributeMaxDynamicSharedMemorySize, sm3);
    cudaFuncSetAttribute(scan4_kernel, cudaFuncAttributeMaxDynamicSharedMemorySize, S4_SMEM);

    scales_kernel<<<1, NCHUNK>>>();
    convX_kernel<<<(B_ * T_ * C_) / 1024, 256>>>(X);
    dim3 wg(16, 16, 3);
    convW_kernel<<<wg, 256>>>(WQ, WK, WV);
    dim3 pg(12, (B_ * T_) / 128);
    projmma_kernel<<<pg, 256, smP>>>(bQ, bK, bV);
    convQ_kernel<<<(B_ * T_ * C_) / 1024, 256>>>();
    dim3 tg(T_ / 32, C_ / 32, B_ * 2);
    convT_kernel<<<tg, 256>>>();
    local_kernel<<<B_ * NCHUNK, 256, sm3>>>();
    scan4_kernel<<<B_ * 32, 256, S4_SMEM>>>(out, Sout, writeS);
}

// round 8
// speedup vs baseline: 3.2167x; 1.0446x over previous
#include <cuda_runtime.h>
#include <cuda_bf16.h>
#include <cstdint>
#include <cstddef>

#define B_ 4
#define T_ 4096
#define C_ 512
#define CHUNK 64
#define NCHUNK (T_/CHUNK)

typedef unsigned long long ull_t;

// bf16 warp MMA: D(16x8,f32) += A(16x16,row) * B(16x8,col)
__device__ __forceinline__ void mma16816(float* c, const uint32_t* a, const uint32_t* b) {
    asm volatile(
        "mma.sync.aligned.m16n8k16.row.col.f32.bf16.bf16.f32 "
        "{%0,%1,%2,%3}, {%4,%5,%6,%7}, {%8,%9}, {%0,%1,%2,%3};\n"
        : "+f"(c[0]), "+f"(c[1]), "+f"(c[2]), "+f"(c[3])
        : "r"(a[0]), "r"(a[1]), "r"(a[2]), "r"(a[3]), "r"(b[0]), "r"(b[1]));
}
__device__ __forceinline__ uint32_t smem_u32(const void* p) {
    uint32_t a;
    asm("{ .reg .u64 t; cvta.to.shared.u64 t, %1; cvt.u32.u64 %0, t; }" : "=r"(a) : "l"(p));
    return a;
}
__device__ __forceinline__ void cpasync16(uint32_t s, const void* g) {
    asm volatile("cp.async.cg.shared.global [%0], [%1], 16;" :: "r"(s), "l"(g));
}
#define CP_COMMIT() asm volatile("cp.async.commit_group;" ::: "memory")
#define CP_WAIT0()  asm volatile("cp.async.wait_group 0;" ::: "memory")

// -------- scratch (__device__ globals) --------
__device__ float g_Qs[B_*T_*C_];   // Q~ = Q * r_t
__device__ float g_Ks[B_*T_*C_];   // K~ = K / r_t
__device__ float g_V [B_*T_*C_];
__device__ float g_OL[B_*T_*C_];   // per-chunk local attention output
__device__ float g_sQ[T_];
__device__ float g_sK[T_];
__device__ float g_SR[NCHUNK];
// split-bf16 operands
__device__ __nv_bfloat16 g_Xh[B_*T_*C_];
__device__ __nv_bfloat16 g_Xl[B_*T_*C_];
__device__ __nv_bfloat16 g_Wht[3*C_*C_];  // [which][n][k]
__device__ __nv_bfloat16 g_Wlt[3*C_*C_];
__device__ __nv_bfloat16 g_Qh[B_*T_*C_];   // [b][t][c]
__device__ __nv_bfloat16 g_Ql[B_*T_*C_];
__device__ __nv_bfloat16 g_Kh[B_*T_*C_];   // [b][t][c] row-major K~ split
__device__ __nv_bfloat16 g_Kl[B_*T_*C_];
__device__ __nv_bfloat16 g_KTh[B_*C_*T_];  // [b][c][t]
__device__ __nv_bfloat16 g_KTl[B_*C_*T_];
__device__ __nv_bfloat16 g_VTh[B_*C_*T_];  // [b][d][t]
__device__ __nv_bfloat16 g_VTl[B_*C_*T_];

// -------- gamma scales --------
__global__ void scales_kernel() {
    int ch = threadIdx.x;
    if (ch >= NCHUNK) return;
    const float step = 0.03f / 4095.0f;
    float r = 1.0f;
    for (int i = 0; i < CHUNK; ++i) {
        int t = ch * CHUNK + i;
        float g = 0.96f + step * (float)t;
        r *= g;
        g_sQ[t] = r;
        g_sK[t] = 1.0f / r;
    }
    g_SR[ch] = r;
}

// -------- split-bf16 converts --------
__global__ __launch_bounds__(256) void convX_kernel(const float* __restrict__ X) {
    int i = blockIdx.x * 256 + threadIdx.x;
    float4 v = *(const float4*)&X[(size_t)i * 4];
    __nv_bfloat16 h[4], l[4];
    float vv[4] = {v.x, v.y, v.z, v.w};
    #pragma unroll
    for (int j = 0; j < 4; ++j) {
        h[j] = __float2bfloat16(vv[j]);
        l[j] = __float2bfloat16(vv[j] - __bfloat162float(h[j]));
    }
    *(uint2*)&g_Xh[(size_t)i * 4] = *(uint2*)h;
    *(uint2*)&g_Xl[(size_t)i * 4] = *(uint2*)l;
}

__global__ __launch_bounds__(256) void convW_kernel(
        const float* __restrict__ W0, const float* __restrict__ W1,
        const float* __restrict__ W2) {
    __shared__ float tile[32][33];
    const int w = blockIdx.z;
    const float* W = (w == 0) ? W0 : ((w == 1) ? W1 : W2);
    const int k0 = blockIdx.y * 32, n0 = blockIdx.x * 32;
    const int tx = threadIdx.x & 31, ty = threadIdx.x >> 5;
    #pragma unroll
    for (int i = 0; i < 32; i += 8)
        tile[ty + i][tx] = W[(size_t)(k0 + ty + i) * C_ + n0 + tx];
    __syncthreads();
    #pragma unroll
    for (int i = 0; i < 32; i += 8) {
        int nl = ty + i;
        float v = tile[tx][nl];
        __nv_bfloat16 h = __float2bfloat16(v);
        __nv_bfloat16 l = __float2bfloat16(v - __bfloat162float(h));
        size_t o = ((size_t)w * C_ + (n0 + nl)) * C_ + k0 + tx;
        g_Wht[o] = h;
        g_Wlt[o] = l;
    }
}

// split of Q~ (row-major, scan GEMM1 + local GEMM1 A operand)
__global__ __launch_bounds__(256) void convQ_kernel() {
    int i = blockIdx.x * 256 + threadIdx.x;
    float4 v = *(const float4*)&g_Qs[(size_t)i * 4];
    __nv_bfloat16 h[4], l[4];
    float vv[4] = {v.x, v.y, v.z, v.w};
    #pragma unroll
    for (int j = 0; j < 4; ++j) {
        h[j] = __float2bfloat16(vv[j]);
        l[j] = __float2bfloat16(vv[j] - __bfloat162float(h[j]));
    }
    *(uint2*)&g_Qh[(size_t)i * 4] = *(uint2*)h;
    *(uint2*)&g_Ql[(size_t)i * 4] = *(uint2*)l;
}

// transposed splits K~ -> g_KT*, V -> g_VT*; also row-major K~ split
__global__ __launch_bounds__(256) void convT_kernel() {
    __shared__ float tile[32][33];
    const int z = blockIdx.z;
    const int b = z >> 1, which = z & 1;
    const float* src = (which ? g_V : g_Ks) + (size_t)b * T_ * C_;
    __nv_bfloat16* dh = (which ? g_VTh : g_KTh) + (size_t)b * C_ * T_;
    __nv_bfloat16* dl = (which ? g_VTl : g_KTl) + (size_t)b * C_ * T_;
    const int t0 = blockIdx.x * 32, c0 = blockIdx.y * 32;
    const int tx = threadIdx.x & 31, ty = threadIdx.x >> 5;
    #pragma unroll
    for (int i = 0; i < 32; i += 8) {
        float v = src[(size_t)(t0 + ty + i) * C_ + c0 + tx];
        tile[ty + i][tx] = v;
        if (which == 0) {
            __nv_bfloat16 h = __float2bfloat16(v);
            size_t o = (size_t)b * T_ * C_ + (size_t)(t0 + ty + i) * C_ + c0 + tx;
            g_Kh[o] = h;
            g_Kl[o] = __float2bfloat16(v - __bfloat162float(h));
        }
    }
    __syncthreads();
    #pragma unroll
    for (int i = 0; i < 32; i += 8) {
        int c = c0 + ty + i;
        float v = tile[tx][ty + i];
        __nv_bfloat16 h = __float2bfloat16(v);
        __nv_bfloat16 l = __float2bfloat16(v - __bfloat162float(h));
        dh[(size_t)c * T_ + t0 + tx] = h;
        dl[(size_t)c * T_ + t0 + tx] = l;
    }
}

// -------- HMMA projection v2: cp.async double-buffered --------
#define SA 40
#define TILE_HW (128 * SA)
#define PJ_TB   (TILE_HW * 2)       // tile bytes = 10240
#define PJ_BUF  (4 * PJ_TB)         // 40960 per buffer
__global__ __launch_bounds__(256, 2) void projmma_kernel(
        const float* __restrict__ bQ, const float* __restrict__ bK,
        const float* __restrict__ bV) {
    extern __shared__ char shp[];
    const uint32_t sbase = smem_u32(shp);

    const int tid = threadIdx.x;
    const int w = tid >> 5, lane = tid & 31;
    const int g = lane >> 2, t4 = lane & 3;
    const int wm = w >> 2, wn = w & 3;
    const int which = blockIdx.x >> 2;
    const int n0 = (blockIdx.x & 3) * 128;
    const int m0 = blockIdx.y * 128;
    const float* bias = (which == 0) ? bQ : ((which == 1) ? bK : bV);
    float* out = (which == 0) ? g_Qs : ((which == 1) ? g_Ks : g_V);

    const __nv_bfloat16* srcs[4] = {
        g_Xh + (size_t)m0 * C_, g_Xl + (size_t)m0 * C_,
        g_Wht + ((size_t)which * C_ + n0) * C_, g_Wlt + ((size_t)which * C_ + n0) * C_ };

    auto stage = [&](int bufi, int ck) {
        uint32_t base = sbase + (uint32_t)bufi * PJ_BUF;
        const int k0 = ck * 32;
        #pragma unroll
        for (int a = 0; a < 4; ++a) {
            #pragma unroll
            for (int j = 0; j < 2; ++j) {
                int u = tid + j * 256;
                int r = u >> 2, cg = u & 3;
                cpasync16(base + a * PJ_TB + r * 80 + cg * 16,
                          srcs[a] + (size_t)r * C_ + k0 + cg * 8);
            }
        }
    };

    float acc[4][4][4];
    #pragma unroll
    for (int i = 0; i < 4; ++i)
        #pragma unroll
        for (int j = 0; j < 4; ++j)
            #pragma unroll
            for (int r = 0; r < 4; ++r) acc[i][j][r] = 0.f;

    stage(0, 0);
    CP_COMMIT(); CP_WAIT0();
    __syncthreads();

    for (int ck = 0; ck < 16; ++ck) {
        const int buf = ck & 1;
        if (ck + 1 < 16) stage(buf ^ 1, ck + 1);
        CP_COMMIT();

        const __nv_bfloat16* Ah = (const __nv_bfloat16*)(shp + buf * PJ_BUF);
        const __nv_bfloat16* Al = (const __nv_bfloat16*)(shp + buf * PJ_BUF + PJ_TB);
        const __nv_bfloat16* Bh = (const __nv_bfloat16*)(shp + buf * PJ_BUF + 2 * PJ_TB);
        const __nv_bfloat16* Bl = (const __nv_bfloat16*)(shp + buf * PJ_BUF + 3 * PJ_TB);

        #pragma unroll
        for (int kk = 0; kk < 32; kk += 16) {
            uint32_t bhf[4][2], blf[4][2];
            #pragma unroll
            for (int nf = 0; nf < 4; ++nf) {
                int hw = (wn * 32 + nf * 8 + g) * SA + kk + 2 * t4;
                bhf[nf][0] = *(const uint32_t*)&Bh[hw];
                bhf[nf][1] = *(const uint32_t*)&Bh[hw + 8];
                blf[nf][0] = *(const uint32_t*)&Bl[hw];
                blf[nf][1] = *(const uint32_t*)&Bl[hw + 8];
            }
            #pragma unroll
            for (int mf = 0; mf < 4; ++mf) {
                int row = (wm * 64 + mf * 16 + g) * SA + kk + 2 * t4;
                uint32_t ah[4], al[4];
                ah[0] = *(const uint32_t*)&Ah[row];
                ah[1] = *(const uint32_t*)&Ah[row + 8 * SA];
                ah[2] = *(const uint32_t*)&Ah[row + 8];
                ah[3] = *(const uint32_t*)&Ah[row + 8 * SA + 8];
                al[0] = *(const uint32_t*)&Al[row];
                al[1] = *(const uint32_t*)&Al[row + 8 * SA];
                al[2] = *(const uint32_t*)&Al[row + 8];
                al[3] = *(const uint32_t*)&Al[row + 8 * SA + 8];
                #pragma unroll
                for (int nf = 0; nf < 4; ++nf) {
                    mma16816(acc[mf][nf], ah, bhf[nf]);
                    mma16816(acc[mf][nf], ah, blf[nf]);
                    mma16816(acc[mf][nf], al, bhf[nf]);
                }
            }
        }
        CP_WAIT0();
        __syncthreads();
    }

    #pragma unroll
    for (int mf = 0; mf < 4; ++mf) {
        int m = m0 + wm * 64 + mf * 16 + g;
        int tA = m & (T_ - 1);
        int tB = (m + 8) & (T_ - 1);
        float sA = (which == 0) ? g_sQ[tA] : ((which == 1) ? g_sK[tA] : 1.0f);
        float sB = (which == 0) ? g_sQ[tB] : ((which == 1) ? g_sK[tB] : 1.0f);
        #pragma unroll
        for (int nf = 0; nf < 4; ++nf) {
            int n = n0 + wn * 32 + nf * 8 + 2 * t4;
            float2 bb = *(const float2*)&bias[n];
            float2 o0 = make_float2((acc[mf][nf][0] + bb.x) * sA,
                                    (acc[mf][nf][1] + bb.y) * sA);
            float2 o1 = make_float2((acc[mf][nf][2] + bb.x) * sB,
                                    (acc[mf][nf][3] + bb.y) * sB);
            *(float2*)&out[(size_t)m * C_ + n] = o0;
            *(float2*)&out[(size_t)(m + 8) * C_ + n] = o1;
        }
    }
}

// -------- local masked attention via HMMA --------
// grid = B*NCHUNK, 256 threads / 8 warps (wm 2 x wn 4).
// GEMM1: A = Q~ K~^T (64x64, k=512 in 8 chunks); mask; re-split to bf16.
// GEMM2: O_local = A V (64x512 via 4 d-blocks of 128), B operand from VT.
#define L_TILE 9216                 // 64 rows * 144 B
#define L_BUF  (4 * L_TILE)         // 36864
#define L_ASH  (2 * L_BUF)          // 73728
#define L_ASL  (L_ASH + L_TILE)
#define L_SMEM (L_ASL + L_TILE)     // 92160
__global__ __launch_bounds__(256, 2) void localmma_kernel() {
    extern __shared__ char shl[];
    const uint32_t sbase = smem_u32(shl);
    __nv_bfloat16* Ash = (__nv_bfloat16*)(shl + L_ASH);
    __nv_bfloat16* Asl = (__nv_bfloat16*)(shl + L_ASL);

    const int tid = threadIdx.x;
    const int w = tid >> 5, lane = tid & 31;
    const int g = lane >> 2, t4 = lane & 3;
    const int wm = w >> 2, wn = w & 3;
    const int b = blockIdx.x >> 6;
    const int ch = blockIdx.x & 63;
    const size_t rowbase = (size_t)b * T_ + (size_t)ch * CHUNK;

    const __nv_bfloat16* qkSrc[4] = {
        g_Qh + rowbase * C_, g_Ql + rowbase * C_,
        g_Kh + rowbase * C_, g_Kl + rowbase * C_ };
    const __nv_bfloat16* VThb = g_VTh + (size_t)b * C_ * T_;
    const __nv_bfloat16* VTlb = g_VTl + (size_t)b * C_ * T_;

    auto stage_qk = [&](int bufi, int ck) {
        uint32_t base = sbase + (uint32_t)bufi * L_BUF;
        #pragma unroll
        for (int a = 0; a < 4; ++a) {
            #pragma unroll
            for (int j = 0; j < 2; ++j) {
                int u = tid + j * 256;       // 512 units
                int row = u >> 3, c8 = u & 7;
                cpasync16(base + a * L_TILE + row * 144 + c8 * 16,
                          qkSrc[a] + (size_t)row * C_ + ck * 64 + c8 * 8);
            }
        }
    };
    auto stage_vt = [&](int bufi, int dt) {
        uint32_t base = sbase + (uint32_t)bufi * L_BUF;
        #pragma unroll
        for (int hl = 0; hl < 2; ++hl) {
            const __nv_bfloat16* src = hl ? VTlb : VThb;
            #pragma unroll
            for (int j = 0; j < 4; ++j) {
                int u = tid + j * 256;       // 1024 units
                int row = u >> 3, c8 = u & 7;
                cpasync16(base + hl * (2 * L_TILE) + row * 144 + c8 * 16,
                          src + (size_t)(dt * 128 + row) * T_ + ch * CHUNK + c8 * 8);
            }
        }
    };

    // ---- Phase A: A = Q~ K~^T ----
    float acc[2][2][4];
    #pragma unroll
    for (int i = 0; i < 2; ++i)
        #pragma unroll
        for (int j = 0; j < 2; ++j)
            #pragma unroll
            for (int r = 0; r < 4; ++r) acc[i][j][r] = 0.f;

    stage_qk(0, 0);
    CP_COMMIT(); CP_WAIT0();
    __syncthreads();

    for (int ck = 0; ck < 8; ++ck) {
        const int buf = ck & 1;
        if (ck + 1 < 8) stage_qk(buf ^ 1, ck + 1);
        CP_COMMIT();
        const __nv_bfloat16* Qsh = (const __nv_bfloat16*)(shl + buf * L_BUF);
        const __nv_bfloat16* Qsl = (const __nv_bfloat16*)(shl + buf * L_BUF + L_TILE);
        const __nv_bfloat16* Ksh = (const __nv_bfloat16*)(shl + buf * L_BUF + 2 * L_TILE);
        const __nv_bfloat16* Ksl = (const __nv_bfloat16*)(shl + buf * L_BUF + 3 * L_TILE);
        #pragma unroll
        for (int kk = 0; kk < 64; kk += 16) {
            uint32_t bh[2][2], bl[2][2];
            #pragma unroll
            for (int nf = 0; nf < 2; ++nf) {
                int hw = (wn * 16 + nf * 8 + g) * 72 + kk + 2 * t4;
                bh[nf][0] = *(const uint32_t*)&Ksh[hw];
                bh[nf][1] = *(const uint32_t*)&Ksh[hw + 8];
                bl[nf][0] = *(const uint32_t*)&Ksl[hw];
                bl[nf][1] = *(const uint32_t*)&Ksl[hw + 8];
            }
            #pragma unroll
            for (int mf = 0; mf < 2; ++mf) {
                int row = (wm * 32 + mf * 16 + g) * 72 + kk + 2 * t4;
                uint32_t ah[4], al[4];
                ah[0] = *(const uint32_t*)&Qsh[row];
                ah[1] = *(const uint32_t*)&Qsh[row + 8 * 72];
                ah[2] = *(const uint32_t*)&Qsh[row + 8];
                ah[3] = *(const uint32_t*)&Qsh[row + 8 * 72 + 8];
                al[0] = *(const uint32_t*)&Qsl[row];
                al[1] = *(const uint32_t*)&Qsl[row + 8 * 72];
                al[2] = *(const uint32_t*)&Qsl[row + 8];
                al[3] = *(const uint32_t*)&Qsl[row + 8 * 72 + 8];
                #pragma unroll
                for (int nf = 0; nf < 2; ++nf) {
                    mma16816(acc[mf][nf], ah, bh[nf]);
                    mma16816(acc[mf][nf], ah, bl[nf]);
                    mma16816(acc[mf][nf], al, bh[nf]);
                }
            }
        }
        CP_WAIT0();
        __syncthreads();
    }

    // mask (s <= t) + bf16 re-split into smem
    #pragma unroll
    for (int mf = 0; mf < 2; ++mf) {
        #pragma unroll
        for (int nf = 0; nf < 2; ++nf) {
            int t0r = wm * 32 + mf * 16 + g;
            int s0 = wn * 16 + nf * 8 + 2 * t4;
            #pragma unroll
            for (int e = 0; e < 4; ++e) {
                int tt = t0r + (e >> 1) * 8;
                int ss = s0 + (e & 1);
                float v = (ss <= tt) ? acc[mf][nf][e] : 0.f;
                __nv_bfloat16 h = __float2bfloat16(v);
                Ash[tt * 72 + ss] = h;
                Asl[tt * 72 + ss] = __float2bfloat16(v - __bfloat162float(h));
            }
        }
    }
    __syncthreads();

    // ---- Phase B: O_local = A V ----
    stage_vt(0, 0);
    CP_COMMIT(); CP_WAIT0();
    __syncthreads();

    for (int dt = 0; dt < 4; ++dt) {
        const int buf = dt & 1;
        if (dt + 1 < 4) stage_vt(buf ^ 1, dt + 1);
        CP_COMMIT();
        const __nv_bfloat16* Vth = (const __nv_bfloat16*)(shl + buf * L_BUF);
        const __nv_bfloat16* Vtl = (const __nv_bfloat16*)(shl + buf * L_BUF + 2 * L_TILE);

        float acc2[2][4][4];
        #pragma unroll
        for (int i = 0; i < 2; ++i)
            #pragma unroll
            for (int j = 0; j < 4; ++j)
                #pragma unroll
                for (int r = 0; r < 4; ++r) acc2[i][j][r] = 0.f;

        #pragma unroll
        for (int kk = 0; kk < 64; kk += 16) {
            uint32_t bh[4][2], bl[4][2];
            #pragma unroll
            for (int nf = 0; nf < 4; ++nf) {
                int hw = (wn * 32 + nf * 8 + g) * 72 + kk + 2 * t4;
                bh[nf][0] = *(const uint32_t*)&Vth[hw];
                bh[nf][1] = *(const uint32_t*)&Vth[hw + 8];
                bl[nf][0] = *(const uint32_t*)&Vtl[hw];
                bl[nf][1] = *(const uint32_t*)&Vtl[hw + 8];
            }
            #pragma unroll
            for (int mf = 0; mf < 2; ++mf) {
                int row = (wm * 32 + mf * 16 + g) * 72 + kk + 2 * t4;
                uint32_t ah[4], al[4];
                ah[0] = *(const uint32_t*)&Ash[row];
                ah[1] = *(const uint32_t*)&Ash[row + 8 * 72];
                ah[2] = *(const uint32_t*)&Ash[row + 8];
                ah[3] = *(const uint32_t*)&Ash[row + 8 * 72 + 8];
                al[0] = *(const uint32_t*)&Asl[row];
                al[1] = *(const uint32_t*)&Asl[row + 8 * 72];
                al[2] = *(const uint32_t*)&Asl[row + 8];
                al[3] = *(const uint32_t*)&Asl[row + 8 * 72 + 8];
                #pragma unroll
                for (int nf = 0; nf < 4; ++nf) {
                    mma16816(acc2[mf][nf], ah, bh[nf]);
                    mma16816(acc2[mf][nf], ah, bl[nf]);
                    mma16816(acc2[mf][nf], al, bh[nf]);
                }
            }
        }

        #pragma unroll
        for (int mf = 0; mf < 2; ++mf) {
            int tt = wm * 32 + mf * 16 + g;
            #pragma unroll
            for (int nf = 0; nf < 4; ++nf) {
                int d = dt * 128 + wn * 32 + nf * 8 + 2 * t4;
                *(float2*)&g_OL[(rowbase + tt) * C_ + d] =
                    make_float2(acc2[mf][nf][0], acc2[mf][nf][1]);
                *(float2*)&g_OL[(rowbase + tt + 8) * C_ + d] =
                    make_float2(acc2[mf][nf][2], acc2[mf][nf][3]);
            }
        }
        CP_WAIT0();
        __syncthreads();
    }
}

// ---------------- scan v4: HMMA chunked scan (unchanged, passing) ----------------
#define S4_ST    0
#define S4_SHH   33024
#define S4_SHL   49664
#define S4_STG   66304
#define S4_STGSZ 18432
#define S4_VT    140032
#define S4_RED   144640
#define S4_SMEM  177408

__global__ __launch_bounds__(256) void scan4_kernel(
        float* __restrict__ O, float* __restrict__ Sout, int writeS) {
    extern __shared__ char s4[];
    float* ST  = (float*)(s4 + S4_ST);
    __nv_bfloat16* SHh = (__nv_bfloat16*)(s4 + S4_SHH);
    __nv_bfloat16* SHl = (__nv_bfloat16*)(s4 + S4_SHL);
    float* RED = (float*)(s4 + S4_RED);
    const uint32_t sbase = smem_u32(s4);

    const int tid = threadIdx.x;
    const int w = tid >> 5, lane = tid & 31;
    const int g = lane >> 2, t4 = lane & 3;
    const int b = blockIdx.x >> 5;
    const int d0 = (blockIdx.x & 31) * 16;

    const __nv_bfloat16* Qh  = g_Qh  + (size_t)b * T_ * C_;
    const __nv_bfloat16* Ql  = g_Ql  + (size_t)b * T_ * C_;
    const __nv_bfloat16* KTh = g_KTh + (size_t)b * C_ * T_;
    const __nv_bfloat16* KTl = g_KTl + (size_t)b * C_ * T_;
    const __nv_bfloat16* VTh = g_VTh + (size_t)b * C_ * T_;
    const __nv_bfloat16* VTl = g_VTl + (size_t)b * C_ * T_;
    const float* OLb = g_OL + (size_t)b * T_ * C_;
    float* Ob = O + (size_t)b * T_ * C_;

    for (int i = tid; i < 16 * 516; i += 256) ST[i] = 0.f;
    for (int i = tid; i < 16 * 520 / 2; i += 256) {
        ((uint32_t*)SHh)[i] = 0u;
        ((uint32_t*)SHl)[i] = 0u;
    }

    auto stage_q = [&](int bufi, size_t rb, int colblk) {
        #pragma unroll
        for (int hl = 0; hl < 2; ++hl) {
            uint32_t sm0 = sbase + S4_STG + (uint32_t)(bufi * 2 + hl) * S4_STGSZ;
            const __nv_bfloat16* src = hl ? Ql : Qh;
            #pragma unroll
            for (int j = 0; j < 4; ++j) {
                int u = tid + 256 * j;
                int row = u >> 4, c16 = u & 15;
                cpasync16(sm0 + row * 272 + c16 * 16,
                          src + (rb + row) * C_ + colblk * 128 + c16 * 8);
            }
        }
    };
    auto stage_k = [&](int bufi, size_t rb, int cblk) {
        #pragma unroll
        for (int hl = 0; hl < 2; ++hl) {
            uint32_t sm0 = sbase + S4_STG + (uint32_t)(bufi * 2 + hl) * S4_STGSZ;
            const __nv_bfloat16* src = hl ? KTl : KTh;
            #pragma unroll
            for (int j = 0; j < 4; ++j) {
                int u = tid + 256 * j;
                int row = u >> 3, c8 = u & 7;
                cpasync16(sm0 + row * 144 + c8 * 16,
                          src + (size_t)(cblk * 128 + row) * T_ + rb + c8 * 8);
            }
        }
    };
    auto stage_vt = [&](size_t rb) {
        int hl = tid >> 7, u = tid & 127;
        int row = u >> 3, c8 = u & 7;
        const __nv_bfloat16* src = hl ? VTl : VTh;
        cpasync16(sbase + S4_VT + hl * 2304 + row * 144 + c8 * 16,
                  src + (size_t)(d0 + row) * T_ + rb + c8 * 8);
    };

    stage_q(0, 0, 0);
    CP_COMMIT(); CP_WAIT0();
    __syncthreads();

    float acc1[4][2][4];
    #pragma unroll
    for (int i = 0; i < 4; ++i)
        #pragma unroll
        for (int j = 0; j < 2; ++j)
            #pragma unroll
            for (int r = 0; r < 4; ++r) acc1[i][j][r] = 0.f;
    float4 olr = make_float4(0.f, 0.f, 0.f, 0.f);
    const int outT = tid >> 2, outD = (tid & 3) * 4;

    for (int ch = 0; ch < NCHUNK; ++ch) {
        const size_t crow = (size_t)ch * CHUNK;
        const float R = __ldg(&g_SR[ch]);

        for (int p = 0; p < 8; ++p) {
            const int buf = p & 1, nbuf = buf ^ 1;
            if (p < 3)       stage_q(nbuf, crow, p + 1);
            else if (p == 3) { stage_k(nbuf, crow, 0); stage_vt(crow); }
            else if (p < 7)  stage_k(nbuf, crow, p - 3);
            else {
                size_t nrow = (ch + 1 < NCHUNK) ? crow + CHUNK : crow;
                stage_q(nbuf, nrow, 0);
            }
            CP_COMMIT();

            if (p == 0)
                olr = __ldg((const float4*)&OLb[(crow + outT) * C_ + d0 + outD]);

            if (p < 4) {
                const __nv_bfloat16* Qsh = (const __nv_bfloat16*)(s4 + S4_STG + (buf * 2 + 0) * S4_STGSZ);
                const __nv_bfloat16* Qsl = (const __nv_bfloat16*)(s4 + S4_STG + (buf * 2 + 1) * S4_STGSZ);
                uint32_t bh[2][2], bl[2][2];
                #pragma unroll
                for (int nf = 0; nf < 2; ++nf) {
                    int hw = (nf * 8 + g) * 520 + p * 128 + w * 16 + 2 * t4;
                    bh[nf][0] = *(const uint32_t*)&SHh[hw];
                    bh[nf][1] = *(const uint32_t*)&SHh[hw + 8];
                    bl[nf][0] = *(const uint32_t*)&SHl[hw];
                    bl[nf][1] = *(const uint32_t*)&SHl[hw + 8];
                }
                #pragma unroll
                for (int mf = 0; mf < 4; ++mf) {
                    int hw = (mf * 16 + g) * 136 + w * 16 + 2 * t4;
                    uint32_t ah[4], al[4];
                    ah[0] = *(const uint32_t*)&Qsh[hw];
                    ah[1] = *(const uint32_t*)&Qsh[hw + 8 * 136];
                    ah[2] = *(const uint32_t*)&Qsh[hw + 8];
                    ah[3] = *(const uint32_t*)&Qsh[hw + 8 * 136 + 8];
                    al[0] = *(const uint32_t*)&Qsl[hw];
                    al[1] = *(const uint32_t*)&Qsl[hw + 8 * 136];
                    al[2] = *(const uint32_t*)&Qsl[hw + 8];
                    al[3] = *(const uint32_t*)&Qsl[hw + 8 * 136 + 8];
                    #pragma unroll
                    for (int nf = 0; nf < 2; ++nf) {
                        mma16816(acc1[mf][nf], ah, bh[nf]);
                        mma16816(acc1[mf][nf], ah, bl[nf]);
                        mma16816(acc1[mf][nf], al, bh[nf]);
                    }
                }
                if (p == 3) {
                    #pragma unroll
                    for (int mf = 0; mf < 4; ++mf)
                        #pragma unroll
                        for (int nf = 0; nf < 2; ++nf) {
                            int base = w * 1024 + (mf * 16 + g) * 16 + nf * 8 + 2 * t4;
                            *(float2*)&RED[base] = make_float2(acc1[mf][nf][0], acc1[mf][nf][1]);
                            *(float2*)&RED[base + 128] = make_float2(acc1[mf][nf][2], acc1[mf][nf][3]);
                            acc1[mf][nf][0] = acc1[mf][nf][1] = 0.f;
                            acc1[mf][nf][2] = acc1[mf][nf][3] = 0.f;
                        }
                }
            } else {
                if (p == 4) {
                    float4 s = olr;
                    #pragma unroll
                    for (int part = 0; part < 8; ++part) {
                        float4 rr = *(const float4*)&RED[part * 1024 + tid * 4];
                        s.x += rr.x; s.y += rr.y; s.z += rr.z; s.w += rr.w;
                    }
                    float4 o = make_float4(tanhf(s.x), tanhf(s.y), tanhf(s.z), tanhf(s.w));
                    *(float4*)&Ob[(crow + outT) * C_ + d0 + outD] = o;
                }
                const __nv_bfloat16* Ksh = (const __nv_bfloat16*)(s4 + S4_STG + (buf * 2 + 0) * S4_STGSZ);
                const __nv_bfloat16* Ksl = (const __nv_bfloat16*)(s4 + S4_STG + (buf * 2 + 1) * S4_STGSZ);
                const __nv_bfloat16* Vth = (const __nv_bfloat16*)(s4 + S4_VT);
                const __nv_bfloat16* Vtl = (const __nv_bfloat16*)(s4 + S4_VT + 2304);
                float acc2[2][4];
                #pragma unroll
                for (int nf = 0; nf < 2; ++nf)
                    #pragma unroll
                    for (int r = 0; r < 4; ++r) acc2[nf][r] = 0.f;
                #pragma unroll
                for (int ks = 0; ks < 4; ++ks) {
                    int hwA = (w * 16 + g) * 72 + ks * 16 + 2 * t4;
                    uint32_t ah[4], al[4];
                    ah[0] = *(const uint32_t*)&Ksh[hwA];
                    ah[1] = *(const uint32_t*)&Ksh[hwA + 8 * 72];
                    ah[2] = *(const uint32_t*)&Ksh[hwA + 8];
                    ah[3] = *(const uint32_t*)&Ksh[hwA + 8 * 72 + 8];
                    al[0] = *(const uint32_t*)&Ksl[hwA];
                    al[1] = *(const uint32_t*)&Ksl[hwA + 8 * 72];
                    al[2] = *(const uint32_t*)&Ksl[hwA + 8];
                    al[3] = *(const uint32_t*)&Ksl[hwA + 8 * 72 + 8];
                    #pragma unroll
                    for (int nf = 0; nf < 2; ++nf) {
                        int hwB = (nf * 8 + g) * 72 + ks * 16 + 2 * t4;
                        uint32_t bh2[2], bl2[2];
                        bh2[0] = *(const uint32_t*)&Vth[hwB];
                        bh2[1] = *(const uint32_t*)&Vth[hwB + 8];
                        bl2[0] = *(const uint32_t*)&Vtl[hwB];
                        bl2[1] = *(const uint32_t*)&Vtl[hwB + 8];
                        mma16816(acc2[nf], ah, bh2);
                        mma16816(acc2[nf], ah, bl2);
                        mma16816(acc2[nf], al, bh2);
                    }
                }
                const int cb = (p - 4) * 128 + w * 16 + g;
                #pragma unroll
                for (int nf = 0; nf < 2; ++nf) {
                    const int d = nf * 8 + 2 * t4;
                    #pragma unroll
                    for (int half = 0; half < 2; ++half) {
                        int cc = cb + half * 8;
                        float v0 = (ST[d * 516 + cc] + acc2[nf][half * 2 + 0]) * R;
                        float v1 = (ST[(d + 1) * 516 + cc] + acc2[nf][half * 2 + 1]) * R;
                        ST[d * 516 + cc] = v0;
                        ST[(d + 1) * 516 + cc] = v1;
                        __nv_bfloat16 h0 = __float2bfloat16(v0);
                        __nv_bfloat16 h1 = __float2bfloat16(v1);
                        SHh[d * 520 + cc] = h0;
                        SHh[(d + 1) * 520 + cc] = h1;
                        SHl[d * 520 + cc] = __float2bfloat16(v0 - __bfloat162float(h0));
                        SHl[(d + 1) * 520 + cc] = __float2bfloat16(v1 - __bfloat162float(h1));
                    }
                }
            }
            CP_WAIT0();
            __syncthreads();
        }
    }

    if (writeS) {
        for (int idx = tid; idx < C_ * 16; idx += 256) {
            int c = idx >> 4, dl = idx & 15;
            Sout[((size_t)b * C_ + c) * C_ + d0 + dl] = ST[dl * 516 + c];
        }
    }
}

extern "C" void kernel_launch(void* const* d_in, const int* in_sizes, int n_in,
                              void* d_out, int out_size) {
    const float* X  = (const float*)d_in[0];
    // d_in[1] = S_n (ignored; reference resets state to zero)
    const float* WQ = (const float*)d_in[2];
    const float* bQ = (const float*)d_in[3];
    const float* WK = (const float*)d_in[4];
    const float* bK = (const float*)d_in[5];
    const float* WV = (const float*)d_in[6];
    const float* bV = (const float*)d_in[7];
    float* out = (float*)d_out;

    const int oElems = B_ * T_ * C_;
    const int sElems = B_ * C_ * C_;
    int writeS = (out_size >= oElems + sElems) ? 1 : 0;
    float* Sout = out + oElems;

    const int smP = 2 * PJ_BUF;     // 81920
    cudaFuncSetAttribute(projmma_kernel, cudaFuncAttributeMaxDynamicSharedMemorySize, smP);
    cudaFuncSetAttribute(localmma_kernel, cudaFuncAttributeMaxDynamicSharedMemorySize, L_SMEM);
    cudaFuncSetAttribute(scan4_kernel, cudaFuncAttributeMaxDynamicSharedMemorySize, S4_SMEM);

    scales_kernel<<<1, NCHUNK>>>();
    convX_kernel<<<(B_ * T_ * C_) / 1024, 256>>>(X);
    dim3 wg(16, 16, 3);
    convW_kernel<<<wg, 256>>>(WQ, WK, WV);
    dim3 pg(12, (B_ * T_) / 128);
    projmma_kernel<<<pg, 256, smP>>>(bQ, bK, bV);
    convQ_kernel<<<(B_ * T_ * C_) / 1024, 256>>>();
    dim3 tg(T_ / 32, C_ / 32, B_ * 2);
    convT_kernel<<<tg, 256>>>();
    localmma_kernel<<<B_ * NCHUNK, 256, L_SMEM>>>();
    scan4_kernel<<<B_ * 32, 256, S4_SMEM>>>(out, Sout, writeS);
}

// round 9
// speedup vs baseline: 4.2622x; 1.3250x over previous
#include <cuda_runtime.h>
#include <cuda_bf16.h>
#include <cstdint>
#include <cstddef>

#define B_ 4
#define T_ 4096
#define C_ 512
#define CHUNK 64
#define NCHUNK (T_/CHUNK)

typedef unsigned long long ull_t;

// bf16 warp MMA: D(16x8,f32) += A(16x16,row) * B(16x8,col)
__device__ __forceinline__ void mma16816(float* c, const uint32_t* a, const uint32_t* b) {
    asm volatile(
        "mma.sync.aligned.m16n8k16.row.col.f32.bf16.bf16.f32 "
        "{%0,%1,%2,%3}, {%4,%5,%6,%7}, {%8,%9}, {%0,%1,%2,%3};\n"
        : "+f"(c[0]), "+f"(c[1]), "+f"(c[2]), "+f"(c[3])
        : "r"(a[0]), "r"(a[1]), "r"(a[2]), "r"(a[3]), "r"(b[0]), "r"(b[1]));
}
__device__ __forceinline__ uint32_t smem_u32(const void* p) {
    uint32_t a;
    asm("{ .reg .u64 t; cvta.to.shared.u64 t, %1; cvt.u32.u64 %0, t; }" : "=r"(a) : "l"(p));
    return a;
}
__device__ __forceinline__ void cpasync16(uint32_t s, const void* g) {
    asm volatile("cp.async.cg.shared.global [%0], [%1], 16;" :: "r"(s), "l"(g));
}
#define CP_COMMIT() asm volatile("cp.async.commit_group;" ::: "memory")
#define CP_WAIT0()  asm volatile("cp.async.wait_group 0;" ::: "memory")

// -------- scratch (__device__ globals) --------
__device__ float g_Qs[B_*T_*C_];   // Q~ = Q * r_t
__device__ float g_Ks[B_*T_*C_];   // K~ = K / r_t
__device__ float g_V [B_*T_*C_];
__device__ float g_OL[B_*T_*C_];   // per-chunk local attention output
__device__ float g_sQ[T_];
__device__ float g_sK[T_];
__device__ float g_SR[NCHUNK];
// split-bf16 operands
__device__ __nv_bfloat16 g_Xh[B_*T_*C_];
__device__ __nv_bfloat16 g_Xl[B_*T_*C_];
__device__ __nv_bfloat16 g_Wht[3*C_*C_];  // [which][n][k]
__device__ __nv_bfloat16 g_Wlt[3*C_*C_];
__device__ __nv_bfloat16 g_Qh[B_*T_*C_];   // [b][t][c]
__device__ __nv_bfloat16 g_Ql[B_*T_*C_];
__device__ __nv_bfloat16 g_Kh[B_*T_*C_];   // [b][t][c] row-major K~ split
__device__ __nv_bfloat16 g_Kl[B_*T_*C_];
__device__ __nv_bfloat16 g_KTh[B_*C_*T_];  // [b][c][t]
__device__ __nv_bfloat16 g_KTl[B_*C_*T_];
__device__ __nv_bfloat16 g_VTh[B_*C_*T_];  // [b][d][t]
__device__ __nv_bfloat16 g_VTl[B_*C_*T_];

// -------- gamma scales --------
__global__ void scales_kernel() {
    int ch = threadIdx.x;
    if (ch >= NCHUNK) return;
    const float step = 0.03f / 4095.0f;
    float r = 1.0f;
    for (int i = 0; i < CHUNK; ++i) {
        int t = ch * CHUNK + i;
        float g = 0.96f + step * (float)t;
        r *= g;
        g_sQ[t] = r;
        g_sK[t] = 1.0f / r;
    }
    g_SR[ch] = r;
}

// -------- split-bf16 converts --------
__global__ __launch_bounds__(256) void convX_kernel(const float* __restrict__ X) {
    int i = blockIdx.x * 256 + threadIdx.x;
    float4 v = *(const float4*)&X[(size_t)i * 4];
    __nv_bfloat16 h[4], l[4];
    float vv[4] = {v.x, v.y, v.z, v.w};
    #pragma unroll
    for (int j = 0; j < 4; ++j) {
        h[j] = __float2bfloat16(vv[j]);
        l[j] = __float2bfloat16(vv[j] - __bfloat162float(h[j]));
    }
    *(uint2*)&g_Xh[(size_t)i * 4] = *(uint2*)h;
    *(uint2*)&g_Xl[(size_t)i * 4] = *(uint2*)l;
}

__global__ __launch_bounds__(256) void convW_kernel(
        const float* __restrict__ W0, const float* __restrict__ W1,
        const float* __restrict__ W2) {
    __shared__ float tile[32][33];
    const int w = blockIdx.z;
    const float* W = (w == 0) ? W0 : ((w == 1) ? W1 : W2);
    const int k0 = blockIdx.y * 32, n0 = blockIdx.x * 32;
    const int tx = threadIdx.x & 31, ty = threadIdx.x >> 5;
    #pragma unroll
    for (int i = 0; i < 32; i += 8)
        tile[ty + i][tx] = W[(size_t)(k0 + ty + i) * C_ + n0 + tx];
    __syncthreads();
    #pragma unroll
    for (int i = 0; i < 32; i += 8) {
        int nl = ty + i;
        float v = tile[tx][nl];
        __nv_bfloat16 h = __float2bfloat16(v);
        __nv_bfloat16 l = __float2bfloat16(v - __bfloat162float(h));
        size_t o = ((size_t)w * C_ + (n0 + nl)) * C_ + k0 + tx;
        g_Wht[o] = h;
        g_Wlt[o] = l;
    }
}

// split of Q~ (row-major)
__global__ __launch_bounds__(256) void convQ_kernel() {
    int i = blockIdx.x * 256 + threadIdx.x;
    float4 v = *(const float4*)&g_Qs[(size_t)i * 4];
    __nv_bfloat16 h[4], l[4];
    float vv[4] = {v.x, v.y, v.z, v.w};
    #pragma unroll
    for (int j = 0; j < 4; ++j) {
        h[j] = __float2bfloat16(vv[j]);
        l[j] = __float2bfloat16(vv[j] - __bfloat162float(h[j]));
    }
    *(uint2*)&g_Qh[(size_t)i * 4] = *(uint2*)h;
    *(uint2*)&g_Ql[(size_t)i * 4] = *(uint2*)l;
}

// transposed splits K~ -> g_KT*, V -> g_VT*; also row-major K~ split
__global__ __launch_bounds__(256) void convT_kernel() {
    __shared__ float tile[32][33];
    const int z = blockIdx.z;
    const int b = z >> 1, which = z & 1;
    const float* src = (which ? g_V : g_Ks) + (size_t)b * T_ * C_;
    __nv_bfloat16* dh = (which ? g_VTh : g_KTh) + (size_t)b * C_ * T_;
    __nv_bfloat16* dl = (which ? g_VTl : g_KTl) + (size_t)b * C_ * T_;
    const int t0 = blockIdx.x * 32, c0 = blockIdx.y * 32;
    const int tx = threadIdx.x & 31, ty = threadIdx.x >> 5;
    #pragma unroll
    for (int i = 0; i < 32; i += 8) {
        float v = src[(size_t)(t0 + ty + i) * C_ + c0 + tx];
        tile[ty + i][tx] = v;
        if (which == 0) {
            __nv_bfloat16 h = __float2bfloat16(v);
            size_t o = (size_t)b * T_ * C_ + (size_t)(t0 + ty + i) * C_ + c0 + tx;
            g_Kh[o] = h;
            g_Kl[o] = __float2bfloat16(v - __bfloat162float(h));
        }
    }
    __syncthreads();
    #pragma unroll
    for (int i = 0; i < 32; i += 8) {
        int c = c0 + ty + i;
        float v = tile[tx][ty + i];
        __nv_bfloat16 h = __float2bfloat16(v);
        __nv_bfloat16 l = __float2bfloat16(v - __bfloat162float(h));
        dh[(size_t)c * T_ + t0 + tx] = h;
        dl[(size_t)c * T_ + t0 + tx] = l;
    }
}

// -------- HMMA projection v2 (unchanged, passing: 231us) --------
#define SA 40
#define TILE_HW (128 * SA)
#define PJ_TB   (TILE_HW * 2)
#define PJ_BUF  (4 * PJ_TB)
__global__ __launch_bounds__(256, 2) void projmma_kernel(
        const float* __restrict__ bQ, const float* __restrict__ bK,
        const float* __restrict__ bV) {
    extern __shared__ char shp[];
    const uint32_t sbase = smem_u32(shp);

    const int tid = threadIdx.x;
    const int w = tid >> 5, lane = tid & 31;
    const int g = lane >> 2, t4 = lane & 3;
    const int wm = w >> 2, wn = w & 3;
    const int which = blockIdx.x >> 2;
    const int n0 = (blockIdx.x & 3) * 128;
    const int m0 = blockIdx.y * 128;
    const float* bias = (which == 0) ? bQ : ((which == 1) ? bK : bV);
    float* out = (which == 0) ? g_Qs : ((which == 1) ? g_Ks : g_V);

    const __nv_bfloat16* srcs[4] = {
        g_Xh + (size_t)m0 * C_, g_Xl + (size_t)m0 * C_,
        g_Wht + ((size_t)which * C_ + n0) * C_, g_Wlt + ((size_t)which * C_ + n0) * C_ };

    auto stage = [&](int bufi, int ck) {
        uint32_t base = sbase + (uint32_t)bufi * PJ_BUF;
        const int k0 = ck * 32;
        #pragma unroll
        for (int a = 0; a < 4; ++a) {
            #pragma unroll
            for (int j = 0; j < 2; ++j) {
                int u = tid + j * 256;
                int r = u >> 2, cg = u & 3;
                cpasync16(base + a * PJ_TB + r * 80 + cg * 16,
                          srcs[a] + (size_t)r * C_ + k0 + cg * 8);
            }
        }
    };

    float acc[4][4][4];
    #pragma unroll
    for (int i = 0; i < 4; ++i)
        #pragma unroll
        for (int j = 0; j < 4; ++j)
            #pragma unroll
            for (int r = 0; r < 4; ++r) acc[i][j][r] = 0.f;

    stage(0, 0);
    CP_COMMIT(); CP_WAIT0();
    __syncthreads();

    for (int ck = 0; ck < 16; ++ck) {
        const int buf = ck & 1;
        if (ck + 1 < 16) stage(buf ^ 1, ck + 1);
        CP_COMMIT();

        const __nv_bfloat16* Ah = (const __nv_bfloat16*)(shp + buf * PJ_BUF);
        const __nv_bfloat16* Al = (const __nv_bfloat16*)(shp + buf * PJ_BUF + PJ_TB);
        const __nv_bfloat16* Bh = (const __nv_bfloat16*)(shp + buf * PJ_BUF + 2 * PJ_TB);
        const __nv_bfloat16* Bl = (const __nv_bfloat16*)(shp + buf * PJ_BUF + 3 * PJ_TB);

        #pragma unroll
        for (int kk = 0; kk < 32; kk += 16) {
            uint32_t bhf[4][2], blf[4][2];
            #pragma unroll
            for (int nf = 0; nf < 4; ++nf) {
                int hw = (wn * 32 + nf * 8 + g) * SA + kk + 2 * t4;
                bhf[nf][0] = *(const uint32_t*)&Bh[hw];
                bhf[nf][1] = *(const uint32_t*)&Bh[hw + 8];
                blf[nf][0] = *(const uint32_t*)&Bl[hw];
                blf[nf][1] = *(const uint32_t*)&Bl[hw + 8];
            }
            #pragma unroll
            for (int mf = 0; mf < 4; ++mf) {
                int row = (wm * 64 + mf * 16 + g) * SA + kk + 2 * t4;
                uint32_t ah[4], al[4];
                ah[0] = *(const uint32_t*)&Ah[row];
                ah[1] = *(const uint32_t*)&Ah[row + 8 * SA];
                ah[2] = *(const uint32_t*)&Ah[row + 8];
                ah[3] = *(const uint32_t*)&Ah[row + 8 * SA + 8];
                al[0] = *(const uint32_t*)&Al[row];
                al[1] = *(const uint32_t*)&Al[row + 8 * SA];
                al[2] = *(const uint32_t*)&Al[row + 8];
                al[3] = *(const uint32_t*)&Al[row + 8 * SA + 8];
                #pragma unroll
                for (int nf = 0; nf < 4; ++nf) {
                    mma16816(acc[mf][nf], ah, bhf[nf]);
                    mma16816(acc[mf][nf], ah, blf[nf]);
                    mma16816(acc[mf][nf], al, bhf[nf]);
                }
            }
        }
        CP_WAIT0();
        __syncthreads();
    }

    #pragma unroll
    for (int mf = 0; mf < 4; ++mf) {
        int m = m0 + wm * 64 + mf * 16 + g;
        int tA = m & (T_ - 1);
        int tB = (m + 8) & (T_ - 1);
        float sA = (which == 0) ? g_sQ[tA] : ((which == 1) ? g_sK[tA] : 1.0f);
        float sB = (which == 0) ? g_sQ[tB] : ((which == 1) ? g_sK[tB] : 1.0f);
        #pragma unroll
        for (int nf = 0; nf < 4; ++nf) {
            int n = n0 + wn * 32 + nf * 8 + 2 * t4;
            float2 bb = *(const float2*)&bias[n];
            float2 o0 = make_float2((acc[mf][nf][0] + bb.x) * sA,
                                    (acc[mf][nf][1] + bb.y) * sA);
            float2 o1 = make_float2((acc[mf][nf][2] + bb.x) * sB,
                                    (acc[mf][nf][3] + bb.y) * sB);
            *(float2*)&out[(size_t)m * C_ + n] = o0;
            *(float2*)&out[(size_t)(m + 8) * C_ + n] = o1;
        }
    }
}

// -------- local masked attention via HMMA (unchanged, passing) --------
#define L_TILE 9216
#define L_BUF  (4 * L_TILE)
#define L_ASH  (2 * L_BUF)
#define L_ASL  (L_ASH + L_TILE)
#define L_SMEM (L_ASL + L_TILE)
__global__ __launch_bounds__(256, 2) void localmma_kernel() {
    extern __shared__ char shl[];
    const uint32_t sbase = smem_u32(shl);
    __nv_bfloat16* Ash = (__nv_bfloat16*)(shl + L_ASH);
    __nv_bfloat16* Asl = (__nv_bfloat16*)(shl + L_ASL);

    const int tid = threadIdx.x;
    const int w = tid >> 5, lane = tid & 31;
    const int g = lane >> 2, t4 = lane & 3;
    const int wm = w >> 2, wn = w & 3;
    const int b = blockIdx.x >> 6;
    const int ch = blockIdx.x & 63;
    const size_t rowbase = (size_t)b * T_ + (size_t)ch * CHUNK;

    const __nv_bfloat16* qkSrc[4] = {
        g_Qh + rowbase * C_, g_Ql + rowbase * C_,
        g_Kh + rowbase * C_, g_Kl + rowbase * C_ };
    const __nv_bfloat16* VThb = g_VTh + (size_t)b * C_ * T_;
    const __nv_bfloat16* VTlb = g_VTl + (size_t)b * C_ * T_;

    auto stage_qk = [&](int bufi, int ck) {
        uint32_t base = sbase + (uint32_t)bufi * L_BUF;
        #pragma unroll
        for (int a = 0; a < 4; ++a) {
            #pragma unroll
            for (int j = 0; j < 2; ++j) {
                int u = tid + j * 256;
                int row = u >> 3, c8 = u & 7;
                cpasync16(base + a * L_TILE + row * 144 + c8 * 16,
                          qkSrc[a] + (size_t)row * C_ + ck * 64 + c8 * 8);
            }
        }
    };
    auto stage_vt = [&](int bufi, int dt) {
        uint32_t base = sbase + (uint32_t)bufi * L_BUF;
        #pragma unroll
        for (int hl = 0; hl < 2; ++hl) {
            const __nv_bfloat16* src = hl ? VTlb : VThb;
            #pragma unroll
            for (int j = 0; j < 4; ++j) {
                int u = tid + j * 256;
                int row = u >> 3, c8 = u & 7;
                cpasync16(base + hl * (2 * L_TILE) + row * 144 + c8 * 16,
                          src + (size_t)(dt * 128 + row) * T_ + ch * CHUNK + c8 * 8);
            }
        }
    };

    float acc[2][2][4];
    #pragma unroll
    for (int i = 0; i < 2; ++i)
        #pragma unroll
        for (int j = 0; j < 2; ++j)
            #pragma unroll
            for (int r = 0; r < 4; ++r) acc[i][j][r] = 0.f;

    stage_qk(0, 0);
    CP_COMMIT(); CP_WAIT0();
    __syncthreads();

    for (int ck = 0; ck < 8; ++ck) {
        const int buf = ck & 1;
        if (ck + 1 < 8) stage_qk(buf ^ 1, ck + 1);
        CP_COMMIT();
        const __nv_bfloat16* Qsh = (const __nv_bfloat16*)(shl + buf * L_BUF);
        const __nv_bfloat16* Qsl = (const __nv_bfloat16*)(shl + buf * L_BUF + L_TILE);
        const __nv_bfloat16* Ksh = (const __nv_bfloat16*)(shl + buf * L_BUF + 2 * L_TILE);
        const __nv_bfloat16* Ksl = (const __nv_bfloat16*)(shl + buf * L_BUF + 3 * L_TILE);
        #pragma unroll
        for (int kk = 0; kk < 64; kk += 16) {
            uint32_t bh[2][2], bl[2][2];
            #pragma unroll
            for (int nf = 0; nf < 2; ++nf) {
                int hw = (wn * 16 + nf * 8 + g) * 72 + kk + 2 * t4;
                bh[nf][0] = *(const uint32_t*)&Ksh[hw];
                bh[nf][1] = *(const uint32_t*)&Ksh[hw + 8];
                bl[nf][0] = *(const uint32_t*)&Ksl[hw];
                bl[nf][1] = *(const uint32_t*)&Ksl[hw + 8];
            }
            #pragma unroll
            for (int mf = 0; mf < 2; ++mf) {
                int row = (wm * 32 + mf * 16 + g) * 72 + kk + 2 * t4;
                uint32_t ah[4], al[4];
                ah[0] = *(const uint32_t*)&Qsh[row];
                ah[1] = *(const uint32_t*)&Qsh[row + 8 * 72];
                ah[2] = *(const uint32_t*)&Qsh[row + 8];
                ah[3] = *(const uint32_t*)&Qsh[row + 8 * 72 + 8];
                al[0] = *(const uint32_t*)&Qsl[row];
                al[1] = *(const uint32_t*)&Qsl[row + 8 * 72];
                al[2] = *(const uint32_t*)&Qsl[row + 8];
                al[3] = *(const uint32_t*)&Qsl[row + 8 * 72 + 8];
                #pragma unroll
                for (int nf = 0; nf < 2; ++nf) {
                    mma16816(acc[mf][nf], ah, bh[nf]);
                    mma16816(acc[mf][nf], ah, bl[nf]);
                    mma16816(acc[mf][nf], al, bh[nf]);
                }
            }
        }
        CP_WAIT0();
        __syncthreads();
    }

    #pragma unroll
    for (int mf = 0; mf < 2; ++mf) {
        #pragma unroll
        for (int nf = 0; nf < 2; ++nf) {
            int t0r = wm * 32 + mf * 16 + g;
            int s0 = wn * 16 + nf * 8 + 2 * t4;
            #pragma unroll
            for (int e = 0; e < 4; ++e) {
                int tt = t0r + (e >> 1) * 8;
                int ss = s0 + (e & 1);
                float v = (ss <= tt) ? acc[mf][nf][e] : 0.f;
                __nv_bfloat16 h = __float2bfloat16(v);
                Ash[tt * 72 + ss] = h;
                Asl[tt * 72 + ss] = __float2bfloat16(v - __bfloat162float(h));
            }
        }
    }
    __syncthreads();

    stage_vt(0, 0);
    CP_COMMIT(); CP_WAIT0();
    __syncthreads();

    for (int dt = 0; dt < 4; ++dt) {
        const int buf = dt & 1;
        if (dt + 1 < 4) stage_vt(buf ^ 1, dt + 1);
        CP_COMMIT();
        const __nv_bfloat16* Vth = (const __nv_bfloat16*)(shl + buf * L_BUF);
        const __nv_bfloat16* Vtl = (const __nv_bfloat16*)(shl + buf * L_BUF + 2 * L_TILE);

        float acc2[2][4][4];
        #pragma unroll
        for (int i = 0; i < 2; ++i)
            #pragma unroll
            for (int j = 0; j < 4; ++j)
                #pragma unroll
                for (int r = 0; r < 4; ++r) acc2[i][j][r] = 0.f;

        #pragma unroll
        for (int kk = 0; kk < 64; kk += 16) {
            uint32_t bh[4][2], bl[4][2];
            #pragma unroll
            for (int nf = 0; nf < 4; ++nf) {
                int hw = (wn * 32 + nf * 8 + g) * 72 + kk + 2 * t4;
                bh[nf][0] = *(const uint32_t*)&Vth[hw];
                bh[nf][1] = *(const uint32_t*)&Vth[hw + 8];
                bl[nf][0] = *(const uint32_t*)&Vtl[hw];
                bl[nf][1] = *(const uint32_t*)&Vtl[hw + 8];
            }
            #pragma unroll
            for (int mf = 0; mf < 2; ++mf) {
                int row = (wm * 32 + mf * 16 + g) * 72 + kk + 2 * t4;
                uint32_t ah[4], al[4];
                ah[0] = *(const uint32_t*)&Ash[row];
                ah[1] = *(const uint32_t*)&Ash[row + 8 * 72];
                ah[2] = *(const uint32_t*)&Ash[row + 8];
                ah[3] = *(const uint32_t*)&Ash[row + 8 * 72 + 8];
                al[0] = *(const uint32_t*)&Asl[row];
                al[1] = *(const uint32_t*)&Asl[row + 8 * 72];
                al[2] = *(const uint32_t*)&Asl[row + 8];
                al[3] = *(const uint32_t*)&Asl[row + 8 * 72 + 8];
                #pragma unroll
                for (int nf = 0; nf < 4; ++nf) {
                    mma16816(acc2[mf][nf], ah, bh[nf]);
                    mma16816(acc2[mf][nf], ah, bl[nf]);
                    mma16816(acc2[mf][nf], al, bh[nf]);
                }
            }
        }

        #pragma unroll
        for (int mf = 0; mf < 2; ++mf) {
            int tt = wm * 32 + mf * 16 + g;
            #pragma unroll
            for (int nf = 0; nf < 4; ++nf) {
                int d = dt * 128 + wn * 32 + nf * 8 + 2 * t4;
                *(float2*)&g_OL[(rowbase + tt) * C_ + d] =
                    make_float2(acc2[mf][nf][0], acc2[mf][nf][1]);
                *(float2*)&g_OL[(rowbase + tt + 8) * C_ + d] =
                    make_float2(acc2[mf][nf][2], acc2[mf][nf][3]);
            }
        }
        CP_WAIT0();
        __syncthreads();
    }
}

// ---------------- scan v5: HMMA chunked scan, 4 phases/chunk ----------------
// 128 CTAs (b, 16-d slab), 256 threads / 8 warps.
// S kept ONLY as bf16 hi/lo [16 d][520 c]. Per chunk:
//   p0,p1: GEMM1 cross = Q~ . S  (k-halves of 256; warp = (m16, n8) tile, no reduction)
//   p2,p3: GEMM2 S = (S + K~^T V)*R (c-halves of 256; warp = 32-c slice)
#define S5_SH    0
#define S5_SL    16640
#define S5_STG   33280
#define S5_TILE  36864
#define S5_BUFSZ (2 * S5_TILE)
#define S5_VT    (S5_STG + 2 * S5_BUFSZ)     // 180736
#define S5_SMEM  (S5_VT + 4608)              // 185344

__global__ __launch_bounds__(256) void scan5_kernel(
        float* __restrict__ O, float* __restrict__ Sout, int writeS) {
    extern __shared__ char s5[];
    __nv_bfloat16* SHh = (__nv_bfloat16*)(s5 + S5_SH);
    __nv_bfloat16* SHl = (__nv_bfloat16*)(s5 + S5_SL);
    const uint32_t sbase = smem_u32(s5);

    const int tid = threadIdx.x;
    const int w = tid >> 5, lane = tid & 31;
    const int g = lane >> 2, t4 = lane & 3;
    const int mg = w >> 1, ng = w & 1;
    const int b = blockIdx.x >> 5;
    const int d0 = (blockIdx.x & 31) * 16;

    const __nv_bfloat16* Qh  = g_Qh  + (size_t)b * T_ * C_;
    const __nv_bfloat16* Ql  = g_Ql  + (size_t)b * T_ * C_;
    const __nv_bfloat16* KTh = g_KTh + (size_t)b * C_ * T_;
    const __nv_bfloat16* KTl = g_KTl + (size_t)b * C_ * T_;
    const __nv_bfloat16* VTh = g_VTh + (size_t)b * C_ * T_;
    const __nv_bfloat16* VTl = g_VTl + (size_t)b * C_ * T_;
    const float* OLb = g_OL + (size_t)b * T_ * C_;
    float* Ob = O + (size_t)b * T_ * C_;

    for (int i = tid; i < 16 * 520 / 2; i += 256) {
        ((uint32_t*)SHh)[i] = 0u;
        ((uint32_t*)SHl)[i] = 0u;
    }

    // q tile: 64 t-rows x 256 c (stride 264 hw); k tile: 256 c-rows x 64 t (stride 72 hw)
    auto stage_q = [&](int bufi, size_t rb, int half) {
        uint32_t base = sbase + S5_STG + (uint32_t)bufi * S5_BUFSZ;
        #pragma unroll
        for (int j = 0; j < 16; ++j) {
            int u = tid + 256 * j;
            int hl = u >> 11, ur = u & 2047;
            int row = ur >> 5, c16 = ur & 31;
            const __nv_bfloat16* src = hl ? Ql : Qh;
            cpasync16(base + (uint32_t)hl * S5_TILE + row * 528 + c16 * 16,
                      src + (rb + row) * C_ + half * 256 + c16 * 8);
        }
    };
    auto stage_k = [&](int bufi, size_t rb, int half) {
        uint32_t base = sbase + S5_STG + (uint32_t)bufi * S5_BUFSZ;
        #pragma unroll
        for (int j = 0; j < 16; ++j) {
            int u = tid + 256 * j;
            int hl = u >> 11, ur = u & 2047;
            int row = ur >> 3, c8 = ur & 7;
            const __nv_bfloat16* src = hl ? KTl : KTh;
            cpasync16(base + (uint32_t)hl * S5_TILE + row * 144 + c8 * 16,
                      src + (size_t)(half * 256 + row) * T_ + rb + c8 * 8);
        }
    };
    auto stage_vt = [&](size_t rb) {
        int hl = tid >> 7, ur = tid & 127;
        int row = ur >> 3, c8 = ur & 7;
        const __nv_bfloat16* src = hl ? VTl : VTh;
        cpasync16(sbase + S5_VT + hl * 2304 + row * 144 + c8 * 16,
                  src + (size_t)(d0 + row) * T_ + rb + c8 * 8);
    };

    stage_q(0, 0, 0);
    CP_COMMIT(); CP_WAIT0();
    __syncthreads();

    float acc1[4] = {0.f, 0.f, 0.f, 0.f};
    float2 ol0 = make_float2(0.f, 0.f), ol1 = make_float2(0.f, 0.f);

    for (int ch = 0; ch < NCHUNK; ++ch) {
        const size_t crow = (size_t)ch * CHUNK;
        const float R = __ldg(&g_SR[ch]);

        for (int p = 0; p < 4; ++p) {
            const int buf = p & 1, nbuf = buf ^ 1;
            if (p == 0) {
                stage_q(nbuf, crow, 1);
                ol0 = __ldg((const float2*)&OLb[(crow + mg * 16 + g) * C_ + d0 + ng * 8 + 2 * t4]);
                ol1 = __ldg((const float2*)&OLb[(crow + mg * 16 + g + 8) * C_ + d0 + ng * 8 + 2 * t4]);
            } else if (p == 1) {
                stage_k(nbuf, crow, 0);
                stage_vt(crow);
            } else if (p == 2) {
                stage_k(nbuf, crow, 1);
            } else {
                size_t nrow = (ch + 1 < NCHUNK) ? crow + CHUNK : crow;
                stage_q(nbuf, nrow, 0);
            }
            CP_COMMIT();

            if (p < 2) {
                // GEMM1: warp tile m=16 (rows mg*16..+16), n=8 (d = ng*8..+8)
                const __nv_bfloat16* Qsh = (const __nv_bfloat16*)(s5 + S5_STG + buf * S5_BUFSZ);
                const __nv_bfloat16* Qsl = (const __nv_bfloat16*)(s5 + S5_STG + buf * S5_BUFSZ + S5_TILE);
                const int bofs = (ng * 8 + g) * 520 + p * 256 + 2 * t4;
                const int arow = (mg * 16 + g) * 264 + 2 * t4;
                #pragma unroll
                for (int kk = 0; kk < 256; kk += 16) {
                    uint32_t bh[2], bl[2];
                    bh[0] = *(const uint32_t*)&SHh[bofs + kk];
                    bh[1] = *(const uint32_t*)&SHh[bofs + kk + 8];
                    bl[0] = *(const uint32_t*)&SHl[bofs + kk];
                    bl[1] = *(const uint32_t*)&SHl[bofs + kk + 8];
                    uint32_t ah[4], al[4];
                    ah[0] = *(const uint32_t*)&Qsh[arow + kk];
                    ah[1] = *(const uint32_t*)&Qsh[arow + kk + 8 * 264];
                    ah[2] = *(const uint32_t*)&Qsh[arow + kk + 8];
                    ah[3] = *(const uint32_t*)&Qsh[arow + kk + 8 * 264 + 8];
                    al[0] = *(const uint32_t*)&Qsl[arow + kk];
                    al[1] = *(const uint32_t*)&Qsl[arow + kk + 8 * 264];
                    al[2] = *(const uint32_t*)&Qsl[arow + kk + 8];
                    al[3] = *(const uint32_t*)&Qsl[arow + kk + 8 * 264 + 8];
                    mma16816(acc1, ah, bh);
                    mma16816(acc1, ah, bl);
                    mma16816(acc1, al, bh);
                }
                if (p == 1) {
                    const int trow = (int)crow + mg * 16 + g;
                    const int d = d0 + ng * 8 + 2 * t4;
                    *(float2*)&Ob[(size_t)trow * C_ + d] =
                        make_float2(tanhf(acc1[0] + ol0.x), tanhf(acc1[1] + ol0.y));
                    *(float2*)&Ob[(size_t)(trow + 8) * C_ + d] =
                        make_float2(tanhf(acc1[2] + ol1.x), tanhf(acc1[3] + ol1.y));
                    acc1[0] = acc1[1] = acc1[2] = acc1[3] = 0.f;
                }
            } else {
                // GEMM2: warp owns 32 c-rows within the 256-c slice
                const __nv_bfloat16* Ksh = (const __nv_bfloat16*)(s5 + S5_STG + buf * S5_BUFSZ);
                const __nv_bfloat16* Ksl = (const __nv_bfloat16*)(s5 + S5_STG + buf * S5_BUFSZ + S5_TILE);
                const __nv_bfloat16* Vth = (const __nv_bfloat16*)(s5 + S5_VT);
                const __nv_bfloat16* Vtl = (const __nv_bfloat16*)(s5 + S5_VT + 2304);
                float acc2[2][2][4];
                #pragma unroll
                for (int i = 0; i < 2; ++i)
                    #pragma unroll
                    for (int j = 0; j < 2; ++j)
                        #pragma unroll
                        for (int r = 0; r < 4; ++r) acc2[i][j][r] = 0.f;
                #pragma unroll
                for (int kk = 0; kk < 64; kk += 16) {
                    uint32_t bh[2][2], bl[2][2];
                    #pragma unroll
                    for (int nf = 0; nf < 2; ++nf) {
                        int hw = (nf * 8 + g) * 72 + kk + 2 * t4;
                        bh[nf][0] = *(const uint32_t*)&Vth[hw];
                        bh[nf][1] = *(const uint32_t*)&Vth[hw + 8];
                        bl[nf][0] = *(const uint32_t*)&Vtl[hw];
                        bl[nf][1] = *(const uint32_t*)&Vtl[hw + 8];
                    }
                    #pragma unroll
                    for (int mf = 0; mf < 2; ++mf) {
                        int row = (w * 32 + mf * 16 + g) * 72 + kk + 2 * t4;
                        uint32_t ah[4], al[4];
                        ah[0] = *(const uint32_t*)&Ksh[row];
                        ah[1] = *(const uint32_t*)&Ksh[row + 8 * 72];
                        ah[2] = *(const uint32_t*)&Ksh[row + 8];
                        ah[3] = *(const uint32_t*)&Ksh[row + 8 * 72 + 8];
                        al[0] = *(const uint32_t*)&Ksl[row];
                        al[1] = *(const uint32_t*)&Ksl[row + 8 * 72];
                        al[2] = *(const uint32_t*)&Ksl[row + 8];
                        al[3] = *(const uint32_t*)&Ksl[row + 8 * 72 + 8];
                        #pragma unroll
                        for (int nf = 0; nf < 2; ++nf) {
                            mma16816(acc2[mf][nf], ah, bh[nf]);
                            mma16816(acc2[mf][nf], ah, bl[nf]);
                            mma16816(acc2[mf][nf], al, bh[nf]);
                        }
                    }
                }
                // S = (S + delta) * R in bf16 hi/lo
                const int cb = (p - 2) * 256 + w * 32;
                #pragma unroll
                for (int mf = 0; mf < 2; ++mf) {
                    #pragma unroll
                    for (int nf = 0; nf < 2; ++nf) {
                        #pragma unroll
                        for (int e = 0; e < 4; ++e) {
                            int c = cb + mf * 16 + g + (e >> 1) * 8;
                            int d = nf * 8 + 2 * t4 + (e & 1);
                            int ad = d * 520 + c;
                            float v = (__bfloat162float(SHh[ad]) + __bfloat162float(SHl[ad])
                                       + acc2[mf][nf][e]) * R;
                            __nv_bfloat16 h = __float2bfloat16(v);
                            SHh[ad] = h;
                            SHl[ad] = __float2bfloat16(v - __bfloat162float(h));
                        }
                    }
                }
            }
            CP_WAIT0();
            __syncthreads();
        }
    }

    if (writeS) {
        for (int idx = tid; idx < C_ * 16; idx += 256) {
            int c = idx >> 4, dl = idx & 15;
            Sout[((size_t)b * C_ + c) * C_ + d0 + dl] =
                __bfloat162float(SHh[dl * 520 + c]) + __bfloat162float(SHl[dl * 520 + c]);
        }
    }
}

extern "C" void kernel_launch(void* const* d_in, const int* in_sizes, int n_in,
                              void* d_out, int out_size) {
    const float* X  = (const float*)d_in[0];
    // d_in[1] = S_n (ignored; reference resets state to zero)
    const float* WQ = (const float*)d_in[2];
    const float* bQ = (const float*)d_in[3];
    const float* WK = (const float*)d_in[4];
    const float* bK = (const float*)d_in[5];
    const float* WV = (const float*)d_in[6];
    const float* bV = (const float*)d_in[7];
    float* out = (float*)d_out;

    const int oElems = B_ * T_ * C_;
    const int sElems = B_ * C_ * C_;
    int writeS = (out_size >= oElems + sElems) ? 1 : 0;
    float* Sout = out + oElems;

    const int smP = 2 * PJ_BUF;
    cudaFuncSetAttribute(projmma_kernel, cudaFuncAttributeMaxDynamicSharedMemorySize, smP);
    cudaFuncSetAttribute(localmma_kernel, cudaFuncAttributeMaxDynamicSharedMemorySize, L_SMEM);
    cudaFuncSetAttribute(scan5_kernel, cudaFuncAttributeMaxDynamicSharedMemorySize, S5_SMEM);

    scales_kernel<<<1, NCHUNK>>>();
    convX_kernel<<<(B_ * T_ * C_) / 1024, 256>>>(X);
    dim3 wg(16, 16, 3);
    convW_kernel<<<wg, 256>>>(WQ, WK, WV);
    dim3 pg(12, (B_ * T_) / 128);
    projmma_kernel<<<pg, 256, smP>>>(bQ, bK, bV);
    convQ_kernel<<<(B_ * T_ * C_) / 1024, 256>>>();
    dim3 tg(T_ / 32, C_ / 32, B_ * 2);
    convT_kernel<<<tg, 256>>>();
    localmma_kernel<<<B_ * NCHUNK, 256, L_SMEM>>>();
    scan5_kernel<<<B_ * 32, 256, S5_SMEM>>>(out, Sout, writeS);
}

// round 10
// speedup vs baseline: 4.5169x; 1.0598x over previous
#include <cuda_runtime.h>
#include <cuda_bf16.h>
#include <cstdint>
#include <cstddef>

#define B_ 4
#define T_ 4096
#define C_ 512
#define CHUNK 64
#define NCHUNK (T_/CHUNK)

// bf16 warp MMA: D(16x8,f32) += A(16x16,row) * B(16x8,col)
__device__ __forceinline__ void mma16816(float* c, const uint32_t* a, const uint32_t* b) {
    asm volatile(
        "mma.sync.aligned.m16n8k16.row.col.f32.bf16.bf16.f32 "
        "{%0,%1,%2,%3}, {%4,%5,%6,%7}, {%8,%9}, {%0,%1,%2,%3};\n"
        : "+f"(c[0]), "+f"(c[1]), "+f"(c[2]), "+f"(c[3])
        : "r"(a[0]), "r"(a[1]), "r"(a[2]), "r"(a[3]), "r"(b[0]), "r"(b[1]));
}
__device__ __forceinline__ void ldsm4(uint32_t* r, uint32_t a) {
    asm volatile("ldmatrix.sync.aligned.m8n8.x4.shared.b16 {%0,%1,%2,%3}, [%4];"
        : "=r"(r[0]), "=r"(r[1]), "=r"(r[2]), "=r"(r[3]) : "r"(a));
}
// A 16x16 tiles (m,k),(m+8,k),(m,k+8),(m+8,k+8); strideHW in halfwords
__device__ __forceinline__ uint32_t addrA(uint32_t base, int row0, int k, int strideHW, int lane) {
    int t = lane >> 3, r = lane & 7;
    return base + (uint32_t)(((row0 + ((t & 1) << 3) + r) * strideHW + k + ((t >> 1) << 3)) * 2);
}
// B (n-major rows) tiles (n,k),(n,k+8),(n+8,k),(n+8,k+8) -> regs b[n0][0],b[n0][1],b[n0+8][0],b[n0+8][1]
__device__ __forceinline__ uint32_t addrB(uint32_t base, int n0, int k, int strideHW, int lane) {
    int t = lane >> 3, r = lane & 7;
    return base + (uint32_t)(((n0 + ((t >> 1) << 3) + r) * strideHW + k + ((t & 1) << 3)) * 2);
}
// B wide-k: tiles (n,k),(n,k+8),(n,k+16),(n,k+24) (n only 8 rows)
__device__ __forceinline__ uint32_t addrBK(uint32_t base, int n0, int k, int strideHW, int lane) {
    int t = lane >> 3, r = lane & 7;
    return base + (uint32_t)(((n0 + r) * strideHW + k + (t << 3)) * 2);
}
__device__ __forceinline__ uint32_t smem_u32(const void* p) {
    uint32_t a;
    asm("{ .reg .u64 t; cvta.to.shared.u64 t, %1; cvt.u32.u64 %0, t; }" : "=r"(a) : "l"(p));
    return a;
}
__device__ __forceinline__ void cpasync16(uint32_t s, const void* g) {
    asm volatile("cp.async.cg.shared.global [%0], [%1], 16;" :: "r"(s), "l"(g));
}
#define CP_COMMIT() asm volatile("cp.async.commit_group;" ::: "memory")
#define CP_WAIT0()  asm volatile("cp.async.wait_group 0;" ::: "memory")

__device__ __forceinline__ void split2(__nv_bfloat16* dh, __nv_bfloat16* dl, float2 v) {
    __nv_bfloat16 h0 = __float2bfloat16(v.x), h1 = __float2bfloat16(v.y);
    __nv_bfloat16 l0 = __float2bfloat16(v.x - __bfloat162float(h0));
    __nv_bfloat16 l1 = __float2bfloat16(v.y - __bfloat162float(h1));
    __nv_bfloat16 hp[2] = {h0, h1}, lp[2] = {l0, l1};
    *(uint32_t*)dh = *(uint32_t*)hp;
    *(uint32_t*)dl = *(uint32_t*)lp;
}

// -------- scratch (__device__ globals) --------
__device__ float g_Ks[B_*T_*C_];   // K~ fp32 (for transpose pass)
__device__ float g_V [B_*T_*C_];
__device__ float g_OL[B_*T_*C_];
__device__ float g_sQ[T_];
__device__ float g_sK[T_];
__device__ float g_SR[NCHUNK];
__device__ __nv_bfloat16 g_Xh[B_*T_*C_];
__device__ __nv_bfloat16 g_Xl[B_*T_*C_];
__device__ __nv_bfloat16 g_Wht[3*C_*C_];
__device__ __nv_bfloat16 g_Wlt[3*C_*C_];
__device__ __nv_bfloat16 g_Qh[B_*T_*C_];   // [b][t][c]
__device__ __nv_bfloat16 g_Ql[B_*T_*C_];
__device__ __nv_bfloat16 g_Kh[B_*T_*C_];
__device__ __nv_bfloat16 g_Kl[B_*T_*C_];
__device__ __nv_bfloat16 g_KTh[B_*C_*T_];  // [b][c][t]
__device__ __nv_bfloat16 g_KTl[B_*C_*T_];
__device__ __nv_bfloat16 g_VTh[B_*C_*T_];
__device__ __nv_bfloat16 g_VTl[B_*C_*T_];

// -------- gamma scales --------
__global__ void scales_kernel() {
    int ch = threadIdx.x;
    if (ch >= NCHUNK) return;
    const float step = 0.03f / 4095.0f;
    float r = 1.0f;
    for (int i = 0; i < CHUNK; ++i) {
        int t = ch * CHUNK + i;
        float g = 0.96f + step * (float)t;
        r *= g;
        g_sQ[t] = r;
        g_sK[t] = 1.0f / r;
    }
    g_SR[ch] = r;
}

// -------- split-bf16 converts --------
__global__ __launch_bounds__(256) void convX_kernel(const float* __restrict__ X) {
    int i = blockIdx.x * 256 + threadIdx.x;
    float4 v = *(const float4*)&X[(size_t)i * 4];
    __nv_bfloat16 h[4], l[4];
    float vv[4] = {v.x, v.y, v.z, v.w};
    #pragma unroll
    for (int j = 0; j < 4; ++j) {
        h[j] = __float2bfloat16(vv[j]);
        l[j] = __float2bfloat16(vv[j] - __bfloat162float(h[j]));
    }
    *(uint2*)&g_Xh[(size_t)i * 4] = *(uint2*)h;
    *(uint2*)&g_Xl[(size_t)i * 4] = *(uint2*)l;
}

__global__ __launch_bounds__(256) void convW_kernel(
        const float* __restrict__ W0, const float* __restrict__ W1,
        const float* __restrict__ W2) {
    __shared__ float tile[32][33];
    const int w = blockIdx.z;
    const float* W = (w == 0) ? W0 : ((w == 1) ? W1 : W2);
    const int k0 = blockIdx.y * 32, n0 = blockIdx.x * 32;
    const int tx = threadIdx.x & 31, ty = threadIdx.x >> 5;
    #pragma unroll
    for (int i = 0; i < 32; i += 8)
        tile[ty + i][tx] = W[(size_t)(k0 + ty + i) * C_ + n0 + tx];
    __syncthreads();
    #pragma unroll
    for (int i = 0; i < 32; i += 8) {
        int nl = ty + i;
        float v = tile[tx][nl];
        __nv_bfloat16 h = __float2bfloat16(v);
        __nv_bfloat16 l = __float2bfloat16(v - __bfloat162float(h));
        size_t o = ((size_t)w * C_ + (n0 + nl)) * C_ + k0 + tx;
        g_Wht[o] = h;
        g_Wlt[o] = l;
    }
}

// transposed splits: K~ -> g_KT*, V -> g_VT*
__global__ __launch_bounds__(256) void convT_kernel() {
    __shared__ float tile[32][33];
    const int z = blockIdx.z;
    const int b = z >> 1, which = z & 1;
    const float* src = (which ? g_V : g_Ks) + (size_t)b * T_ * C_;
    __nv_bfloat16* dh = (which ? g_VTh : g_KTh) + (size_t)b * C_ * T_;
    __nv_bfloat16* dl = (which ? g_VTl : g_KTl) + (size_t)b * C_ * T_;
    const int t0 = blockIdx.x * 32, c0 = blockIdx.y * 32;
    const int tx = threadIdx.x & 31, ty = threadIdx.x >> 5;
    #pragma unroll
    for (int i = 0; i < 32; i += 8)
        tile[ty + i][tx] = src[(size_t)(t0 + ty + i) * C_ + c0 + tx];
    __syncthreads();
    #pragma unroll
    for (int i = 0; i < 32; i += 8) {
        int c = c0 + ty + i;
        float v = tile[tx][ty + i];
        __nv_bfloat16 h = __float2bfloat16(v);
        __nv_bfloat16 l = __float2bfloat16(v - __bfloat162float(h));
        dh[(size_t)c * T_ + t0 + tx] = h;
        dl[(size_t)c * T_ + t0 + tx] = l;
    }
}

// -------- HMMA projection v3: cp.async double-buffered + ldmatrix, fused splits --------
#define SA 40
#define TILE_HW (128 * SA)
#define PJ_TB   (TILE_HW * 2)
#define PJ_BUF  (4 * PJ_TB)
__global__ __launch_bounds__(256, 2) void projmma_kernel(
        const float* __restrict__ bQ, const float* __restrict__ bK,
        const float* __restrict__ bV) {
    extern __shared__ char shp[];
    const uint32_t sbase = smem_u32(shp);

    const int tid = threadIdx.x;
    const int w = tid >> 5, lane = tid & 31;
    const int g = lane >> 2, t4 = lane & 3;
    const int wm = w >> 2, wn = w & 3;
    const int which = blockIdx.x >> 2;
    const int n0 = (blockIdx.x & 3) * 128;
    const int m0 = blockIdx.y * 128;
    const float* bias = (which == 0) ? bQ : ((which == 1) ? bK : bV);

    const __nv_bfloat16* srcs[4] = {
        g_Xh + (size_t)m0 * C_, g_Xl + (size_t)m0 * C_,
        g_Wht + ((size_t)which * C_ + n0) * C_, g_Wlt + ((size_t)which * C_ + n0) * C_ };

    auto stage = [&](int bufi, int ck) {
        uint32_t base = sbase + (uint32_t)bufi * PJ_BUF;
        const int k0 = ck * 32;
        #pragma unroll
        for (int a = 0; a < 4; ++a) {
            #pragma unroll
            for (int j = 0; j < 2; ++j) {
                int u = tid + j * 256;
                int r = u >> 2, cg = u & 3;
                cpasync16(base + a * PJ_TB + r * 80 + cg * 16,
                          srcs[a] + (size_t)r * C_ + k0 + cg * 8);
            }
        }
    };

    float acc[4][4][4];
    #pragma unroll
    for (int i = 0; i < 4; ++i)
        #pragma unroll
        for (int j = 0; j < 4; ++j)
            #pragma unroll
            for (int r = 0; r < 4; ++r) acc[i][j][r] = 0.f;

    stage(0, 0);
    CP_COMMIT(); CP_WAIT0();
    __syncthreads();

    for (int ck = 0; ck < 16; ++ck) {
        const int buf = ck & 1;
        if (ck + 1 < 16) stage(buf ^ 1, ck + 1);
        CP_COMMIT();

        const uint32_t bAh = sbase + buf * PJ_BUF;
        const uint32_t bAl = bAh + PJ_TB;
        const uint32_t bBh = bAh + 2 * PJ_TB;
        const uint32_t bBl = bAh + 3 * PJ_TB;

        #pragma unroll
        for (int kk = 0; kk < 32; kk += 16) {
            uint32_t bhf[4], blf[4], bhf2[4], blf2[4];
            ldsm4(bhf,  addrB(bBh, wn * 32,      kk, SA, lane));
            ldsm4(bhf2, addrB(bBh, wn * 32 + 16, kk, SA, lane));
            ldsm4(blf,  addrB(bBl, wn * 32,      kk, SA, lane));
            ldsm4(blf2, addrB(bBl, wn * 32 + 16, kk, SA, lane));
            #pragma unroll
            for (int mf = 0; mf < 4; ++mf) {
                uint32_t ah[4], al[4];
                ldsm4(ah, addrA(bAh, wm * 64 + mf * 16, kk, SA, lane));
                ldsm4(al, addrA(bAl, wm * 64 + mf * 16, kk, SA, lane));
                mma16816(acc[mf][0], ah, bhf);      mma16816(acc[mf][0], ah, blf);
                mma16816(acc[mf][0], al, bhf);
                mma16816(acc[mf][1], ah, bhf + 2);  mma16816(acc[mf][1], ah, blf + 2);
                mma16816(acc[mf][1], al, bhf + 2);
                mma16816(acc[mf][2], ah, bhf2);     mma16816(acc[mf][2], ah, blf2);
                mma16816(acc[mf][2], al, bhf2);
                mma16816(acc[mf][3], ah, bhf2 + 2); mma16816(acc[mf][3], ah, blf2 + 2);
                mma16816(acc[mf][3], al, bhf2 + 2);
            }
        }
        CP_WAIT0();
        __syncthreads();
    }

    #pragma unroll
    for (int mf = 0; mf < 4; ++mf) {
        int m = m0 + wm * 64 + mf * 16 + g;
        int tA = m & (T_ - 1);
        int tB = (m + 8) & (T_ - 1);
        float sA = (which == 0) ? g_sQ[tA] : ((which == 1) ? g_sK[tA] : 1.0f);
        float sB = (which == 0) ? g_sQ[tB] : ((which == 1) ? g_sK[tB] : 1.0f);
        #pragma unroll
        for (int nf = 0; nf < 4; ++nf) {
            int n = n0 + wn * 32 + nf * 8 + 2 * t4;
            float2 bb = *(const float2*)&bias[n];
            float2 o0 = make_float2((acc[mf][nf][0] + bb.x) * sA,
                                    (acc[mf][nf][1] + bb.y) * sA);
            float2 o1 = make_float2((acc[mf][nf][2] + bb.x) * sB,
                                    (acc[mf][nf][3] + bb.y) * sB);
            size_t i0 = (size_t)m * C_ + n, i1 = (size_t)(m + 8) * C_ + n;
            if (which == 0) {
                split2(&g_Qh[i0], &g_Ql[i0], o0);
                split2(&g_Qh[i1], &g_Ql[i1], o1);
            } else if (which == 1) {
                *(float2*)&g_Ks[i0] = o0;
                *(float2*)&g_Ks[i1] = o1;
                split2(&g_Kh[i0], &g_Kl[i0], o0);
                split2(&g_Kh[i1], &g_Kl[i1], o1);
            } else {
                *(float2*)&g_V[i0] = o0;
                *(float2*)&g_V[i1] = o1;
            }
        }
    }
}

// -------- local masked attention via HMMA + ldmatrix --------
#define L_TILE 9216
#define L_BUF  (4 * L_TILE)
#define L_ASH  (2 * L_BUF)
#define L_ASL  (L_ASH + L_TILE)
#define L_SMEM (L_ASL + L_TILE)
__global__ __launch_bounds__(256, 2) void localmma_kernel() {
    extern __shared__ char shl[];
    const uint32_t sbase = smem_u32(shl);
    __nv_bfloat16* Ash = (__nv_bfloat16*)(shl + L_ASH);
    __nv_bfloat16* Asl = (__nv_bfloat16*)(shl + L_ASL);
    const uint32_t aAsh = sbase + L_ASH, aAsl = sbase + L_ASL;

    const int tid = threadIdx.x;
    const int w = tid >> 5, lane = tid & 31;
    const int g = lane >> 2, t4 = lane & 3;
    const int wm = w >> 2, wn = w & 3;
    const int b = blockIdx.x >> 6;
    const int ch = blockIdx.x & 63;
    const size_t rowbase = (size_t)b * T_ + (size_t)ch * CHUNK;

    const __nv_bfloat16* qkSrc[4] = {
        g_Qh + rowbase * C_, g_Ql + rowbase * C_,
        g_Kh + rowbase * C_, g_Kl + rowbase * C_ };
    const __nv_bfloat16* VThb = g_VTh + (size_t)b * C_ * T_;
    const __nv_bfloat16* VTlb = g_VTl + (size_t)b * C_ * T_;

    auto stage_qk = [&](int bufi, int ck2) {
        uint32_t base = sbase + (uint32_t)bufi * L_BUF;
        #pragma unroll
        for (int a = 0; a < 4; ++a) {
            #pragma unroll
            for (int j = 0; j < 2; ++j) {
                int u = tid + j * 256;
                int row = u >> 3, c8 = u & 7;
                cpasync16(base + a * L_TILE + row * 144 + c8 * 16,
                          qkSrc[a] + (size_t)row * C_ + ck2 * 64 + c8 * 8);
            }
        }
    };
    auto stage_vt = [&](int bufi, int dt) {
        uint32_t base = sbase + (uint32_t)bufi * L_BUF;
        #pragma unroll
        for (int hl = 0; hl < 2; ++hl) {
            const __nv_bfloat16* src = hl ? VTlb : VThb;
            #pragma unroll
            for (int j = 0; j < 4; ++j) {
                int u = tid + j * 256;
                int row = u >> 3, c8 = u & 7;
                cpasync16(base + hl * (2 * L_TILE) + row * 144 + c8 * 16,
                          src + (size_t)(dt * 128 + row) * T_ + ch * CHUNK + c8 * 8);
            }
        }
    };

    float acc[2][2][4];
    #pragma unroll
    for (int i = 0; i < 2; ++i)
        #pragma unroll
        for (int j = 0; j < 2; ++j)
            #pragma unroll
            for (int r = 0; r < 4; ++r) acc[i][j][r] = 0.f;

    stage_qk(0, 0);
    CP_COMMIT(); CP_WAIT0();
    __syncthreads();

    for (int ck2 = 0; ck2 < 8; ++ck2) {
        const int buf = ck2 & 1;
        if (ck2 + 1 < 8) stage_qk(buf ^ 1, ck2 + 1);
        CP_COMMIT();
        const uint32_t bQh = sbase + buf * L_BUF;
        const uint32_t bQl = bQh + L_TILE;
        const uint32_t bKh = bQh + 2 * L_TILE;
        const uint32_t bKl = bQh + 3 * L_TILE;
        #pragma unroll
        for (int kk = 0; kk < 64; kk += 16) {
            uint32_t bh[4], bl[4];
            ldsm4(bh, addrB(bKh, wn * 16, kk, 72, lane));
            ldsm4(bl, addrB(bKl, wn * 16, kk, 72, lane));
            #pragma unroll
            for (int mf = 0; mf < 2; ++mf) {
                uint32_t ah[4], al[4];
                ldsm4(ah, addrA(bQh, wm * 32 + mf * 16, kk, 72, lane));
                ldsm4(al, addrA(bQl, wm * 32 + mf * 16, kk, 72, lane));
                mma16816(acc[mf][0], ah, bh);     mma16816(acc[mf][0], ah, bl);
                mma16816(acc[mf][0], al, bh);
                mma16816(acc[mf][1], ah, bh + 2); mma16816(acc[mf][1], ah, bl + 2);
                mma16816(acc[mf][1], al, bh + 2);
            }
        }
        CP_WAIT0();
        __syncthreads();
    }

    #pragma unroll
    for (int mf = 0; mf < 2; ++mf) {
        #pragma unroll
        for (int nf = 0; nf < 2; ++nf) {
            int t0r = wm * 32 + mf * 16 + g;
            int s0 = wn * 16 + nf * 8 + 2 * t4;
            #pragma unroll
            for (int e = 0; e < 4; ++e) {
                int tt = t0r + (e >> 1) * 8;
                int ss = s0 + (e & 1);
                float v = (ss <= tt) ? acc[mf][nf][e] : 0.f;
                __nv_bfloat16 h = __float2bfloat16(v);
                Ash[tt * 72 + ss] = h;
                Asl[tt * 72 + ss] = __float2bfloat16(v - __bfloat162float(h));
            }
        }
    }
    __syncthreads();

    stage_vt(0, 0);
    CP_COMMIT(); CP_WAIT0();
    __syncthreads();

    for (int dt = 0; dt < 4; ++dt) {
        const int buf = dt & 1;
        if (dt + 1 < 4) stage_vt(buf ^ 1, dt + 1);
        CP_COMMIT();
        const uint32_t bVh = sbase + buf * L_BUF;
        const uint32_t bVl = bVh + 2 * L_TILE;

        float acc2[2][4][4];
        #pragma unroll
        for (int i = 0; i < 2; ++i)
            #pragma unroll
            for (int j = 0; j < 4; ++j)
                #pragma unroll
                for (int r = 0; r < 4; ++r) acc2[i][j][r] = 0.f;

        #pragma unroll
        for (int kk = 0; kk < 64; kk += 16) {
            uint32_t bh[4], bl[4], bh2[4], bl2[4];
            ldsm4(bh,  addrB(bVh, wn * 32,      kk, 72, lane));
            ldsm4(bh2, addrB(bVh, wn * 32 + 16, kk, 72, lane));
            ldsm4(bl,  addrB(bVl, wn * 32,      kk, 72, lane));
            ldsm4(bl2, addrB(bVl, wn * 32 + 16, kk, 72, lane));
            #pragma unroll
            for (int mf = 0; mf < 2; ++mf) {
                uint32_t ah[4], al[4];
                ldsm4(ah, addrA(aAsh, wm * 32 + mf * 16, kk, 72, lane));
                ldsm4(al, addrA(aAsl, wm * 32 + mf * 16, kk, 72, lane));
                mma16816(acc2[mf][0], ah, bh);      mma16816(acc2[mf][0], ah, bl);
                mma16816(acc2[mf][0], al, bh);
                mma16816(acc2[mf][1], ah, bh + 2);  mma16816(acc2[mf][1], ah, bl + 2);
                mma16816(acc2[mf][1], al, bh + 2);
                mma16816(acc2[mf][2], ah, bh2);     mma16816(acc2[mf][2], ah, bl2);
                mma16816(acc2[mf][2], al, bh2);
                mma16816(acc2[mf][3], ah, bh2 + 2); mma16816(acc2[mf][3], ah, bl2 + 2);
                mma16816(acc2[mf][3], al, bh2 + 2);
            }
        }

        #pragma unroll
        for (int mf = 0; mf < 2; ++mf) {
            int tt = wm * 32 + mf * 16 + g;
            #pragma unroll
            for (int nf = 0; nf < 4; ++nf) {
                int d = dt * 128 + wn * 32 + nf * 8 + 2 * t4;
                *(float2*)&g_OL[(rowbase + tt) * C_ + d] =
                    make_float2(acc2[mf][nf][0], acc2[mf][nf][1]);
                *(float2*)&g_OL[(rowbase + tt + 8) * C_ + d] =
                    make_float2(acc2[mf][nf][2], acc2[mf][nf][3]);
            }
        }
        CP_WAIT0();
        __syncthreads();
    }
}

// ---------------- scan v6: HMMA + ldmatrix, register fp32 S ----------------
#define S5_SH    0
#define S5_SL    16640
#define S5_STG   33280
#define S5_TILE  36864
#define S5_BUFSZ (2 * S5_TILE)
#define S5_VT    (S5_STG + 2 * S5_BUFSZ)
#define S5_SMEM  (S5_VT + 4608)

__global__ __launch_bounds__(256) void scan6_kernel(
        float* __restrict__ O, float* __restrict__ Sout, int writeS) {
    extern __shared__ char s5[];
    __nv_bfloat16* SHh = (__nv_bfloat16*)(s5 + S5_SH);
    __nv_bfloat16* SHl = (__nv_bfloat16*)(s5 + S5_SL);
    const uint32_t sbase = smem_u32(s5);
    const uint32_t aSHh = sbase + S5_SH, aSHl = sbase + S5_SL;

    const int tid = threadIdx.x;
    const int w = tid >> 5, lane = tid & 31;
    const int g = lane >> 2, t4 = lane & 3;
    const int mg = w >> 1, ng = w & 1;
    const int b = blockIdx.x >> 5;
    const int d0 = (blockIdx.x & 31) * 16;

    const __nv_bfloat16* Qh  = g_Qh  + (size_t)b * T_ * C_;
    const __nv_bfloat16* Ql  = g_Ql  + (size_t)b * T_ * C_;
    const __nv_bfloat16* KTh = g_KTh + (size_t)b * C_ * T_;
    const __nv_bfloat16* KTl = g_KTl + (size_t)b * C_ * T_;
    const __nv_bfloat16* VTh = g_VTh + (size_t)b * C_ * T_;
    const __nv_bfloat16* VTl = g_VTl + (size_t)b * C_ * T_;
    const float* OLb = g_OL + (size_t)b * T_ * C_;
    float* Ob = O + (size_t)b * T_ * C_;

    for (int i = tid; i < 16 * 520 / 2; i += 256) {
        ((uint32_t*)SHh)[i] = 0u;
        ((uint32_t*)SHl)[i] = 0u;
    }

    auto stage_q = [&](int bufi, size_t rb, int half) {
        uint32_t base = sbase + S5_STG + (uint32_t)bufi * S5_BUFSZ;
        #pragma unroll
        for (int j = 0; j < 16; ++j) {
            int u = tid + 256 * j;
            int hl = u >> 11, ur = u & 2047;
            int row = ur >> 5, c16 = ur & 31;
            const __nv_bfloat16* src = hl ? Ql : Qh;
            cpasync16(base + (uint32_t)hl * S5_TILE + row * 528 + c16 * 16,
                      src + (rb + row) * C_ + half * 256 + c16 * 8);
        }
    };
    auto stage_k = [&](int bufi, size_t rb, int half) {
        uint32_t base = sbase + S5_STG + (uint32_t)bufi * S5_BUFSZ;
        #pragma unroll
        for (int j = 0; j < 16; ++j) {
            int u = tid + 256 * j;
            int hl = u >> 11, ur = u & 2047;
            int row = ur >> 3, c8 = ur & 7;
            const __nv_bfloat16* src = hl ? KTl : KTh;
            cpasync16(base + (uint32_t)hl * S5_TILE + row * 144 + c8 * 16,
                      src + (size_t)(half * 256 + row) * T_ + rb + c8 * 8);
        }
    };
    auto stage_vt = [&](size_t rb) {
        int hl = tid >> 7, ur = tid & 127;
        int row = ur >> 3, c8 = ur & 7;
        const __nv_bfloat16* src = hl ? VTl : VTh;
        cpasync16(sbase + S5_VT + hl * 2304 + row * 144 + c8 * 16,
                  src + (size_t)(d0 + row) * T_ + rb + c8 * 8);
    };

    stage_q(0, 0, 0);
    CP_COMMIT(); CP_WAIT0();
    __syncthreads();

    float acc1[4] = {0.f, 0.f, 0.f, 0.f};
    float2 ol0 = make_float2(0.f, 0.f), ol1 = make_float2(0.f, 0.f);
    float Sreg[32];
    #pragma unroll
    for (int i = 0; i < 32; ++i) Sreg[i] = 0.f;

    for (int ch = 0; ch < NCHUNK; ++ch) {
        const size_t crow = (size_t)ch * CHUNK;
        const float R = __ldg(&g_SR[ch]);

        for (int p = 0; p < 4; ++p) {
            const int buf = p & 1, nbuf = buf ^ 1;
            if (p == 0) {
                stage_q(nbuf, crow, 1);
                ol0 = __ldg((const float2*)&OLb[(crow + mg * 16 + g) * C_ + d0 + ng * 8 + 2 * t4]);
                ol1 = __ldg((const float2*)&OLb[(crow + mg * 16 + g + 8) * C_ + d0 + ng * 8 + 2 * t4]);
            } else if (p == 1) {
                stage_k(nbuf, crow, 0);
                stage_vt(crow);
            } else if (p == 2) {
                stage_k(nbuf, crow, 1);
            } else {
                size_t nrow = (ch + 1 < NCHUNK) ? crow + CHUNK : crow;
                stage_q(nbuf, nrow, 0);
            }
            CP_COMMIT();

            if (p < 2) {
                // GEMM1: warp tile m=16 (mg), n=8 (ng); A from staged Q (stride 264), B = S (stride 520)
                const uint32_t bQsh = sbase + S5_STG + buf * S5_BUFSZ;
                const uint32_t bQsl = bQsh + S5_TILE;
                #pragma unroll
                for (int kk = 0; kk < 256; kk += 32) {
                    uint32_t bh4[4], bl4[4];
                    ldsm4(bh4, addrBK(aSHh, ng * 8, p * 256 + kk, 520, lane));
                    ldsm4(bl4, addrBK(aSHl, ng * 8, p * 256 + kk, 520, lane));
                    #pragma unroll
                    for (int s = 0; s < 2; ++s) {
                        uint32_t ah[4], al[4];
                        ldsm4(ah, addrA(bQsh, mg * 16, kk + s * 16, 264, lane));
                        ldsm4(al, addrA(bQsl, mg * 16, kk + s * 16, 264, lane));
                        mma16816(acc1, ah, bh4 + 2 * s);
                        mma16816(acc1, ah, bl4 + 2 * s);
                        mma16816(acc1, al, bh4 + 2 * s);
                    }
                }
                if (p == 1) {
                    const int trow = (int)crow + mg * 16 + g;
                    const int d = d0 + ng * 8 + 2 * t4;
                    *(float2*)&Ob[(size_t)trow * C_ + d] =
                        make_float2(tanhf(acc1[0] + ol0.x), tanhf(acc1[1] + ol0.y));
                    *(float2*)&Ob[(size_t)(trow + 8) * C_ + d] =
                        make_float2(tanhf(acc1[2] + ol1.x), tanhf(acc1[3] + ol1.y));
                    acc1[0] = acc1[1] = acc1[2] = acc1[3] = 0.f;
                }
            } else {
                // GEMM2: warp = 32-c slice; A = staged K^T (stride 72), B = V^T (stride 72, n=16)
                const uint32_t bKsh = sbase + S5_STG + buf * S5_BUFSZ;
                const uint32_t bKsl = bKsh + S5_TILE;
                const uint32_t bVth = sbase + S5_VT;
                const uint32_t bVtl = bVth + 2304;
                float acc2[2][2][4];
                #pragma unroll
                for (int i = 0; i < 2; ++i)
                    #pragma unroll
                    for (int j = 0; j < 2; ++j)
                        #pragma unroll
                        for (int r = 0; r < 4; ++r) acc2[i][j][r] = 0.f;
                #pragma unroll
                for (int kk = 0; kk < 64; kk += 16) {
                    uint32_t bh[4], bl[4];
                    ldsm4(bh, addrB(bVth, 0, kk, 72, lane));
                    ldsm4(bl, addrB(bVtl, 0, kk, 72, lane));
                    #pragma unroll
                    for (int mf = 0; mf < 2; ++mf) {
                        uint32_t ah[4], al[4];
                        ldsm4(ah, addrA(bKsh, w * 32 + mf * 16, kk, 72, lane));
                        ldsm4(al, addrA(bKsl, w * 32 + mf * 16, kk, 72, lane));
                        mma16816(acc2[mf][0], ah, bh);     mma16816(acc2[mf][0], ah, bl);
                        mma16816(acc2[mf][0], al, bh);
                        mma16816(acc2[mf][1], ah, bh + 2); mma16816(acc2[mf][1], ah, bl + 2);
                        mma16816(acc2[mf][1], al, bh + 2);
                    }
                }
                // S = (S + delta) * R; fp32 master in regs, bf16 h/l to smem
                const int pi = p - 2;
                const int cb = pi * 256 + w * 32;
                #pragma unroll
                for (int mf = 0; mf < 2; ++mf) {
                    #pragma unroll
                    for (int nf = 0; nf < 2; ++nf) {
                        #pragma unroll
                        for (int e = 0; e < 4; ++e) {
                            int idx = ((pi * 2 + mf) * 2 + nf) * 4 + e;
                            int c = cb + mf * 16 + g + (e >> 1) * 8;
                            int d = nf * 8 + 2 * t4 + (e & 1);
                            int ad = d * 520 + c;
                            float v = (Sreg[idx] + acc2[mf][nf][e]) * R;
                            Sreg[idx] = v;
                            __nv_bfloat16 h = __float2bfloat16(v);
                            SHh[ad] = h;
                            SHl[ad] = __float2bfloat16(v - __bfloat162float(h));
                        }
                    }
                }
            }
            CP_WAIT0();
            __syncthreads();
        }
    }

    if (writeS) {
        for (int idx = tid; idx < C_ * 16; idx += 256) {
            int c = idx >> 4, dl = idx & 15;
            Sout[((size_t)b * C_ + c) * C_ + d0 + dl] =
                __bfloat162float(SHh[dl * 520 + c]) + __bfloat162float(SHl[dl * 520 + c]);
        }
    }
}

extern "C" void kernel_launch(void* const* d_in, const int* in_sizes, int n_in,
                              void* d_out, int out_size) {
    const float* X  = (const float*)d_in[0];
    // d_in[1] = S_n (ignored; reference resets state to zero)
    const float* WQ = (const float*)d_in[2];
    const float* bQ = (const float*)d_in[3];
    const float* WK = (const float*)d_in[4];
    const float* bK = (const float*)d_in[5];
    const float* WV = (const float*)d_in[6];
    const float* bV = (const float*)d_in[7];
    float* out = (float*)d_out;

    const int oElems = B_ * T_ * C_;
    const int sElems = B_ * C_ * C_;
    int writeS = (out_size >= oElems + sElems) ? 1 : 0;
    float* Sout = out + oElems;

    const int smP = 2 * PJ_BUF;
    cudaFuncSetAttribute(projmma_kernel, cudaFuncAttributeMaxDynamicSharedMemorySize, smP);
    cudaFuncSetAttribute(localmma_kernel, cudaFuncAttributeMaxDynamicSharedMemorySize, L_SMEM);
    cudaFuncSetAttribute(scan6_kernel, cudaFuncAttributeMaxDynamicSharedMemorySize, S5_SMEM);

    scales_kernel<<<1, NCHUNK>>>();
    convX_kernel<<<(B_ * T_ * C_) / 1024, 256>>>(X);
    dim3 wg(16, 16, 3);
    convW_kernel<<<wg, 256>>>(WQ, WK, WV);
    dim3 pg(12, (B_ * T_) / 128);
    projmma_kernel<<<pg, 256, smP>>>(bQ, bK, bV);
    dim3 tg(T_ / 32, C_ / 32, B_ * 2);
    convT_kernel<<<tg, 256>>>();
    localmma_kernel<<<B_ * NCHUNK, 256, L_SMEM>>>();
    scan6_kernel<<<B_ * 32, 256, S5_SMEM>>>(out, Sout, writeS);
}

// round 11
// speedup vs baseline: 4.5785x; 1.0136x over previous
#include <cuda_runtime.h>
#include <cuda_bf16.h>
#include <cstdint>
#include <cstddef>

#define B_ 4
#define T_ 4096
#define C_ 512
#define CHUNK 64
#define NCHUNK (T_/CHUNK)

// bf16 warp MMA: D(16x8,f32) += A(16x16,row) * B(16x8,col)
__device__ __forceinline__ void mma16816(float* c, const uint32_t* a, const uint32_t* b) {
    asm volatile(
        "mma.sync.aligned.m16n8k16.row.col.f32.bf16.bf16.f32 "
        "{%0,%1,%2,%3}, {%4,%5,%6,%7}, {%8,%9}, {%0,%1,%2,%3};\n"
        : "+f"(c[0]), "+f"(c[1]), "+f"(c[2]), "+f"(c[3])
        : "r"(a[0]), "r"(a[1]), "r"(a[2]), "r"(a[3]), "r"(b[0]), "r"(b[1]));
}
__device__ __forceinline__ void ldsm4(uint32_t* r, uint32_t a) {
    asm volatile("ldmatrix.sync.aligned.m8n8.x4.shared.b16 {%0,%1,%2,%3}, [%4];"
        : "=r"(r[0]), "=r"(r[1]), "=r"(r[2]), "=r"(r[3]) : "r"(a));
}
// A 16x16 tiles (m,k),(m+8,k),(m,k+8),(m+8,k+8); strideHW in halfwords
__device__ __forceinline__ uint32_t addrA(uint32_t base, int row0, int k, int strideHW, int lane) {
    int t = lane >> 3, r = lane & 7;
    return base + (uint32_t)(((row0 + ((t & 1) << 3) + r) * strideHW + k + ((t >> 1) << 3)) * 2);
}
// B (n-major rows) tiles (n,k),(n,k+8),(n+8,k),(n+8,k+8)
__device__ __forceinline__ uint32_t addrB(uint32_t base, int n0, int k, int strideHW, int lane) {
    int t = lane >> 3, r = lane & 7;
    return base + (uint32_t)(((n0 + ((t >> 1) << 3) + r) * strideHW + k + ((t & 1) << 3)) * 2);
}
// B wide-k: tiles (n,k),(n,k+8),(n,k+16),(n,k+24) (n only 8 rows)
__device__ __forceinline__ uint32_t addrBK(uint32_t base, int n0, int k, int strideHW, int lane) {
    int t = lane >> 3, r = lane & 7;
    return base + (uint32_t)(((n0 + r) * strideHW + k + (t << 3)) * 2);
}
__device__ __forceinline__ uint32_t smem_u32(const void* p) {
    uint32_t a;
    asm("{ .reg .u64 t; cvta.to.shared.u64 t, %1; cvt.u32.u64 %0, t; }" : "=r"(a) : "l"(p));
    return a;
}
__device__ __forceinline__ void cpasync16(uint32_t s, const void* g) {
    asm volatile("cp.async.cg.shared.global [%0], [%1], 16;" :: "r"(s), "l"(g));
}
#define CP_COMMIT() asm volatile("cp.async.commit_group;" ::: "memory")
#define CP_WAIT0()  asm volatile("cp.async.wait_group 0;" ::: "memory")

__device__ __forceinline__ void split2(__nv_bfloat16* dh, __nv_bfloat16* dl, float2 v) {
    __nv_bfloat16 h0 = __float2bfloat16(v.x), h1 = __float2bfloat16(v.y);
    __nv_bfloat16 l0 = __float2bfloat16(v.x - __bfloat162float(h0));
    __nv_bfloat16 l1 = __float2bfloat16(v.y - __bfloat162float(h1));
    __nv_bfloat16 hp[2] = {h0, h1}, lp[2] = {l0, l1};
    *(uint32_t*)dh = *(uint32_t*)hp;
    *(uint32_t*)dl = *(uint32_t*)lp;
}

// -------- scratch (__device__ globals) --------
__device__ float g_Ks[B_*T_*C_];
__device__ float g_V [B_*T_*C_];
__device__ float g_OL[B_*T_*C_];
__device__ float g_sQ[T_];
__device__ float g_sK[T_];
__device__ float g_SR[NCHUNK];
__device__ __nv_bfloat16 g_Xh[B_*T_*C_];
__device__ __nv_bfloat16 g_Xl[B_*T_*C_];
__device__ __nv_bfloat16 g_Wht[3*C_*C_];
__device__ __nv_bfloat16 g_Wlt[3*C_*C_];
__device__ __nv_bfloat16 g_Qh[B_*T_*C_];
__device__ __nv_bfloat16 g_Ql[B_*T_*C_];
__device__ __nv_bfloat16 g_Kh[B_*T_*C_];
__device__ __nv_bfloat16 g_Kl[B_*T_*C_];
__device__ __nv_bfloat16 g_KTh[B_*C_*T_];
__device__ __nv_bfloat16 g_KTl[B_*C_*T_];
__device__ __nv_bfloat16 g_VTh[B_*C_*T_];
__device__ __nv_bfloat16 g_VTl[B_*C_*T_];

// -------- gamma scales --------
__global__ void scales_kernel() {
    int ch = threadIdx.x;
    if (ch >= NCHUNK) return;
    const float step = 0.03f / 4095.0f;
    float r = 1.0f;
    for (int i = 0; i < CHUNK; ++i) {
        int t = ch * CHUNK + i;
        float g = 0.96f + step * (float)t;
        r *= g;
        g_sQ[t] = r;
        g_sK[t] = 1.0f / r;
    }
    g_SR[ch] = r;
}

// -------- split-bf16 converts --------
__global__ __launch_bounds__(256) void convX_kernel(const float* __restrict__ X) {
    int i = blockIdx.x * 256 + threadIdx.x;
    float4 v = *(const float4*)&X[(size_t)i * 4];
    __nv_bfloat16 h[4], l[4];
    float vv[4] = {v.x, v.y, v.z, v.w};
    #pragma unroll
    for (int j = 0; j < 4; ++j) {
        h[j] = __float2bfloat16(vv[j]);
        l[j] = __float2bfloat16(vv[j] - __bfloat162float(h[j]));
    }
    *(uint2*)&g_Xh[(size_t)i * 4] = *(uint2*)h;
    *(uint2*)&g_Xl[(size_t)i * 4] = *(uint2*)l;
}

__global__ __launch_bounds__(256) void convW_kernel(
        const float* __restrict__ W0, const float* __restrict__ W1,
        const float* __restrict__ W2) {
    __shared__ float tile[32][33];
    const int w = blockIdx.z;
    const float* W = (w == 0) ? W0 : ((w == 1) ? W1 : W2);
    const int k0 = blockIdx.y * 32, n0 = blockIdx.x * 32;
    const int tx = threadIdx.x & 31, ty = threadIdx.x >> 5;
    #pragma unroll
    for (int i = 0; i < 32; i += 8)
        tile[ty + i][tx] = W[(size_t)(k0 + ty + i) * C_ + n0 + tx];
    __syncthreads();
    #pragma unroll
    for (int i = 0; i < 32; i += 8) {
        int nl = ty + i;
        float v = tile[tx][nl];
        __nv_bfloat16 h = __float2bfloat16(v);
        __nv_bfloat16 l = __float2bfloat16(v - __bfloat162float(h));
        size_t o = ((size_t)w * C_ + (n0 + nl)) * C_ + k0 + tx;
        g_Wht[o] = h;
        g_Wlt[o] = l;
    }
}

// transposed splits: K~ -> g_KT*, V -> g_VT*
__global__ __launch_bounds__(256) void convT_kernel() {
    __shared__ float tile[32][33];
    const int z = blockIdx.z;
    const int b = z >> 1, which = z & 1;
    const float* src = (which ? g_V : g_Ks) + (size_t)b * T_ * C_;
    __nv_bfloat16* dh = (which ? g_VTh : g_KTh) + (size_t)b * C_ * T_;
    __nv_bfloat16* dl = (which ? g_VTl : g_KTl) + (size_t)b * C_ * T_;
    const int t0 = blockIdx.x * 32, c0 = blockIdx.y * 32;
    const int tx = threadIdx.x & 31, ty = threadIdx.x >> 5;
    #pragma unroll
    for (int i = 0; i < 32; i += 8)
        tile[ty + i][tx] = src[(size_t)(t0 + ty + i) * C_ + c0 + tx];
    __syncthreads();
    #pragma unroll
    for (int i = 0; i < 32; i += 8) {
        int c = c0 + ty + i;
        float v = tile[tx][ty + i];
        __nv_bfloat16 h = __float2bfloat16(v);
        __nv_bfloat16 l = __float2bfloat16(v - __bfloat162float(h));
        dh[(size_t)c * T_ + t0 + tx] = h;
        dl[(size_t)c * T_ + t0 + tx] = l;
    }
}

// -------- HMMA projection v3 (unchanged, passing: 225us) --------
#define SA 40
#define TILE_HW (128 * SA)
#define PJ_TB   (TILE_HW * 2)
#define PJ_BUF  (4 * PJ_TB)
__global__ __launch_bounds__(256, 2) void projmma_kernel(
        const float* __restrict__ bQ, const float* __restrict__ bK,
        const float* __restrict__ bV) {
    extern __shared__ char shp[];
    const uint32_t sbase = smem_u32(shp);

    const int tid = threadIdx.x;
    const int w = tid >> 5, lane = tid & 31;
    const int g = lane >> 2, t4 = lane & 3;
    const int wm = w >> 2, wn = w & 3;
    const int which = blockIdx.x >> 2;
    const int n0 = (blockIdx.x & 3) * 128;
    const int m0 = blockIdx.y * 128;
    const float* bias = (which == 0) ? bQ : ((which == 1) ? bK : bV);

    const __nv_bfloat16* srcs[4] = {
        g_Xh + (size_t)m0 * C_, g_Xl + (size_t)m0 * C_,
        g_Wht + ((size_t)which * C_ + n0) * C_, g_Wlt + ((size_t)which * C_ + n0) * C_ };

    auto stage = [&](int bufi, int ck) {
        uint32_t base = sbase + (uint32_t)bufi * PJ_BUF;
        const int k0 = ck * 32;
        #pragma unroll
        for (int a = 0; a < 4; ++a) {
            #pragma unroll
            for (int j = 0; j < 2; ++j) {
                int u = tid + j * 256;
                int r = u >> 2, cg = u & 3;
                cpasync16(base + a * PJ_TB + r * 80 + cg * 16,
                          srcs[a] + (size_t)r * C_ + k0 + cg * 8);
            }
        }
    };

    float acc[4][4][4];
    #pragma unroll
    for (int i = 0; i < 4; ++i)
        #pragma unroll
        for (int j = 0; j < 4; ++j)
            #pragma unroll
            for (int r = 0; r < 4; ++r) acc[i][j][r] = 0.f;

    stage(0, 0);
    CP_COMMIT(); CP_WAIT0();
    __syncthreads();

    for (int ck = 0; ck < 16; ++ck) {
        const int buf = ck & 1;
        if (ck + 1 < 16) stage(buf ^ 1, ck + 1);
        CP_COMMIT();

        const uint32_t bAh = sbase + buf * PJ_BUF;
        const uint32_t bAl = bAh + PJ_TB;
        const uint32_t bBh = bAh + 2 * PJ_TB;
        const uint32_t bBl = bAh + 3 * PJ_TB;

        #pragma unroll
        for (int kk = 0; kk < 32; kk += 16) {
            uint32_t bhf[4], blf[4], bhf2[4], blf2[4];
            ldsm4(bhf,  addrB(bBh, wn * 32,      kk, SA, lane));
            ldsm4(bhf2, addrB(bBh, wn * 32 + 16, kk, SA, lane));
            ldsm4(blf,  addrB(bBl, wn * 32,      kk, SA, lane));
            ldsm4(blf2, addrB(bBl, wn * 32 + 16, kk, SA, lane));
            #pragma unroll
            for (int mf = 0; mf < 4; ++mf) {
                uint32_t ah[4], al[4];
                ldsm4(ah, addrA(bAh, wm * 64 + mf * 16, kk, SA, lane));
                ldsm4(al, addrA(bAl, wm * 64 + mf * 16, kk, SA, lane));
                mma16816(acc[mf][0], ah, bhf);      mma16816(acc[mf][0], ah, blf);
                mma16816(acc[mf][0], al, bhf);
                mma16816(acc[mf][1], ah, bhf + 2);  mma16816(acc[mf][1], ah, blf + 2);
                mma16816(acc[mf][1], al, bhf + 2);
                mma16816(acc[mf][2], ah, bhf2);     mma16816(acc[mf][2], ah, blf2);
                mma16816(acc[mf][2], al, bhf2);
                mma16816(acc[mf][3], ah, bhf2 + 2); mma16816(acc[mf][3], ah, blf2 + 2);
                mma16816(acc[mf][3], al, bhf2 + 2);
            }
        }
        CP_WAIT0();
        __syncthreads();
    }

    #pragma unroll
    for (int mf = 0; mf < 4; ++mf) {
        int m = m0 + wm * 64 + mf * 16 + g;
        int tA = m & (T_ - 1);
        int tB = (m + 8) & (T_ - 1);
        float sA = (which == 0) ? g_sQ[tA] : ((which == 1) ? g_sK[tA] : 1.0f);
        float sB = (which == 0) ? g_sQ[tB] : ((which == 1) ? g_sK[tB] : 1.0f);
        #pragma unroll
        for (int nf = 0; nf < 4; ++nf) {
            int n = n0 + wn * 32 + nf * 8 + 2 * t4;
            float2 bb = *(const float2*)&bias[n];
            float2 o0 = make_float2((acc[mf][nf][0] + bb.x) * sA,
                                    (acc[mf][nf][1] + bb.y) * sA);
            float2 o1 = make_float2((acc[mf][nf][2] + bb.x) * sB,
                                    (acc[mf][nf][3] + bb.y) * sB);
            size_t i0 = (size_t)m * C_ + n, i1 = (size_t)(m + 8) * C_ + n;
            if (which == 0) {
                split2(&g_Qh[i0], &g_Ql[i0], o0);
                split2(&g_Qh[i1], &g_Ql[i1], o1);
            } else if (which == 1) {
                *(float2*)&g_Ks[i0] = o0;
                *(float2*)&g_Ks[i1] = o1;
                split2(&g_Kh[i0], &g_Kl[i0], o0);
                split2(&g_Kh[i1], &g_Kl[i1], o1);
            } else {
                *(float2*)&g_V[i0] = o0;
                *(float2*)&g_V[i1] = o1;
            }
        }
    }
}

// -------- local masked attention via HMMA + ldmatrix (unchanged, passing) --------
#define L_TILE 9216
#define L_BUF  (4 * L_TILE)
#define L_ASH  (2 * L_BUF)
#define L_ASL  (L_ASH + L_TILE)
#define L_SMEM (L_ASL + L_TILE)
__global__ __launch_bounds__(256, 2) void localmma_kernel() {
    extern __shared__ char shl[];
    const uint32_t sbase = smem_u32(shl);
    __nv_bfloat16* Ash = (__nv_bfloat16*)(shl + L_ASH);
    __nv_bfloat16* Asl = (__nv_bfloat16*)(shl + L_ASL);
    const uint32_t aAsh = sbase + L_ASH, aAsl = sbase + L_ASL;

    const int tid = threadIdx.x;
    const int w = tid >> 5, lane = tid & 31;
    const int g = lane >> 2, t4 = lane & 3;
    const int wm = w >> 2, wn = w & 3;
    const int b = blockIdx.x >> 6;
    const int ch = blockIdx.x & 63;
    const size_t rowbase = (size_t)b * T_ + (size_t)ch * CHUNK;

    const __nv_bfloat16* qkSrc[4] = {
        g_Qh + rowbase * C_, g_Ql + rowbase * C_,
        g_Kh + rowbase * C_, g_Kl + rowbase * C_ };
    const __nv_bfloat16* VThb = g_VTh + (size_t)b * C_ * T_;
    const __nv_bfloat16* VTlb = g_VTl + (size_t)b * C_ * T_;

    auto stage_qk = [&](int bufi, int ck2) {
        uint32_t base = sbase + (uint32_t)bufi * L_BUF;
        #pragma unroll
        for (int a = 0; a < 4; ++a) {
            #pragma unroll
            for (int j = 0; j < 2; ++j) {
                int u = tid + j * 256;
                int row = u >> 3, c8 = u & 7;
                cpasync16(base + a * L_TILE + row * 144 + c8 * 16,
                          qkSrc[a] + (size_t)row * C_ + ck2 * 64 + c8 * 8);
            }
        }
    };
    auto stage_vt = [&](int bufi, int dt) {
        uint32_t base = sbase + (uint32_t)bufi * L_BUF;
        #pragma unroll
        for (int hl = 0; hl < 2; ++hl) {
            const __nv_bfloat16* src = hl ? VTlb : VThb;
            #pragma unroll
            for (int j = 0; j < 4; ++j) {
                int u = tid + j * 256;
                int row = u >> 3, c8 = u & 7;
                cpasync16(base + hl * (2 * L_TILE) + row * 144 + c8 * 16,
                          src + (size_t)(dt * 128 + row) * T_ + ch * CHUNK + c8 * 8);
            }
        }
    };

    float acc[2][2][4];
    #pragma unroll
    for (int i = 0; i < 2; ++i)
        #pragma unroll
        for (int j = 0; j < 2; ++j)
            #pragma unroll
            for (int r = 0; r < 4; ++r) acc[i][j][r] = 0.f;

    stage_qk(0, 0);
    CP_COMMIT(); CP_WAIT0();
    __syncthreads();

    for (int ck2 = 0; ck2 < 8; ++ck2) {
        const int buf = ck2 & 1;
        if (ck2 + 1 < 8) stage_qk(buf ^ 1, ck2 + 1);
        CP_COMMIT();
        const uint32_t bQh = sbase + buf * L_BUF;
        const uint32_t bQl = bQh + L_TILE;
        const uint32_t bKh = bQh + 2 * L_TILE;
        const uint32_t bKl = bQh + 3 * L_TILE;
        #pragma unroll
        for (int kk = 0; kk < 64; kk += 16) {
            uint32_t bh[4], bl[4];
            ldsm4(bh, addrB(bKh, wn * 16, kk, 72, lane));
            ldsm4(bl, addrB(bKl, wn * 16, kk, 72, lane));
            #pragma unroll
            for (int mf = 0; mf < 2; ++mf) {
                uint32_t ah[4], al[4];
                ldsm4(ah, addrA(bQh, wm * 32 + mf * 16, kk, 72, lane));
                ldsm4(al, addrA(bQl, wm * 32 + mf * 16, kk, 72, lane));
                mma16816(acc[mf][0], ah, bh);     mma16816(acc[mf][0], ah, bl);
                mma16816(acc[mf][0], al, bh);
                mma16816(acc[mf][1], ah, bh + 2); mma16816(acc[mf][1], ah, bl + 2);
                mma16816(acc[mf][1], al, bh + 2);
            }
        }
        CP_WAIT0();
        __syncthreads();
    }

    #pragma unroll
    for (int mf = 0; mf < 2; ++mf) {
        #pragma unroll
        for (int nf = 0; nf < 2; ++nf) {
            int t0r = wm * 32 + mf * 16 + g;
            int s0 = wn * 16 + nf * 8 + 2 * t4;
            #pragma unroll
            for (int e = 0; e < 4; ++e) {
                int tt = t0r + (e >> 1) * 8;
                int ss = s0 + (e & 1);
                float v = (ss <= tt) ? acc[mf][nf][e] : 0.f;
                __nv_bfloat16 h = __float2bfloat16(v);
                Ash[tt * 72 + ss] = h;
                Asl[tt * 72 + ss] = __float2bfloat16(v - __bfloat162float(h));
            }
        }
    }
    __syncthreads();

    stage_vt(0, 0);
    CP_COMMIT(); CP_WAIT0();
    __syncthreads();

    for (int dt = 0; dt < 4; ++dt) {
        const int buf = dt & 1;
        if (dt + 1 < 4) stage_vt(buf ^ 1, dt + 1);
        CP_COMMIT();
        const uint32_t bVh = sbase + buf * L_BUF;
        const uint32_t bVl = bVh + 2 * L_TILE;

        float acc2[2][4][4];
        #pragma unroll
        for (int i = 0; i < 2; ++i)
            #pragma unroll
            for (int j = 0; j < 4; ++j)
                #pragma unroll
                for (int r = 0; r < 4; ++r) acc2[i][j][r] = 0.f;

        #pragma unroll
        for (int kk = 0; kk < 64; kk += 16) {
            uint32_t bh[4], bl[4], bh2[4], bl2[4];
            ldsm4(bh,  addrB(bVh, wn * 32,      kk, 72, lane));
            ldsm4(bh2, addrB(bVh, wn * 32 + 16, kk, 72, lane));
            ldsm4(bl,  addrB(bVl, wn * 32,      kk, 72, lane));
            ldsm4(bl2, addrB(bVl, wn * 32 + 16, kk, 72, lane));
            #pragma unroll
            for (int mf = 0; mf < 2; ++mf) {
                uint32_t ah[4], al[4];
                ldsm4(ah, addrA(aAsh, wm * 32 + mf * 16, kk, 72, lane));
                ldsm4(al, addrA(aAsl, wm * 32 + mf * 16, kk, 72, lane));
                mma16816(acc2[mf][0], ah, bh);      mma16816(acc2[mf][0], ah, bl);
                mma16816(acc2[mf][0], al, bh);
                mma16816(acc2[mf][1], ah, bh + 2);  mma16816(acc2[mf][1], ah, bl + 2);
                mma16816(acc2[mf][1], al, bh + 2);
                mma16816(acc2[mf][2], ah, bh2);     mma16816(acc2[mf][2], ah, bl2);
                mma16816(acc2[mf][2], al, bh2);
                mma16816(acc2[mf][3], ah, bh2 + 2); mma16816(acc2[mf][3], ah, bl2 + 2);
                mma16816(acc2[mf][3], al, bh2 + 2);
            }
        }

        #pragma unroll
        for (int mf = 0; mf < 2; ++mf) {
            int tt = wm * 32 + mf * 16 + g;
            #pragma unroll
            for (int nf = 0; nf < 4; ++nf) {
                int d = dt * 128 + wn * 32 + nf * 8 + 2 * t4;
                *(float2*)&g_OL[(rowbase + tt) * C_ + d] =
                    make_float2(acc2[mf][nf][0], acc2[mf][nf][1]);
                *(float2*)&g_OL[(rowbase + tt + 8) * C_ + d] =
                    make_float2(acc2[mf][nf][2], acc2[mf][nf][3]);
            }
        }
        CP_WAIT0();
        __syncthreads();
    }
}

// ---------------- scan v7: 512 threads / 16 warps, split-k GEMM1 + split-c GEMM2 ----------------
#define S5_SH    0
#define S5_SL    16640
#define S5_STG   33280
#define S5_TILE  36864
#define S5_BUFSZ (2 * S5_TILE)
#define S5_VT    (S5_STG + 2 * S5_BUFSZ)
#define S5_RED   (S5_VT + 4608)              // 185344
#define S5_SMEM  (S5_RED + 4096)             // 189440

__global__ __launch_bounds__(512) void scan7_kernel(
        float* __restrict__ O, float* __restrict__ Sout, int writeS) {
    extern __shared__ char s5[];
    __nv_bfloat16* SHh = (__nv_bfloat16*)(s5 + S5_SH);
    __nv_bfloat16* SHl = (__nv_bfloat16*)(s5 + S5_SL);
    float* RED = (float*)(s5 + S5_RED);
    const uint32_t sbase = smem_u32(s5);
    const uint32_t aSHh = sbase + S5_SH, aSHl = sbase + S5_SL;

    const int tid = threadIdx.x;
    const int w = tid >> 5, lane = tid & 31;
    const int g = lane >> 2, t4 = lane & 3;
    // GEMM1 mapping: 16 warps = 8 output tiles x 2 k-halves
    const int w8 = w & 7, khalf = w >> 3;
    const int mg = w8 >> 1, ng = w8 & 1;
    const int b = blockIdx.x >> 5;
    const int d0 = (blockIdx.x & 31) * 16;

    const __nv_bfloat16* Qh  = g_Qh  + (size_t)b * T_ * C_;
    const __nv_bfloat16* Ql  = g_Ql  + (size_t)b * T_ * C_;
    const __nv_bfloat16* KTh = g_KTh + (size_t)b * C_ * T_;
    const __nv_bfloat16* KTl = g_KTl + (size_t)b * C_ * T_;
    const __nv_bfloat16* VTh = g_VTh + (size_t)b * C_ * T_;
    const __nv_bfloat16* VTl = g_VTl + (size_t)b * C_ * T_;
    const float* OLb = g_OL + (size_t)b * T_ * C_;
    float* Ob = O + (size_t)b * T_ * C_;

    for (int i = tid; i < 16 * 520 / 2; i += 512) {
        ((uint32_t*)SHh)[i] = 0u;
        ((uint32_t*)SHl)[i] = 0u;
    }

    auto stage_q = [&](int bufi, size_t rb, int half) {
        uint32_t base = sbase + S5_STG + (uint32_t)bufi * S5_BUFSZ;
        #pragma unroll
        for (int j = 0; j < 8; ++j) {
            int u = tid + 512 * j;
            int hl = u >> 11, ur = u & 2047;
            int row = ur >> 5, c16 = ur & 31;
            const __nv_bfloat16* src = hl ? Ql : Qh;
            cpasync16(base + (uint32_t)hl * S5_TILE + row * 528 + c16 * 16,
                      src + (rb + row) * C_ + half * 256 + c16 * 8);
        }
    };
    auto stage_k = [&](int bufi, size_t rb, int half) {
        uint32_t base = sbase + S5_STG + (uint32_t)bufi * S5_BUFSZ;
        #pragma unroll
        for (int j = 0; j < 8; ++j) {
            int u = tid + 512 * j;
            int hl = u >> 11, ur = u & 2047;
            int row = ur >> 3, c8 = ur & 7;
            const __nv_bfloat16* src = hl ? KTl : KTh;
            cpasync16(base + (uint32_t)hl * S5_TILE + row * 144 + c8 * 16,
                      src + (size_t)(half * 256 + row) * T_ + rb + c8 * 8);
        }
    };
    auto stage_vt = [&](size_t rb) {
        if (tid < 256) {
            int hl = tid >> 7, ur = tid & 127;
            int row = ur >> 3, c8 = ur & 7;
            const __nv_bfloat16* src = hl ? VTl : VTh;
            cpasync16(sbase + S5_VT + hl * 2304 + row * 144 + c8 * 16,
                      src + (size_t)(d0 + row) * T_ + rb + c8 * 8);
        }
    };

    stage_q(0, 0, 0);
    CP_COMMIT(); CP_WAIT0();
    __syncthreads();

    float acc1[4] = {0.f, 0.f, 0.f, 0.f};
    float2 ol0 = make_float2(0.f, 0.f), ol1 = make_float2(0.f, 0.f);
    float Sreg[16];
    #pragma unroll
    for (int i = 0; i < 16; ++i) Sreg[i] = 0.f;

    for (int ch = 0; ch < NCHUNK; ++ch) {
        const size_t crow = (size_t)ch * CHUNK;
        const float R = __ldg(&g_SR[ch]);

        for (int p = 0; p < 4; ++p) {
            const int buf = p & 1, nbuf = buf ^ 1;
            if (p == 0) {
                stage_q(nbuf, crow, 1);
                if (khalf == 0) {
                    ol0 = __ldg((const float2*)&OLb[(crow + mg * 16 + g) * C_ + d0 + ng * 8 + 2 * t4]);
                    ol1 = __ldg((const float2*)&OLb[(crow + mg * 16 + g + 8) * C_ + d0 + ng * 8 + 2 * t4]);
                }
            } else if (p == 1) {
                stage_k(nbuf, crow, 0);
                stage_vt(crow);
            } else if (p == 2) {
                stage_k(nbuf, crow, 1);
            } else {
                size_t nrow = (ch + 1 < NCHUNK) ? crow + CHUNK : crow;
                stage_q(nbuf, nrow, 0);
            }
            CP_COMMIT();

            if (p < 2) {
                // GEMM1: warp (mg,ng,khalf): m rows mg*16, d cols ng*8, k slice khalf*128
                const uint32_t bQsh = sbase + S5_STG + buf * S5_BUFSZ;
                const uint32_t bQsl = bQsh + S5_TILE;
                #pragma unroll
                for (int kk = 0; kk < 128; kk += 32) {
                    const int kloc = khalf * 128 + kk;
                    uint32_t bh4[4], bl4[4];
                    ldsm4(bh4, addrBK(aSHh, ng * 8, p * 256 + kloc, 520, lane));
                    ldsm4(bl4, addrBK(aSHl, ng * 8, p * 256 + kloc, 520, lane));
                    #pragma unroll
                    for (int s = 0; s < 2; ++s) {
                        uint32_t ah[4], al[4];
                        ldsm4(ah, addrA(bQsh, mg * 16, kloc + s * 16, 264, lane));
                        ldsm4(al, addrA(bQsl, mg * 16, kloc + s * 16, 264, lane));
                        mma16816(acc1, ah, bh4 + 2 * s);
                        mma16816(acc1, ah, bl4 + 2 * s);
                        mma16816(acc1, al, bh4 + 2 * s);
                    }
                }
                if (p == 1 && khalf == 1) {
                    // partner half -> RED; owner reads at p==2
                    *(float4*)&RED[(w8 * 32 + lane) * 4] =
                        make_float4(acc1[0], acc1[1], acc1[2], acc1[3]);
                    acc1[0] = acc1[1] = acc1[2] = acc1[3] = 0.f;
                }
            } else {
                if (p == 2 && khalf == 0) {
                    float4 pr = *(const float4*)&RED[(w8 * 32 + lane) * 4];
                    const int trow = (int)crow + mg * 16 + g;
                    const int d = d0 + ng * 8 + 2 * t4;
                    *(float2*)&Ob[(size_t)trow * C_ + d] =
                        make_float2(tanhf(acc1[0] + pr.x + ol0.x), tanhf(acc1[1] + pr.y + ol0.y));
                    *(float2*)&Ob[(size_t)(trow + 8) * C_ + d] =
                        make_float2(tanhf(acc1[2] + pr.z + ol1.x), tanhf(acc1[3] + pr.w + ol1.y));
                    acc1[0] = acc1[1] = acc1[2] = acc1[3] = 0.f;
                }
                // GEMM2: warp owns 16 c-rows within the 256-c slice; n = 16 d
                const uint32_t bKsh = sbase + S5_STG + buf * S5_BUFSZ;
                const uint32_t bKsl = bKsh + S5_TILE;
                const uint32_t bVth = sbase + S5_VT;
                const uint32_t bVtl = bVth + 2304;
                float acc2[2][4];
                #pragma unroll
                for (int j = 0; j < 2; ++j)
                    #pragma unroll
                    for (int r = 0; r < 4; ++r) acc2[j][r] = 0.f;
                #pragma unroll
                for (int kk = 0; kk < 64; kk += 16) {
                    uint32_t bh[4], bl[4];
                    ldsm4(bh, addrB(bVth, 0, kk, 72, lane));
                    ldsm4(bl, addrB(bVtl, 0, kk, 72, lane));
                    uint32_t ah[4], al[4];
                    ldsm4(ah, addrA(bKsh, w * 16, kk, 72, lane));
                    ldsm4(al, addrA(bKsl, w * 16, kk, 72, lane));
                    mma16816(acc2[0], ah, bh);     mma16816(acc2[0], ah, bl);
                    mma16816(acc2[0], al, bh);
                    mma16816(acc2[1], ah, bh + 2); mma16816(acc2[1], ah, bl + 2);
                    mma16816(acc2[1], al, bh + 2);
                }
                // S = (S + delta) * R; fp32 master in regs, bf16 h/l to smem
                const int pi = p - 2;
                const int cb = pi * 256 + w * 16;
                #pragma unroll
                for (int nf = 0; nf < 2; ++nf) {
                    #pragma unroll
                    for (int e = 0; e < 4; ++e) {
                        int idx = (pi * 2 + nf) * 4 + e;
                        int c = cb + g + (e >> 1) * 8;
                        int d = nf * 8 + 2 * t4 + (e & 1);
                        int ad = d * 520 + c;
                        float v = (Sreg[idx] + acc2[nf][e]) * R;
                        Sreg[idx] = v;
                        __nv_bfloat16 h = __float2bfloat16(v);
                        SHh[ad] = h;
                        SHl[ad] = __float2bfloat16(v - __bfloat162float(h));
                    }
                }
            }
            CP_WAIT0();
            __syncthreads();
        }
    }

    if (writeS) {
        for (int idx = tid; idx < C_ * 16; idx += 512) {
            int c = idx >> 4, dl = idx & 15;
            Sout[((size_t)b * C_ + c) * C_ + d0 + dl] =
                __bfloat162float(SHh[dl * 520 + c]) + __bfloat162float(SHl[dl * 520 + c]);
        }
    }
}

extern "C" void kernel_launch(void* const* d_in, const int* in_sizes, int n_in,
                              void* d_out, int out_size) {
    const float* X  = (const float*)d_in[0];
    // d_in[1] = S_n (ignored; reference resets state to zero)
    const float* WQ = (const float*)d_in[2];
    const float* bQ = (const float*)d_in[3];
    const float* WK = (const float*)d_in[4];
    const float* bK = (const float*)d_in[5];
    const float* WV = (const float*)d_in[6];
    const float* bV = (const float*)d_in[7];
    float* out = (float*)d_out;

    const int oElems = B_ * T_ * C_;
    const int sElems = B_ * C_ * C_;
    int writeS = (out_size >= oElems + sElems) ? 1 : 0;
    float* Sout = out + oElems;

    const int smP = 2 * PJ_BUF;
    cudaFuncSetAttribute(projmma_kernel, cudaFuncAttributeMaxDynamicSharedMemorySize, smP);
    cudaFuncSetAttribute(localmma_kernel, cudaFuncAttributeMaxDynamicSharedMemorySize, L_SMEM);
    cudaFuncSetAttribute(scan7_kernel, cudaFuncAttributeMaxDynamicSharedMemorySize, S5_SMEM);

    scales_kernel<<<1, NCHUNK>>>();
    convX_kernel<<<(B_ * T_ * C_) / 1024, 256>>>(X);
    dim3 wg(16, 16, 3);
    convW_kernel<<<wg, 256>>>(WQ, WK, WV);
    dim3 pg(12, (B_ * T_) / 128);
    projmma_kernel<<<pg, 256, smP>>>(bQ, bK, bV);
    dim3 tg(T_ / 32, C_ / 32, B_ * 2);
    convT_kernel<<<tg, 256>>>();
    localmma_kernel<<<B_ * NCHUNK, 256, L_SMEM>>>();
    scan7_kernel<<<B_ * 32, 512, S5_SMEM>>>(out, Sout, writeS);
}

// round 12
// speedup vs baseline: 4.6033x; 1.0054x over previous
#include <cuda_runtime.h>
#include <cuda_bf16.h>
#include <cstdint>
#include <cstddef>

#define B_ 4
#define T_ 4096
#define C_ 512
#define CHUNK 64
#define NCHUNK (T_/CHUNK)

// bf16 warp MMA: D(16x8,f32) += A(16x16,row) * B(16x8,col)
__device__ __forceinline__ void mma16816(float* c, const uint32_t* a, const uint32_t* b) {
    asm volatile(
        "mma.sync.aligned.m16n8k16.row.col.f32.bf16.bf16.f32 "
        "{%0,%1,%2,%3}, {%4,%5,%6,%7}, {%8,%9}, {%0,%1,%2,%3};\n"
        : "+f"(c[0]), "+f"(c[1]), "+f"(c[2]), "+f"(c[3])
        : "r"(a[0]), "r"(a[1]), "r"(a[2]), "r"(a[3]), "r"(b[0]), "r"(b[1]));
}
__device__ __forceinline__ void ldsm4(uint32_t* r, uint32_t a) {
    asm volatile("ldmatrix.sync.aligned.m8n8.x4.shared.b16 {%0,%1,%2,%3}, [%4];"
        : "=r"(r[0]), "=r"(r[1]), "=r"(r[2]), "=r"(r[3]) : "r"(a));
}
// A 16x16 tiles (m,k),(m+8,k),(m,k+8),(m+8,k+8); strideHW in halfwords
__device__ __forceinline__ uint32_t addrA(uint32_t base, int row0, int k, int strideHW, int lane) {
    int t = lane >> 3, r = lane & 7;
    return base + (uint32_t)(((row0 + ((t & 1) << 3) + r) * strideHW + k + ((t >> 1) << 3)) * 2);
}
// B (n-major rows) tiles (n,k),(n,k+8),(n+8,k),(n+8,k+8)
__device__ __forceinline__ uint32_t addrB(uint32_t base, int n0, int k, int strideHW, int lane) {
    int t = lane >> 3, r = lane & 7;
    return base + (uint32_t)(((n0 + ((t >> 1) << 3) + r) * strideHW + k + ((t & 1) << 3)) * 2);
}
// B wide-k: tiles (n,k),(n,k+8),(n,k+16),(n,k+24) (n only 8 rows)
__device__ __forceinline__ uint32_t addrBK(uint32_t base, int n0, int k, int strideHW, int lane) {
    int t = lane >> 3, r = lane & 7;
    return base + (uint32_t)(((n0 + r) * strideHW + k + (t << 3)) * 2);
}
__device__ __forceinline__ uint32_t smem_u32(const void* p) {
    uint32_t a;
    asm("{ .reg .u64 t; cvta.to.shared.u64 t, %1; cvt.u32.u64 %0, t; }" : "=r"(a) : "l"(p));
    return a;
}
__device__ __forceinline__ void cpasync16(uint32_t s, const void* g) {
    asm volatile("cp.async.cg.shared.global [%0], [%1], 16;" :: "r"(s), "l"(g));
}
#define CP_COMMIT() asm volatile("cp.async.commit_group;" ::: "memory")
#define CP_WAIT0()  asm volatile("cp.async.wait_group 0;" ::: "memory")

__device__ __forceinline__ void split2(__nv_bfloat16* dh, __nv_bfloat16* dl, float2 v) {
    __nv_bfloat16 h0 = __float2bfloat16(v.x), h1 = __float2bfloat16(v.y);
    __nv_bfloat16 l0 = __float2bfloat16(v.x - __bfloat162float(h0));
    __nv_bfloat16 l1 = __float2bfloat16(v.y - __bfloat162float(h1));
    __nv_bfloat16 hp[2] = {h0, h1}, lp[2] = {l0, l1};
    *(uint32_t*)dh = *(uint32_t*)hp;
    *(uint32_t*)dl = *(uint32_t*)lp;
}

// -------- scratch (__device__ globals) --------
__device__ float g_OL[B_*T_*C_];
__device__ float g_sQ[T_];
__device__ float g_sK[T_];
__device__ float g_SR[NCHUNK];
__device__ __nv_bfloat16 g_Xh[B_*T_*C_];
__device__ __nv_bfloat16 g_Xl[B_*T_*C_];
__device__ __nv_bfloat16 g_Wht[3*C_*C_];
__device__ __nv_bfloat16 g_Wlt[3*C_*C_];
__device__ __nv_bfloat16 g_Qh[B_*T_*C_];   // [b][t][c]
__device__ __nv_bfloat16 g_Ql[B_*T_*C_];
__device__ __nv_bfloat16 g_Kh[B_*T_*C_];
__device__ __nv_bfloat16 g_Kl[B_*T_*C_];
__device__ __nv_bfloat16 g_KTh[B_*C_*T_];  // [b][c][t]
__device__ __nv_bfloat16 g_KTl[B_*C_*T_];
__device__ __nv_bfloat16 g_VTh[B_*C_*T_];
__device__ __nv_bfloat16 g_VTl[B_*C_*T_];

// -------- gamma scales --------
__global__ void scales_kernel() {
    int ch = threadIdx.x;
    if (ch >= NCHUNK) return;
    const float step = 0.03f / 4095.0f;
    float r = 1.0f;
    for (int i = 0; i < CHUNK; ++i) {
        int t = ch * CHUNK + i;
        float g = 0.96f + step * (float)t;
        r *= g;
        g_sQ[t] = r;
        g_sK[t] = 1.0f / r;
    }
    g_SR[ch] = r;
}

// -------- split-bf16 converts --------
__global__ __launch_bounds__(256) void convX_kernel(const float* __restrict__ X) {
    int i = blockIdx.x * 256 + threadIdx.x;
    float4 v = *(const float4*)&X[(size_t)i * 4];
    __nv_bfloat16 h[4], l[4];
    float vv[4] = {v.x, v.y, v.z, v.w};
    #pragma unroll
    for (int j = 0; j < 4; ++j) {
        h[j] = __float2bfloat16(vv[j]);
        l[j] = __float2bfloat16(vv[j] - __bfloat162float(h[j]));
    }
    *(uint2*)&g_Xh[(size_t)i * 4] = *(uint2*)h;
    *(uint2*)&g_Xl[(size_t)i * 4] = *(uint2*)l;
}

__global__ __launch_bounds__(256) void convW_kernel(
        const float* __restrict__ W0, const float* __restrict__ W1,
        const float* __restrict__ W2) {
    __shared__ float tile[32][33];
    const int w = blockIdx.z;
    const float* W = (w == 0) ? W0 : ((w == 1) ? W1 : W2);
    const int k0 = blockIdx.y * 32, n0 = blockIdx.x * 32;
    const int tx = threadIdx.x & 31, ty = threadIdx.x >> 5;
    #pragma unroll
    for (int i = 0; i < 32; i += 8)
        tile[ty + i][tx] = W[(size_t)(k0 + ty + i) * C_ + n0 + tx];
    __syncthreads();
    #pragma unroll
    for (int i = 0; i < 32; i += 8) {
        int nl = ty + i;
        float v = tile[tx][nl];
        __nv_bfloat16 h = __float2bfloat16(v);
        __nv_bfloat16 l = __float2bfloat16(v - __bfloat162float(h));
        size_t o = ((size_t)w * C_ + (n0 + nl)) * C_ + k0 + tx;
        g_Wht[o] = h;
        g_Wlt[o] = l;
    }
}

// -------- HMMA projection v4: fused transpose epilogue for K/V --------
#define SA 40
#define TILE_HW (128 * SA)
#define PJ_TB   (TILE_HW * 2)
#define PJ_BUF  (4 * PJ_TB)
#define PJ_TRS  136                       // transpose buffer stride (hw)
__global__ __launch_bounds__(256, 2) void projmma_kernel(
        const float* __restrict__ bQ, const float* __restrict__ bK,
        const float* __restrict__ bV) {
    extern __shared__ char shp[];
    const uint32_t sbase = smem_u32(shp);

    const int tid = threadIdx.x;
    const int w = tid >> 5, lane = tid & 31;
    const int g = lane >> 2, t4 = lane & 3;
    const int wm = w >> 2, wn = w & 3;
    const int which = blockIdx.x >> 2;
    const int n0 = (blockIdx.x & 3) * 128;
    const int m0 = blockIdx.y * 128;
    const float* bias = (which == 0) ? bQ : ((which == 1) ? bK : bV);

    const __nv_bfloat16* srcs[4] = {
        g_Xh + (size_t)m0 * C_, g_Xl + (size_t)m0 * C_,
        g_Wht + ((size_t)which * C_ + n0) * C_, g_Wlt + ((size_t)which * C_ + n0) * C_ };

    auto stage = [&](int bufi, int ck) {
        uint32_t base = sbase + (uint32_t)bufi * PJ_BUF;
        const int k0 = ck * 32;
        #pragma unroll
        for (int a = 0; a < 4; ++a) {
            #pragma unroll
            for (int j = 0; j < 2; ++j) {
                int u = tid + j * 256;
                int r = u >> 2, cg = u & 3;
                cpasync16(base + a * PJ_TB + r * 80 + cg * 16,
                          srcs[a] + (size_t)r * C_ + k0 + cg * 8);
            }
        }
    };

    float acc[4][4][4];
    #pragma unroll
    for (int i = 0; i < 4; ++i)
        #pragma unroll
        for (int j = 0; j < 4; ++j)
            #pragma unroll
            for (int r = 0; r < 4; ++r) acc[i][j][r] = 0.f;

    stage(0, 0);
    CP_COMMIT(); CP_WAIT0();
    __syncthreads();

    for (int ck = 0; ck < 16; ++ck) {
        const int buf = ck & 1;
        if (ck + 1 < 16) stage(buf ^ 1, ck + 1);
        CP_COMMIT();

        const uint32_t bAh = sbase + buf * PJ_BUF;
        const uint32_t bAl = bAh + PJ_TB;
        const uint32_t bBh = bAh + 2 * PJ_TB;
        const uint32_t bBl = bAh + 3 * PJ_TB;

        #pragma unroll
        for (int kk = 0; kk < 32; kk += 16) {
            uint32_t bhf[4], blf[4], bhf2[4], blf2[4];
            ldsm4(bhf,  addrB(bBh, wn * 32,      kk, SA, lane));
            ldsm4(bhf2, addrB(bBh, wn * 32 + 16, kk, SA, lane));
            ldsm4(blf,  addrB(bBl, wn * 32,      kk, SA, lane));
            ldsm4(blf2, addrB(bBl, wn * 32 + 16, kk, SA, lane));
            #pragma unroll
            for (int mf = 0; mf < 4; ++mf) {
                uint32_t ah[4], al[4];
                ldsm4(ah, addrA(bAh, wm * 64 + mf * 16, kk, SA, lane));
                ldsm4(al, addrA(bAl, wm * 64 + mf * 16, kk, SA, lane));
                mma16816(acc[mf][0], ah, bhf);      mma16816(acc[mf][0], ah, blf);
                mma16816(acc[mf][0], al, bhf);
                mma16816(acc[mf][1], ah, bhf + 2);  mma16816(acc[mf][1], ah, blf + 2);
                mma16816(acc[mf][1], al, bhf + 2);
                mma16816(acc[mf][2], ah, bhf2);     mma16816(acc[mf][2], ah, blf2);
                mma16816(acc[mf][2], al, bhf2);
                mma16816(acc[mf][3], ah, bhf2 + 2); mma16816(acc[mf][3], ah, blf2 + 2);
                mma16816(acc[mf][3], al, bhf2 + 2);
            }
        }
        CP_WAIT0();
        __syncthreads();
    }

    __nv_bfloat16* Th = (__nv_bfloat16*)shp;
    __nv_bfloat16* Tl = (__nv_bfloat16*)(shp + 128 * PJ_TRS * 2);

    #pragma unroll
    for (int mf = 0; mf < 4; ++mf) {
        int m = m0 + wm * 64 + mf * 16 + g;
        int tA = m & (T_ - 1);
        int tB = (m + 8) & (T_ - 1);
        float sA = (which == 0) ? g_sQ[tA] : ((which == 1) ? g_sK[tA] : 1.0f);
        float sB = (which == 0) ? g_sQ[tB] : ((which == 1) ? g_sK[tB] : 1.0f);
        #pragma unroll
        for (int nf = 0; nf < 4; ++nf) {
            int nl = wn * 32 + nf * 8 + 2 * t4;
            int n = n0 + nl;
            float2 bb = *(const float2*)&bias[n];
            float2 o0 = make_float2((acc[mf][nf][0] + bb.x) * sA,
                                    (acc[mf][nf][1] + bb.y) * sA);
            float2 o1 = make_float2((acc[mf][nf][2] + bb.x) * sB,
                                    (acc[mf][nf][3] + bb.y) * sB);
            size_t i0 = (size_t)m * C_ + n, i1 = (size_t)(m + 8) * C_ + n;
            if (which == 0) {
                split2(&g_Qh[i0], &g_Ql[i0], o0);
                split2(&g_Qh[i1], &g_Ql[i1], o1);
            } else {
                int ml = wm * 64 + mf * 16 + g;
                split2(&Th[ml * PJ_TRS + nl], &Tl[ml * PJ_TRS + nl], o0);
                split2(&Th[(ml + 8) * PJ_TRS + nl], &Tl[(ml + 8) * PJ_TRS + nl], o1);
                if (which == 1) {
                    split2(&g_Kh[i0], &g_Kl[i0], o0);
                    split2(&g_Kh[i1], &g_Kl[i1], o1);
                }
            }
        }
    }

    if (which != 0) {
        __syncthreads();
        __nv_bfloat16* dsth = (which == 1) ? g_KTh : g_VTh;
        __nv_bfloat16* dstl = (which == 1) ? g_KTl : g_VTl;
        const size_t bofs = (size_t)(m0 >> 12) * C_ * T_;
        const int tbase = m0 & (T_ - 1);
        const int cl = tid >> 1, seg = tid & 1;
        #pragma unroll
        for (int u = 0; u < 16; ++u) {
            int tl = seg * 64 + u * 4;
            __nv_bfloat16 hp[4], lp[4];
            #pragma unroll
            for (int e = 0; e < 4; ++e) {
                hp[e] = Th[(tl + e) * PJ_TRS + cl];
                lp[e] = Tl[(tl + e) * PJ_TRS + cl];
            }
            size_t o = bofs + (size_t)(n0 + cl) * T_ + tbase + tl;
            *(uint2*)&dsth[o] = *(uint2*)hp;
            *(uint2*)&dstl[o] = *(uint2*)lp;
        }
    }
}

// -------- local masked attention via HMMA + ldmatrix (unchanged, passing) --------
#define L_TILE 9216
#define L_BUF  (4 * L_TILE)
#define L_ASH  (2 * L_BUF)
#define L_ASL  (L_ASH + L_TILE)
#define L_SMEM (L_ASL + L_TILE)
__global__ __launch_bounds__(256, 2) void localmma_kernel() {
    extern __shared__ char shl[];
    const uint32_t sbase = smem_u32(shl);
    __nv_bfloat16* Ash = (__nv_bfloat16*)(shl + L_ASH);
    __nv_bfloat16* Asl = (__nv_bfloat16*)(shl + L_ASL);
    const uint32_t aAsh = sbase + L_ASH, aAsl = sbase + L_ASL;

    const int tid = threadIdx.x;
    const int w = tid >> 5, lane = tid & 31;
    const int g = lane >> 2, t4 = lane & 3;
    const int wm = w >> 2, wn = w & 3;
    const int b = blockIdx.x >> 6;
    const int ch = blockIdx.x & 63;
    const size_t rowbase = (size_t)b * T_ + (size_t)ch * CHUNK;

    const __nv_bfloat16* qkSrc[4] = {
        g_Qh + rowbase * C_, g_Ql + rowbase * C_,
        g_Kh + rowbase * C_, g_Kl + rowbase * C_ };
    const __nv_bfloat16* VThb = g_VTh + (size_t)b * C_ * T_;
    const __nv_bfloat16* VTlb = g_VTl + (size_t)b * C_ * T_;

    auto stage_qk = [&](int bufi, int ck2) {
        uint32_t base = sbase + (uint32_t)bufi * L_BUF;
        #pragma unroll
        for (int a = 0; a < 4; ++a) {
            #pragma unroll
            for (int j = 0; j < 2; ++j) {
                int u = tid + j * 256;
                int row = u >> 3, c8 = u & 7;
                cpasync16(base + a * L_TILE + row * 144 + c8 * 16,
                          qkSrc[a] + (size_t)row * C_ + ck2 * 64 + c8 * 8);
            }
        }
    };
    auto stage_vt = [&](int bufi, int dt) {
        uint32_t base = sbase + (uint32_t)bufi * L_BUF;
        #pragma unroll
        for (int hl = 0; hl < 2; ++hl) {
            const __nv_bfloat16* src = hl ? VTlb : VThb;
            #pragma unroll
            for (int j = 0; j < 4; ++j) {
                int u = tid + j * 256;
                int row = u >> 3, c8 = u & 7;
                cpasync16(base + hl * (2 * L_TILE) + row * 144 + c8 * 16,
                          src + (size_t)(dt * 128 + row) * T_ + ch * CHUNK + c8 * 8);
            }
        }
    };

    float acc[2][2][4];
    #pragma unroll
    for (int i = 0; i < 2; ++i)
        #pragma unroll
        for (int j = 0; j < 2; ++j)
            #pragma unroll
            for (int r = 0; r < 4; ++r) acc[i][j][r] = 0.f;

    stage_qk(0, 0);
    CP_COMMIT(); CP_WAIT0();
    __syncthreads();

    for (int ck2 = 0; ck2 < 8; ++ck2) {
        const int buf = ck2 & 1;
        if (ck2 + 1 < 8) stage_qk(buf ^ 1, ck2 + 1);
        CP_COMMIT();
        const uint32_t bQh = sbase + buf * L_BUF;
        const uint32_t bQl = bQh + L_TILE;
        const uint32_t bKh = bQh + 2 * L_TILE;
        const uint32_t bKl = bQh + 3 * L_TILE;
        #pragma unroll
        for (int kk = 0; kk < 64; kk += 16) {
            uint32_t bh[4], bl[4];
            ldsm4(bh, addrB(bKh, wn * 16, kk, 72, lane));
            ldsm4(bl, addrB(bKl, wn * 16, kk, 72, lane));
            #pragma unroll
            for (int mf = 0; mf < 2; ++mf) {
                uint32_t ah[4], al[4];
                ldsm4(ah, addrA(bQh, wm * 32 + mf * 16, kk, 72, lane));
                ldsm4(al, addrA(bQl, wm * 32 + mf * 16, kk, 72, lane));
                mma16816(acc[mf][0], ah, bh);     mma16816(acc[mf][0], ah, bl);
                mma16816(acc[mf][0], al, bh);
                mma16816(acc[mf][1], ah, bh + 2); mma16816(acc[mf][1], ah, bl + 2);
                mma16816(acc[mf][1], al, bh + 2);
            }
        }
        CP_WAIT0();
        __syncthreads();
    }

    #pragma unroll
    for (int mf = 0; mf < 2; ++mf) {
        #pragma unroll
        for (int nf = 0; nf < 2; ++nf) {
            int t0r = wm * 32 + mf * 16 + g;
            int s0 = wn * 16 + nf * 8 + 2 * t4;
            #pragma unroll
            for (int e = 0; e < 4; ++e) {
                int tt = t0r + (e >> 1) * 8;
                int ss = s0 + (e & 1);
                float v = (ss <= tt) ? acc[mf][nf][e] : 0.f;
                __nv_bfloat16 h = __float2bfloat16(v);
                Ash[tt * 72 + ss] = h;
                Asl[tt * 72 + ss] = __float2bfloat16(v - __bfloat162float(h));
            }
        }
    }
    __syncthreads();

    stage_vt(0, 0);
    CP_COMMIT(); CP_WAIT0();
    __syncthreads();

    for (int dt = 0; dt < 4; ++dt) {
        const int buf = dt & 1;
        if (dt + 1 < 4) stage_vt(buf ^ 1, dt + 1);
        CP_COMMIT();
        const uint32_t bVh = sbase + buf * L_BUF;
        const uint32_t bVl = bVh + 2 * L_TILE;

        float acc2[2][4][4];
        #pragma unroll
        for (int i = 0; i < 2; ++i)
            #pragma unroll
            for (int j = 0; j < 4; ++j)
                #pragma unroll
                for (int r = 0; r < 4; ++r) acc2[i][j][r] = 0.f;

        #pragma unroll
        for (int kk = 0; kk < 64; kk += 16) {
            uint32_t bh[4], bl[4], bh2[4], bl2[4];
            ldsm4(bh,  addrB(bVh, wn * 32,      kk, 72, lane));
            ldsm4(bh2, addrB(bVh, wn * 32 + 16, kk, 72, lane));
            ldsm4(bl,  addrB(bVl, wn * 32,      kk, 72, lane));
            ldsm4(bl2, addrB(bVl, wn * 32 + 16, kk, 72, lane));
            #pragma unroll
            for (int mf = 0; mf < 2; ++mf) {
                uint32_t ah[4], al[4];
                ldsm4(ah, addrA(aAsh, wm * 32 + mf * 16, kk, 72, lane));
                ldsm4(al, addrA(aAsl, wm * 32 + mf * 16, kk, 72, lane));
                mma16816(acc2[mf][0], ah, bh);      mma16816(acc2[mf][0], ah, bl);
                mma16816(acc2[mf][0], al, bh);
                mma16816(acc2[mf][1], ah, bh + 2);  mma16816(acc2[mf][1], ah, bl + 2);
                mma16816(acc2[mf][1], al, bh + 2);
                mma16816(acc2[mf][2], ah, bh2);     mma16816(acc2[mf][2], ah, bl2);
                mma16816(acc2[mf][2], al, bh2);
                mma16816(acc2[mf][3], ah, bh2 + 2); mma16816(acc2[mf][3], ah, bl2 + 2);
                mma16816(acc2[mf][3], al, bh2 + 2);
            }
        }

        #pragma unroll
        for (int mf = 0; mf < 2; ++mf) {
            int tt = wm * 32 + mf * 16 + g;
            #pragma unroll
            for (int nf = 0; nf < 4; ++nf) {
                int d = dt * 128 + wn * 32 + nf * 8 + 2 * t4;
                *(float2*)&g_OL[(rowbase + tt) * C_ + d] =
                    make_float2(acc2[mf][nf][0], acc2[mf][nf][1]);
                *(float2*)&g_OL[(rowbase + tt + 8) * C_ + d] =
                    make_float2(acc2[mf][nf][2], acc2[mf][nf][3]);
            }
        }
        CP_WAIT0();
        __syncthreads();
    }
}

// ---------------- scan v7b: 512 threads, split-k GEMM1 (dual acc) + split-c GEMM2 ----------------
#define S5_SH    0
#define S5_SL    16640
#define S5_STG   33280
#define S5_TILE  36864
#define S5_BUFSZ (2 * S5_TILE)
#define S5_VT    (S5_STG + 2 * S5_BUFSZ)
#define S5_RED   (S5_VT + 4608)
#define S5_SMEM  (S5_RED + 4096)

__global__ __launch_bounds__(512) void scan7_kernel(
        float* __restrict__ O, float* __restrict__ Sout, int writeS) {
    extern __shared__ char s5[];
    __nv_bfloat16* SHh = (__nv_bfloat16*)(s5 + S5_SH);
    __nv_bfloat16* SHl = (__nv_bfloat16*)(s5 + S5_SL);
    float* RED = (float*)(s5 + S5_RED);
    const uint32_t sbase = smem_u32(s5);
    const uint32_t aSHh = sbase + S5_SH, aSHl = sbase + S5_SL;

    const int tid = threadIdx.x;
    const int w = tid >> 5, lane = tid & 31;
    const int g = lane >> 2, t4 = lane & 3;
    const int w8 = w & 7, khalf = w >> 3;
    const int mg = w8 >> 1, ng = w8 & 1;
    const int b = blockIdx.x >> 5;
    const int d0 = (blockIdx.x & 31) * 16;

    const __nv_bfloat16* Qh  = g_Qh  + (size_t)b * T_ * C_;
    const __nv_bfloat16* Ql  = g_Ql  + (size_t)b * T_ * C_;
    const __nv_bfloat16* KTh = g_KTh + (size_t)b * C_ * T_;
    const __nv_bfloat16* KTl = g_KTl + (size_t)b * C_ * T_;
    const __nv_bfloat16* VTh = g_VTh + (size_t)b * C_ * T_;
    const __nv_bfloat16* VTl = g_VTl + (size_t)b * C_ * T_;
    const float* OLb = g_OL + (size_t)b * T_ * C_;
    float* Ob = O + (size_t)b * T_ * C_;

    for (int i = tid; i < 16 * 520 / 2; i += 512) {
        ((uint32_t*)SHh)[i] = 0u;
        ((uint32_t*)SHl)[i] = 0u;
    }

    auto stage_q = [&](int bufi, size_t rb, int half) {
        uint32_t base = sbase + S5_STG + (uint32_t)bufi * S5_BUFSZ;
        #pragma unroll
        for (int j = 0; j < 8; ++j) {
            int u = tid + 512 * j;
            int hl = u >> 11, ur = u & 2047;
            int row = ur >> 5, c16 = ur & 31;
            const __nv_bfloat16* src = hl ? Ql : Qh;
            cpasync16(base + (uint32_t)hl * S5_TILE + row * 528 + c16 * 16,
                      src + (rb + row) * C_ + half * 256 + c16 * 8);
        }
    };
    auto stage_k = [&](int bufi, size_t rb, int half) {
        uint32_t base = sbase + S5_STG + (uint32_t)bufi * S5_BUFSZ;
        #pragma unroll
        for (int j = 0; j < 8; ++j) {
            int u = tid + 512 * j;
            int hl = u >> 11, ur = u & 2047;
            int row = ur >> 3, c8 = ur & 7;
            const __nv_bfloat16* src = hl ? KTl : KTh;
            cpasync16(base + (uint32_t)hl * S5_TILE + row * 144 + c8 * 16,
                      src + (size_t)(half * 256 + row) * T_ + rb + c8 * 8);
        }
    };
    auto stage_vt = [&](size_t rb) {
        if (tid < 256) {
            int hl = tid >> 7, ur = tid & 127;
            int row = ur >> 3, c8 = ur & 7;
            const __nv_bfloat16* src = hl ? VTl : VTh;
            cpasync16(sbase + S5_VT + hl * 2304 + row * 144 + c8 * 16,
                      src + (size_t)(d0 + row) * T_ + rb + c8 * 8);
        }
    };

    stage_q(0, 0, 0);
    CP_COMMIT(); CP_WAIT0();
    __syncthreads();

    float acc1a[4] = {0.f, 0.f, 0.f, 0.f};
    float acc1b[4] = {0.f, 0.f, 0.f, 0.f};
    float2 ol0 = make_float2(0.f, 0.f), ol1 = make_float2(0.f, 0.f);
    float Sreg[16];
    #pragma unroll
    for (int i = 0; i < 16; ++i) Sreg[i] = 0.f;

    for (int ch = 0; ch < NCHUNK; ++ch) {
        const size_t crow = (size_t)ch * CHUNK;
        const float R = __ldg(&g_SR[ch]);

        for (int p = 0; p < 4; ++p) {
            const int buf = p & 1, nbuf = buf ^ 1;
            if (p == 0) {
                stage_q(nbuf, crow, 1);
                if (khalf == 0) {
                    ol0 = __ldg((const float2*)&OLb[(crow + mg * 16 + g) * C_ + d0 + ng * 8 + 2 * t4]);
                    ol1 = __ldg((const float2*)&OLb[(crow + mg * 16 + g + 8) * C_ + d0 + ng * 8 + 2 * t4]);
                }
            } else if (p == 1) {
                stage_k(nbuf, crow, 0);
                stage_vt(crow);
            } else if (p == 2) {
                stage_k(nbuf, crow, 1);
            } else {
                size_t nrow = (ch + 1 < NCHUNK) ? crow + CHUNK : crow;
                stage_q(nbuf, nrow, 0);
            }
            CP_COMMIT();

            if (p < 2) {
                const uint32_t bQsh = sbase + S5_STG + buf * S5_BUFSZ;
                const uint32_t bQsl = bQsh + S5_TILE;
                #pragma unroll
                for (int kk = 0; kk < 128; kk += 32) {
                    const int kloc = khalf * 128 + kk;
                    uint32_t bh4[4], bl4[4];
                    ldsm4(bh4, addrBK(aSHh, ng * 8, p * 256 + kloc, 520, lane));
                    ldsm4(bl4, addrBK(aSHl, ng * 8, p * 256 + kloc, 520, lane));
                    #pragma unroll
                    for (int s = 0; s < 2; ++s) {
                        float* a1 = s ? acc1b : acc1a;
                        uint32_t ah[4], al[4];
                        ldsm4(ah, addrA(bQsh, mg * 16, kloc + s * 16, 264, lane));
                        ldsm4(al, addrA(bQsl, mg * 16, kloc + s * 16, 264, lane));
                        mma16816(a1, ah, bh4 + 2 * s);
                        mma16816(a1, ah, bl4 + 2 * s);
                        mma16816(a1, al, bh4 + 2 * s);
                    }
                }
                if (p == 1 && khalf == 1) {
                    *(float4*)&RED[(w8 * 32 + lane) * 4] =
                        make_float4(acc1a[0] + acc1b[0], acc1a[1] + acc1b[1],
                                    acc1a[2] + acc1b[2], acc1a[3] + acc1b[3]);
                    #pragma unroll
                    for (int r = 0; r < 4; ++r) { acc1a[r] = 0.f; acc1b[r] = 0.f; }
                }
            } else {
                if (p == 2 && khalf == 0) {
                    float4 pr = *(const float4*)&RED[(w8 * 32 + lane) * 4];
                    const int trow = (int)crow + mg * 16 + g;
                    const int d = d0 + ng * 8 + 2 * t4;
                    *(float2*)&Ob[(size_t)trow * C_ + d] =
                        make_float2(tanhf(acc1a[0] + acc1b[0] + pr.x + ol0.x),
                                    tanhf(acc1a[1] + acc1b[1] + pr.y + ol0.y));
                    *(float2*)&Ob[(size_t)(trow + 8) * C_ + d] =
                        make_float2(tanhf(acc1a[2] + acc1b[2] + pr.z + ol1.x),
                                    tanhf(acc1a[3] + acc1b[3] + pr.w + ol1.y));
                    #pragma unroll
                    for (int r = 0; r < 4; ++r) { acc1a[r] = 0.f; acc1b[r] = 0.f; }
                }
                const uint32_t bKsh = sbase + S5_STG + buf * S5_BUFSZ;
                const uint32_t bKsl = bKsh + S5_TILE;
                const uint32_t bVth = sbase + S5_VT;
                const uint32_t bVtl = bVth + 2304;
                float acc2[2][4];
                #pragma unroll
                for (int j = 0; j < 2; ++j)
                    #pragma unroll
                    for (int r = 0; r < 4; ++r) acc2[j][r] = 0.f;
                #pragma unroll
                for (int kk = 0; kk < 64; kk += 16) {
                    uint32_t bh[4], bl[4];
                    ldsm4(bh, addrB(bVth, 0, kk, 72, lane));
                    ldsm4(bl, addrB(bVtl, 0, kk, 72, lane));
                    uint32_t ah[4], al[4];
                    ldsm4(ah, addrA(bKsh, w * 16, kk, 72, lane));
                    ldsm4(al, addrA(bKsl, w * 16, kk, 72, lane));
                    mma16816(acc2[0], ah, bh);     mma16816(acc2[0], ah, bl);
                    mma16816(acc2[0], al, bh);
                    mma16816(acc2[1], ah, bh + 2); mma16816(acc2[1], ah, bl + 2);
                    mma16816(acc2[1], al, bh + 2);
                }
                const int pi = p - 2;
                const int cb = pi * 256 + w * 16;
                #pragma unroll
                for (int nf = 0; nf < 2; ++nf) {
                    #pragma unroll
                    for (int e = 0; e < 4; ++e) {
                        int idx = (pi * 2 + nf) * 4 + e;
                        int c = cb + g + (e >> 1) * 8;
                        int d = nf * 8 + 2 * t4 + (e & 1);
                        int ad = d * 520 + c;
                        float v = (Sreg[idx] + acc2[nf][e]) * R;
                        Sreg[idx] = v;
                        __nv_bfloat16 h = __float2bfloat16(v);
                        SHh[ad] = h;
                        SHl[ad] = __float2bfloat16(v - __bfloat162float(h));
                    }
                }
            }
            CP_WAIT0();
            __syncthreads();
        }
    }

    if (writeS) {
        for (int idx = tid; idx < C_ * 16; idx += 512) {
            int c = idx >> 4, dl = idx & 15;
            Sout[((size_t)b * C_ + c) * C_ + d0 + dl] =
                __bfloat162float(SHh[dl * 520 + c]) + __bfloat162float(SHl[dl * 520 + c]);
        }
    }
}

extern "C" void kernel_launch(void* const* d_in, const int* in_sizes, int n_in,
                              void* d_out, int out_size) {
    const float* X  = (const float*)d_in[0];
    // d_in[1] = S_n (ignored; reference resets state to zero)
    const float* WQ = (const float*)d_in[2];
    const float* bQ = (const float*)d_in[3];
    const float* WK = (const float*)d_in[4];
    const float* bK = (const float*)d_in[5];
    const float* WV = (const float*)d_in[6];
    const float* bV = (const float*)d_in[7];
    float* out = (float*)d_out;

    const int oElems = B_ * T_ * C_;
    const int sElems = B_ * C_ * C_;
    int writeS = (out_size >= oElems + sElems) ? 1 : 0;
    float* Sout = out + oElems;

    const int smP = 2 * PJ_BUF;
    cudaFuncSetAttribute(projmma_kernel, cudaFuncAttributeMaxDynamicSharedMemorySize, smP);
    cudaFuncSetAttribute(localmma_kernel, cudaFuncAttributeMaxDynamicSharedMemorySize, L_SMEM);
    cudaFuncSetAttribute(scan7_kernel, cudaFuncAttributeMaxDynamicSharedMemorySize, S5_SMEM);

    scales_kernel<<<1, NCHUNK>>>();
    convX_kernel<<<(B_ * T_ * C_) / 1024, 256>>>(X);
    dim3 wg(16, 16, 3);
    convW_kernel<<<wg, 256>>>(WQ, WK, WV);
    dim3 pg(12, (B_ * T_) / 128);
    projmma_kernel<<<pg, 256, smP>>>(bQ, bK, bV);
    localmma_kernel<<<B_ * NCHUNK, 256, L_SMEM>>>();
    scan7_kernel<<<B_ * 32, 512, S5_SMEM>>>(out, Sout, writeS);
}